// round 7
// baseline (speedup 1.0000x reference)
#include <cuda_runtime.h>
#include <cuda_bf16.h>
#include <stdint.h>

// ---------------------------------------------------------------------------
// MultiHeadAttention: out = LN(ctx@W_fc + X@W_fc0), attn materialized.
// B=8, S=2048, D=128, H=4, dk=dv=32.
// Output layout: [out (8*2048*128)] then [attn (8*4*2048*2048)].
// K2: bf16 mma.sync; Q/K pre-split bf16 hi/lo; V pre-transposed; K/V tiles
// staged with cp.async (2-stage); 4 blocks/SM -> grid fits in ONE wave.
// ---------------------------------------------------------------------------

namespace {
constexpr int BATCH = 8;
constexpr int SEQ   = 2048;
constexpr int DM    = 128;
constexpr int NR    = BATCH * SEQ;                 // 16384 rows
constexpr size_t OUT_ELEMS = (size_t)NR * DM;      // 2,097,152
constexpr int TQ = 128;                            // q-tile per block
constexpr int TK = 64;                             // k-chunk

// smem (bf16 units)
constexpr int QSTR = 40;    // Q/K row stride (32 + pad): conflict-free frags
constexpr int ESTR = 72;    // V row stride (64 + pad): conflict-free frags
constexpr int QH_OFF  = 0;                         // sQh[128][40]
constexpr int QL_OFF  = QH_OFF + 128 * QSTR;       // sQl[128][40]
constexpr int BUF_OFF = QL_OFF + 128 * QSTR;       // double-buffered K/V
constexpr int BUF_SZ  = 64 * QSTR * 2 + 32 * ESTR; // KH + KL + VH = 7424
constexpr int SMEM_BF16 = BUF_OFF + 2 * BUF_SZ;    // 25088
constexpr size_t SMEM_BYTES = (size_t)SMEM_BF16 * 2;  // 50,176 B
}

// Scratch (device globals: allocation-free rule)
__device__ float g_R  [NR * DM];
__device__ float g_ctx[NR * DM];
__device__ float g_rinv[BATCH * 4 * SEQ];
__device__ __nv_bfloat16 g_Qh[NR * DM];
__device__ __nv_bfloat16 g_Ql[NR * DM];
__device__ __nv_bfloat16 g_Kh[NR * DM];
__device__ __nv_bfloat16 g_Kl[NR * DM];
__device__ __nv_bfloat16 g_Vt[(size_t)BATCH * 4 * 32 * SEQ];  // [bh][v][s]
__device__ int   g_mask_mode;   // 0=uint8, 1=int32, 2=float32

// ---------------------------------------------------------------------------
__device__ __forceinline__ float exp2_poly(float y)
{
    float t   = __fadd_rn(y, 12582912.0f);         // 1.5*2^23 round trick
    float n_f = __fsub_rn(t, 12582912.0f);
    float r   = __fsub_rn(y, n_f);
    int   n   = __float_as_int(t) - 0x4B400000;
    float p   = 1.333355815e-3f;
    p = __fmaf_rn(p, r, 9.618129107e-3f);
    p = __fmaf_rn(p, r, 5.550410866e-2f);
    p = __fmaf_rn(p, r, 2.402265070e-1f);
    p = __fmaf_rn(p, r, 6.931471806e-1f);
    p = __fmaf_rn(p, r, 1.0f);
    return __int_as_float(__float_as_int(p) + (n << 23));
}

__device__ __forceinline__ uint32_t pack_bf16x2(float lo, float hi)
{
    uint32_t r;
    asm("cvt.rn.bf16x2.f32 %0, %1, %2;" : "=r"(r) : "f"(hi), "f"(lo));
    return r;
}

__device__ __forceinline__ uint32_t bf16_rn_bits(float x)
{
    uint32_t b = __float_as_uint(x);
    return (b + 0x7fffu + ((b >> 16) & 1u)) >> 16;
}

__device__ __forceinline__ void mma16816(float c[4],
                                         uint32_t a0, uint32_t a1, uint32_t a2, uint32_t a3,
                                         uint32_t b0, uint32_t b1)
{
    asm volatile("mma.sync.aligned.m16n8k16.row.col.f32.bf16.bf16.f32 "
                 "{%0,%1,%2,%3}, {%4,%5,%6,%7}, {%8,%9}, {%0,%1,%2,%3};"
                 : "+f"(c[0]), "+f"(c[1]), "+f"(c[2]), "+f"(c[3])
                 : "r"(a0), "r"(a1), "r"(a2), "r"(a3), "r"(b0), "r"(b1));
}

__device__ __forceinline__ void cp16(const __nv_bfloat16* smem_dst, const void* gsrc)
{
    uint32_t d = (uint32_t)__cvta_generic_to_shared(smem_dst);
    asm volatile("cp.async.cg.shared.global [%0], [%1], 16;" :: "r"(d), "l"(gsrc));
}
__device__ __forceinline__ void cp_commit()
{
    asm volatile("cp.async.commit_group;");
}
template <int N>
__device__ __forceinline__ void cp_wait()
{
    asm volatile("cp.async.wait_group %0;" :: "n"(N));
}

// ---------------------------------------------------------------------------
// K0: detect mask dtype from byte patterns in the first 4096 bytes.
// ---------------------------------------------------------------------------
__global__ void detect_mask(const unsigned char* __restrict__ m)
{
    __shared__ int s_gt1, s_off;
    if (threadIdx.x == 0) { s_gt1 = 0; s_off = 0; }
    __syncthreads();
    int gt1 = 0, off = 0;
    for (int i = threadIdx.x; i < 4096; i += 256) {
        unsigned char v = m[i];
        if (v > 1) gt1 = 1;
        else if (v == 1 && (i & 3) != 0) off = 1;
    }
    if (gt1) atomicOr(&s_gt1, 1);
    if (off) atomicOr(&s_off, 1);
    __syncthreads();
    if (threadIdx.x == 0)
        g_mask_mode = s_gt1 ? 2 : (s_off ? 0 : 1);
}

// K0b: tiny filler (keeps ncu capture window on attn_mma)
__global__ void zero_rinv()
{
    g_rinv[blockIdx.x * 256 + threadIdx.x] = 0.f;
}

__device__ __forceinline__ uint2 load_mask2(const unsigned char* __restrict__ mask,
                                            size_t idx, int mode)
{
    if (mode == 0) {
        uchar2 m = *(const uchar2*)(mask + idx);
        return make_uint2(m.x, m.y);
    } else if (mode == 1) {
        int2 m = *(const int2*)((const int*)mask + idx);
        return make_uint2((unsigned)m.x, (unsigned)m.y);
    } else {
        float2 m = *(const float2*)((const float*)mask + idx);
        return make_uint2(m.x != 0.f, m.y != 0.f);
    }
}

// ---------------------------------------------------------------------------
// K1: four projections in one launch. Writes R (fp32), Q/K (bf16 hi+lo),
// V transposed as g_Vt[bh][v][s] (bf16 hi).
// ---------------------------------------------------------------------------
__global__ __launch_bounds__(256) void gemm_proj4(const float* __restrict__ inQ,
                                                  const float* __restrict__ inK,
                                                  const float* __restrict__ inV,
                                                  const float* __restrict__ Wfc0,
                                                  const float* __restrict__ WQ,
                                                  const float* __restrict__ WK,
                                                  const float* __restrict__ WV)
{
    const float* A; const float* W;
    switch (blockIdx.y) {
        case 0:  A = inQ; W = Wfc0; break;
        case 1:  A = inQ; W = WQ;   break;
        case 2:  A = inK; W = WK;   break;
        default: A = inV; W = WV;   break;
    }

    __shared__ float sA[64][36];
    __shared__ float sW[32][132];
    const int tid = threadIdx.x;
    const int tx = tid & 15, ty = tid >> 4;
    const int r0 = blockIdx.x * 64;

    float acc[4][8];
#pragma unroll
    for (int r = 0; r < 4; r++)
#pragma unroll
        for (int c = 0; c < 8; c++) acc[r][c] = 0.f;

    for (int kk = 0; kk < DM; kk += 32) {
        for (int t = tid; t < 64 * 32; t += 256) {
            int r = t >> 5, i = t & 31;
            sA[r][i] = A[(size_t)(r0 + r) * DM + kk + i];
        }
        for (int t = tid; t < 32 * 128; t += 256) {
            int i = t >> 7, c = t & 127;
            sW[i][c] = W[(size_t)(kk + i) * DM + c];
        }
        __syncthreads();
#pragma unroll
        for (int i = 0; i < 32; i++) {
            float a[4];
#pragma unroll
            for (int r = 0; r < 4; r++) a[r] = sA[ty * 4 + r][i];
            float4 w0 = *(const float4*)&sW[i][tx * 8];
            float4 w1 = *(const float4*)&sW[i][tx * 8 + 4];
            float wv[8] = {w0.x, w0.y, w0.z, w0.w, w1.x, w1.y, w1.z, w1.w};
#pragma unroll
            for (int r = 0; r < 4; r++)
#pragma unroll
                for (int c = 0; c < 8; c++) acc[r][c] += a[r] * wv[c];
        }
        __syncthreads();
    }

    if (blockIdx.y == 3) {
        // V: write transposed g_Vt[bh][v][s], packing 4 consecutive s (rows).
        int b  = r0 / SEQ;
        int s0 = r0 - b * SEQ + ty * 4;
#pragma unroll
        for (int c = 0; c < 8; c++) {
            int col = tx * 8 + c;
            int bh = b * 4 + (col >> 5);
            int v  = col & 31;
            uint32_t w0 = bf16_rn_bits(acc[0][c]) | (bf16_rn_bits(acc[1][c]) << 16);
            uint32_t w1 = bf16_rn_bits(acc[2][c]) | (bf16_rn_bits(acc[3][c]) << 16);
            *(uint2*)&g_Vt[((size_t)bh * 32 + v) * SEQ + s0] = make_uint2(w0, w1);
        }
        return;
    }

#pragma unroll
    for (int r = 0; r < 4; r++) {
        size_t row = (size_t)(r0 + ty * 4 + r);
        size_t off = row * DM + tx * 8;
        if (blockIdx.y == 0) {
            *(float4*)&g_R[off]     = make_float4(acc[r][0], acc[r][1], acc[r][2], acc[r][3]);
            *(float4*)&g_R[off + 4] = make_float4(acc[r][4], acc[r][5], acc[r][6], acc[r][7]);
        } else {
            __nv_bfloat16* H = (blockIdx.y == 1) ? g_Qh : g_Kh;
            __nv_bfloat16* L = (blockIdx.y == 1) ? g_Ql : g_Kl;
            uint32_t hw[4], lw[4];
#pragma unroll
            for (int c2 = 0; c2 < 4; c2++) {
                uint32_t h0 = bf16_rn_bits(acc[r][2 * c2]);
                uint32_t h1 = bf16_rn_bits(acc[r][2 * c2 + 1]);
                float l0 = acc[r][2 * c2]     - __uint_as_float(h0 << 16);
                float l1 = acc[r][2 * c2 + 1] - __uint_as_float(h1 << 16);
                hw[c2] = h0 | (h1 << 16);
                lw[c2] = bf16_rn_bits(l0) | (bf16_rn_bits(l1) << 16);
            }
            *(uint4*)&H[off] = make_uint4(hw[0], hw[1], hw[2], hw[3]);
            *(uint4*)&L[off] = make_uint4(lw[0], lw[1], lw[2], lw[3]);
        }
    }
}

// ---------------------------------------------------------------------------
// K2: tensor-core attention; cp.async 2-stage K/V; one wave at 4 blocks/SM.
// ---------------------------------------------------------------------------
__global__ __launch_bounds__(256, 4) void attn_mma(const unsigned char* __restrict__ mask,
                                                   float* __restrict__ attn)
{
    extern __shared__ __nv_bfloat16 smb[];
    __nv_bfloat16* sQh = smb + QH_OFF;
    __nv_bfloat16* sQl = smb + QL_OFF;
    __shared__ float srow[128];

    const int tid  = threadIdx.x;
    const int w    = tid >> 5;
    const int lane = tid & 31;
    const int g    = lane >> 2;
    const int tig  = lane & 3;
    const int qb   = w * 16;

    const int bh = blockIdx.y;
    const int b = bh >> 2, h = bh & 3;
    const int q0 = blockIdx.x * TQ;
    const float CE = 1.4426950408889634f * 0.17677669529663689f; // log2e/sqrt(32)
    const int mmode = g_mask_mode;
    const size_t bS = (size_t)b * SEQ;

    // cp.async work assignment
    const int kj   = tid >> 2;            // K row 0..63
    const int kseg = (tid & 3) * 8;       // K col seg (bf16)
    const int vv   = tid >> 3;            // V row 0..31
    const int vseg = (tid & 7) * 8;       // V col seg (bf16)
    const __nv_bfloat16* gK_h = g_Kh + bS * DM + h * 32;
    const __nv_bfloat16* gK_l = g_Kl + bS * DM + h * 32;
    const __nv_bfloat16* gV_t = g_Vt + ((size_t)bh * 32 + vv) * SEQ;

    // ---- issue chunk 0 loads ----
    {
        __nv_bfloat16* kh = smb + BUF_OFF;
        __nv_bfloat16* kl = kh + 64 * QSTR;
        __nv_bfloat16* vh = kl + 64 * QSTR;
        cp16(kh + kj * QSTR + kseg, gK_h + (size_t)kj * DM + kseg);
        cp16(kl + kj * QSTR + kseg, gK_l + (size_t)kj * DM + kseg);
        cp16(vh + vv * ESTR + vseg, gV_t + vseg);
        cp_commit();
    }

    // ---- copy Q tile (bf16, pre-split) ----
    {
        int q = tid >> 1, dseg = (tid & 1) * 16;
        size_t src = (bS + q0 + q) * DM + h * 32 + dseg;
        *(uint4*)&sQh[q * QSTR + dseg]     = *(const uint4*)&g_Qh[src];
        *(uint4*)&sQh[q * QSTR + dseg + 8] = *(const uint4*)&g_Qh[src + 8];
        *(uint4*)&sQl[q * QSTR + dseg]     = *(const uint4*)&g_Ql[src];
        *(uint4*)&sQl[q * QSTR + dseg + 8] = *(const uint4*)&g_Ql[src + 8];
    }
    __syncthreads();

    // ---- Q fragments (loop-invariant) ----
    uint32_t qh[2][4], ql[2][4];
#pragma unroll
    for (int kk = 0; kk < 2; kk++) {
        int c0 = kk * 16 + tig * 2;
        qh[kk][0] = *(const uint32_t*)&sQh[(qb + g) * QSTR + c0];
        qh[kk][1] = *(const uint32_t*)&sQh[(qb + g + 8) * QSTR + c0];
        qh[kk][2] = *(const uint32_t*)&sQh[(qb + g) * QSTR + c0 + 8];
        qh[kk][3] = *(const uint32_t*)&sQh[(qb + g + 8) * QSTR + c0 + 8];
        ql[kk][0] = *(const uint32_t*)&sQl[(qb + g) * QSTR + c0];
        ql[kk][1] = *(const uint32_t*)&sQl[(qb + g + 8) * QSTR + c0];
        ql[kk][2] = *(const uint32_t*)&sQl[(qb + g) * QSTR + c0 + 8];
        ql[kk][3] = *(const uint32_t*)&sQl[(qb + g + 8) * QSTR + c0 + 8];
    }

    float rs0 = 0.f, rs1 = 0.f;
    float cacc[4][4];
#pragma unroll
    for (int n = 0; n < 4; n++)
#pragma unroll
        for (int i = 0; i < 4; i++) cacc[n][i] = 0.f;

    const int qg0 = q0 + qb + g;
    const size_t arow0 = ((size_t)bh * SEQ + qg0) * SEQ;
    const size_t arow1 = arow0 + 8 * SEQ;
    const size_t mrow0 = (bS + qg0) * SEQ;
    const size_t mrow1 = mrow0 + 8 * SEQ;

    for (int kc = 0; kc < SEQ / TK; kc++) {
        const int k0 = kc * TK;
        // issue next chunk's loads into the other buffer (safe: the barrier at
        // the end of iteration kc-1 separated all readers of that buffer).
        if (kc < SEQ / TK - 1) {
            __nv_bfloat16* kh = smb + BUF_OFF + ((kc + 1) & 1) * BUF_SZ;
            __nv_bfloat16* kl = kh + 64 * QSTR;
            __nv_bfloat16* vh = kl + 64 * QSTR;
            size_t koff = (size_t)(k0 + TK + kj) * DM + kseg;
            cp16(kh + kj * QSTR + kseg, gK_h + koff);
            cp16(kl + kj * QSTR + kseg, gK_l + koff);
            cp16(vh + vv * ESTR + vseg, gV_t + k0 + TK + vseg);
            cp_commit();
            cp_wait<1>();
        } else {
            cp_wait<0>();
        }
        __syncthreads();

        const __nv_bfloat16* kh = smb + BUF_OFF + (kc & 1) * BUF_SZ;
        const __nv_bfloat16* kl = kh + 64 * QSTR;
        const __nv_bfloat16* vh = kl + 64 * QSTR;

#pragma unroll
        for (int jj = 0; jj < 4; jj++) {
            // mask loads for this jj (covered by the score MMA chain below)
            const int jm = jj * 16 + tig * 2;
            uint2 pmc[4];
            pmc[0] = load_mask2(mask, mrow0 + k0 + jm, mmode);
            pmc[1] = load_mask2(mask, mrow1 + k0 + jm, mmode);
            pmc[2] = load_mask2(mask, mrow0 + k0 + jm + 8, mmode);
            pmc[3] = load_mask2(mask, mrow1 + k0 + jm + 8, mmode);

            uint32_t eh[2][2];
#pragma unroll
            for (int s = 0; s < 2; s++) {
                const int j0 = jj * 16 + s * 8;
                float c[4] = {0.f, 0.f, 0.f, 0.f};
#pragma unroll
                for (int kk = 0; kk < 2; kk++) {
                    int dof = kk * 16 + tig * 2;
                    uint32_t bh0 = *(const uint32_t*)&kh[(j0 + g) * QSTR + dof];
                    uint32_t bh1 = *(const uint32_t*)&kh[(j0 + g) * QSTR + dof + 8];
                    uint32_t bl0 = *(const uint32_t*)&kl[(j0 + g) * QSTR + dof];
                    uint32_t bl1 = *(const uint32_t*)&kl[(j0 + g) * QSTR + dof + 8];
                    mma16816(c, qh[kk][0], qh[kk][1], qh[kk][2], qh[kk][3], bh0, bh1);
                    mma16816(c, qh[kk][0], qh[kk][1], qh[kk][2], qh[kk][3], bl0, bl1);
                    mma16816(c, ql[kk][0], ql[kk][1], ql[kk][2], ql[kk][3], bh0, bh1);
                }
                const int jgl = k0 + j0 + tig * 2;
                uint2 m0 = pmc[s * 2];
                uint2 m1 = pmc[s * 2 + 1];
                float e00 = m0.x ? 0.f : exp2_poly(c[0] * CE);
                float e01 = m0.y ? 0.f : exp2_poly(c[1] * CE);
                float e10 = m1.x ? 0.f : exp2_poly(c[2] * CE);
                float e11 = m1.y ? 0.f : exp2_poly(c[3] * CE);
                rs0 += e00 + e01;
                rs1 += e10 + e11;
                *(float2*)(attn + arow0 + jgl) = make_float2(e00, e01);
                *(float2*)(attn + arow1 + jgl) = make_float2(e10, e11);
                eh[s][0] = pack_bf16x2(e00, e01);
                eh[s][1] = pack_bf16x2(e10, e11);
            }
            const int c0 = jj * 16 + tig * 2;
#pragma unroll
            for (int nt2 = 0; nt2 < 4; nt2++) {
                int v0 = nt2 * 8;
                uint32_t vb0 = *(const uint32_t*)&vh[(v0 + g) * ESTR + c0];
                uint32_t vb1 = *(const uint32_t*)&vh[(v0 + g) * ESTR + c0 + 8];
                mma16816(cacc[nt2], eh[0][0], eh[0][1], eh[1][0], eh[1][1], vb0, vb1);
            }
        }
        __syncthreads();   // readers done before next iteration overwrites buffer
    }

    // ---- rowsum reduction and rinv ----
    rs0 += __shfl_xor_sync(0xffffffff, rs0, 1);
    rs0 += __shfl_xor_sync(0xffffffff, rs0, 2);
    rs1 += __shfl_xor_sync(0xffffffff, rs1, 1);
    rs1 += __shfl_xor_sync(0xffffffff, rs1, 2);
    if (tig == 0) {
        srow[qb + g]     = rs0;
        srow[qb + g + 8] = rs1;
    }
    __syncthreads();
    if (tid < 128) {
        float r = 1.0f / srow[tid];
        g_rinv[(size_t)bh * SEQ + q0 + tid] = r;
        srow[tid] = r;
    }
    __syncthreads();

    // ---- normalized context write ----
    {
        float r0 = srow[qb + g];
        float r1 = srow[qb + g + 8];
        size_t row0 = (bS + q0 + qb + g) * (size_t)DM + h * 32;
        size_t row1 = row0 + 8 * DM;
#pragma unroll
        for (int nt = 0; nt < 4; nt++) {
            int v = nt * 8 + tig * 2;
            *(float2*)&g_ctx[row0 + v] = make_float2(cacc[nt][0] * r0, cacc[nt][1] * r0);
            *(float2*)&g_ctx[row1 + v] = make_float2(cacc[nt][2] * r1, cacc[nt][3] * r1);
        }
    }
}

// ---------------------------------------------------------------------------
// K3: attn *= rinv[row]
// ---------------------------------------------------------------------------
__global__ void norm_attn(float* __restrict__ attn)
{
    size_t i = (size_t)blockIdx.x * blockDim.x + threadIdx.x;
    size_t row = i >> 9;
    float r = __ldg(&g_rinv[row]);
    float4* p = (float4*)attn;
    float4 v = p[i];
    v.x *= r; v.y *= r; v.z *= r; v.w *= r;
    p[i] = v;
}

// ---------------------------------------------------------------------------
// K4: out = LayerNorm(g_ctx @ W_fc + g_R) * gamma + beta
// ---------------------------------------------------------------------------
__global__ __launch_bounds__(256) void out_ln(const float* __restrict__ Wfc,
                                              const float* __restrict__ gamma,
                                              const float* __restrict__ beta,
                                              float* __restrict__ out)
{
    __shared__ float sA[64][36];
    __shared__ float sW[32][132];
    __shared__ float red1[64][17];
    __shared__ float red2[64][17];
    __shared__ float smu[64];
    __shared__ float srs[64];

    const int tid = threadIdx.x;
    const int tx = tid & 15, ty = tid >> 4;
    const int r0 = blockIdx.x * 64;

    float acc[4][8];
#pragma unroll
    for (int r = 0; r < 4; r++)
#pragma unroll
        for (int c = 0; c < 8; c++) acc[r][c] = 0.f;

    for (int kk = 0; kk < DM; kk += 32) {
        for (int t = tid; t < 64 * 32; t += 256) {
            int r = t >> 5, i = t & 31;
            sA[r][i] = g_ctx[(size_t)(r0 + r) * DM + kk + i];
        }
        for (int t = tid; t < 32 * 128; t += 256) {
            int i = t >> 7, c = t & 127;
            sW[i][c] = Wfc[(size_t)(kk + i) * DM + c];
        }
        __syncthreads();
#pragma unroll
        for (int i = 0; i < 32; i++) {
            float a[4];
#pragma unroll
            for (int r = 0; r < 4; r++) a[r] = sA[ty * 4 + r][i];
            float4 w0 = *(const float4*)&sW[i][tx * 8];
            float4 w1 = *(const float4*)&sW[i][tx * 8 + 4];
            float wv[8] = {w0.x, w0.y, w0.z, w0.w, w1.x, w1.y, w1.z, w1.w};
#pragma unroll
            for (int r = 0; r < 4; r++)
#pragma unroll
                for (int c = 0; c < 8; c++) acc[r][c] += a[r] * wv[c];
        }
        __syncthreads();
    }

#pragma unroll
    for (int r = 0; r < 4; r++) {
        size_t row = (size_t)(r0 + ty * 4 + r);
        float4 rv0 = *(const float4*)&g_R[row * DM + tx * 8];
        float4 rv1 = *(const float4*)&g_R[row * DM + tx * 8 + 4];
        float rsv[8] = {rv0.x, rv0.y, rv0.z, rv0.w, rv1.x, rv1.y, rv1.z, rv1.w};
        float ps = 0.f, pq = 0.f;
#pragma unroll
        for (int c = 0; c < 8; c++) {
            acc[r][c] += rsv[c];
            ps += acc[r][c];
            pq += acc[r][c] * acc[r][c];
        }
        red1[ty * 4 + r][tx] = ps;
        red2[ty * 4 + r][tx] = pq;
    }
    __syncthreads();
    if (tid < 64) {
        float s = 0.f, q = 0.f;
#pragma unroll
        for (int j = 0; j < 16; j++) { s += red1[tid][j]; q += red2[tid][j]; }
        float mu = s * (1.0f / 128.0f);
        float var = q * (1.0f / 128.0f) - mu * mu;
        smu[tid] = mu;
        srs[tid] = rsqrtf(var + 1e-5f);
    }
    __syncthreads();

    float4 g0 = *(const float4*)&gamma[tx * 8];
    float4 g1 = *(const float4*)&gamma[tx * 8 + 4];
    float4 b0 = *(const float4*)&beta[tx * 8];
    float4 b1 = *(const float4*)&beta[tx * 8 + 4];
    float gs[8] = {g0.x, g0.y, g0.z, g0.w, g1.x, g1.y, g1.z, g1.w};
    float bs[8] = {b0.x, b0.y, b0.z, b0.w, b1.x, b1.y, b1.z, b1.w};

#pragma unroll
    for (int r = 0; r < 4; r++) {
        float mu = smu[ty * 4 + r];
        float rstd = srs[ty * 4 + r];
        size_t row = (size_t)(r0 + ty * 4 + r);
        float o[8];
#pragma unroll
        for (int c = 0; c < 8; c++) o[c] = (acc[r][c] - mu) * rstd * gs[c] + bs[c];
        *(float4*)&out[row * DM + tx * 8]     = make_float4(o[0], o[1], o[2], o[3]);
        *(float4*)&out[row * DM + tx * 8 + 4] = make_float4(o[4], o[5], o[6], o[7]);
    }
}

// ---------------------------------------------------------------------------
extern "C" void kernel_launch(void* const* d_in, const int* in_sizes, int n_in,
                              void* d_out, int out_size)
{
    const float* inQ  = (const float*)d_in[0];
    const float* inK  = (const float*)d_in[1];
    const float* inV  = (const float*)d_in[2];
    const unsigned char* mask = (const unsigned char*)d_in[3];
    const float* Wfc0 = (const float*)d_in[4];
    const float* WQ   = (const float*)d_in[5];
    const float* WK   = (const float*)d_in[6];
    const float* WV   = (const float*)d_in[7];
    const float* Wfc  = (const float*)d_in[8];
    const float* gam  = (const float*)d_in[9];
    const float* bet  = (const float*)d_in[10];
    float* out  = (float*)d_out;
    float* attn = out + OUT_ELEMS;

    detect_mask<<<1, 256>>>(mask);
    zero_rinv<<<BATCH * 4 * SEQ / 256, 256>>>();   // filler: keeps ncu window

    gemm_proj4<<<dim3(NR / 64, 4), 256>>>(inQ, inK, inV, Wfc0, WQ, WK, WV);

    cudaFuncSetAttribute(attn_mma, cudaFuncAttributeMaxDynamicSharedMemorySize,
                         (int)SMEM_BYTES);
    dim3 agrid(SEQ / TQ, BATCH * 4);
    attn_mma<<<agrid, 256, SMEM_BYTES>>>(mask, attn);

    size_t nf4 = (size_t)BATCH * 4 * SEQ * SEQ / 4;
    norm_attn<<<(unsigned)(nf4 / 256), 256>>>(attn);

    out_ln<<<NR / 64, 256>>>(Wfc, gam, bet, out);
}

// round 9
// speedup vs baseline: 1.2520x; 1.2520x over previous
#include <cuda_runtime.h>
#include <cuda_bf16.h>
#include <stdint.h>

// ---------------------------------------------------------------------------
// MultiHeadAttention: out = LN(ctx@W_fc + X@W_fc0), attn materialized.
// B=8, S=2048, D=128, H=4, dk=dv=32.
// Output layout: [out (8*2048*128)] then [attn (8*4*2048*2048)].
// K2: bf16 mma.sync; Q frags straight from gmem (no Q smem); K/V via 3-stage
// cp.async pipeline: wait -> barrier -> issue  (race-free, 1 barrier/chunk).
// ---------------------------------------------------------------------------

namespace {
constexpr int BATCH = 8;
constexpr int SEQ   = 2048;
constexpr int DM    = 128;
constexpr int NR    = BATCH * SEQ;                 // 16384 rows
constexpr size_t OUT_ELEMS = (size_t)NR * DM;      // 2,097,152
constexpr int TQ = 128;                            // q-tile per block
constexpr int TK = 64;                             // k-chunk
constexpr int NC = SEQ / TK;                       // 32 chunks

// smem (bf16 units)
constexpr int QSTR = 40;    // K row stride (32 + pad): conflict-free frags
constexpr int ESTR = 72;    // V row stride (64 + pad): conflict-free frags
constexpr int BUF_SZ  = 64 * QSTR * 2 + 32 * ESTR; // KH + KL + VH = 7424
constexpr int SMEM_BF16 = 3 * BUF_SZ;              // 22272
constexpr size_t SMEM_BYTES = (size_t)SMEM_BF16 * 2;  // 44,544 B
}

// Scratch (device globals: allocation-free rule)
__device__ float g_R  [NR * DM];
__device__ float g_ctx[NR * DM];
__device__ float g_rinv[BATCH * 4 * SEQ];
__device__ __nv_bfloat16 g_Qh[NR * DM];
__device__ __nv_bfloat16 g_Ql[NR * DM];
__device__ __nv_bfloat16 g_Kh[NR * DM];
__device__ __nv_bfloat16 g_Kl[NR * DM];
__device__ __nv_bfloat16 g_Vt[(size_t)BATCH * 4 * 32 * SEQ];  // [bh][v][s]
__device__ int   g_mask_mode;   // 0=uint8, 1=int32, 2=float32

// ---------------------------------------------------------------------------
__device__ __forceinline__ float exp2_poly(float y)
{
    float t   = __fadd_rn(y, 12582912.0f);         // 1.5*2^23 round trick
    float n_f = __fsub_rn(t, 12582912.0f);
    float r   = __fsub_rn(y, n_f);
    int   n   = __float_as_int(t) - 0x4B400000;
    float p   = 1.333355815e-3f;
    p = __fmaf_rn(p, r, 9.618129107e-3f);
    p = __fmaf_rn(p, r, 5.550410866e-2f);
    p = __fmaf_rn(p, r, 2.402265070e-1f);
    p = __fmaf_rn(p, r, 6.931471806e-1f);
    p = __fmaf_rn(p, r, 1.0f);
    return __int_as_float(__float_as_int(p) + (n << 23));
}

__device__ __forceinline__ uint32_t pack_bf16x2(float lo, float hi)
{
    uint32_t r;
    asm("cvt.rn.bf16x2.f32 %0, %1, %2;" : "=r"(r) : "f"(hi), "f"(lo));
    return r;
}

__device__ __forceinline__ uint32_t bf16_rn_bits(float x)
{
    uint32_t b = __float_as_uint(x);
    return (b + 0x7fffu + ((b >> 16) & 1u)) >> 16;
}

__device__ __forceinline__ void mma16816(float c[4],
                                         uint32_t a0, uint32_t a1, uint32_t a2, uint32_t a3,
                                         uint32_t b0, uint32_t b1)
{
    asm volatile("mma.sync.aligned.m16n8k16.row.col.f32.bf16.bf16.f32 "
                 "{%0,%1,%2,%3}, {%4,%5,%6,%7}, {%8,%9}, {%0,%1,%2,%3};"
                 : "+f"(c[0]), "+f"(c[1]), "+f"(c[2]), "+f"(c[3])
                 : "r"(a0), "r"(a1), "r"(a2), "r"(a3), "r"(b0), "r"(b1));
}

__device__ __forceinline__ void cp16(const __nv_bfloat16* smem_dst, const void* gsrc)
{
    uint32_t d = (uint32_t)__cvta_generic_to_shared(smem_dst);
    asm volatile("cp.async.cg.shared.global [%0], [%1], 16;" :: "r"(d), "l"(gsrc));
}
__device__ __forceinline__ void cp_commit()
{
    asm volatile("cp.async.commit_group;");
}
template <int N>
__device__ __forceinline__ void cp_wait()
{
    asm volatile("cp.async.wait_group %0;" :: "n"(N));
}

// ---------------------------------------------------------------------------
// K0: detect mask dtype from byte patterns in the first 4096 bytes.
// ---------------------------------------------------------------------------
__global__ void detect_mask(const unsigned char* __restrict__ m)
{
    __shared__ int s_gt1, s_off;
    if (threadIdx.x == 0) { s_gt1 = 0; s_off = 0; }
    __syncthreads();
    int gt1 = 0, off = 0;
    for (int i = threadIdx.x; i < 4096; i += 256) {
        unsigned char v = m[i];
        if (v > 1) gt1 = 1;
        else if (v == 1 && (i & 3) != 0) off = 1;
    }
    if (gt1) atomicOr(&s_gt1, 1);
    if (off) atomicOr(&s_off, 1);
    __syncthreads();
    if (threadIdx.x == 0)
        g_mask_mode = s_gt1 ? 2 : (s_off ? 0 : 1);
}

// K0b: tiny filler (keeps ncu capture window on attn_mma)
__global__ void zero_rinv()
{
    g_rinv[blockIdx.x * 256 + threadIdx.x] = 0.f;
}

__device__ __forceinline__ uint2 load_mask2(const unsigned char* __restrict__ mask,
                                            size_t idx, int mode)
{
    if (mode == 0) {
        uchar2 m = *(const uchar2*)(mask + idx);
        return make_uint2(m.x, m.y);
    } else if (mode == 1) {
        int2 m = *(const int2*)((const int*)mask + idx);
        return make_uint2((unsigned)m.x, (unsigned)m.y);
    } else {
        float2 m = *(const float2*)((const float*)mask + idx);
        return make_uint2(m.x != 0.f, m.y != 0.f);
    }
}

// ---------------------------------------------------------------------------
// K1: four projections in one launch. Writes R (fp32), Q/K (bf16 hi+lo),
// V transposed as g_Vt[bh][v][s] via smem transpose (COALESCED 128B rows).
// ---------------------------------------------------------------------------
__global__ __launch_bounds__(256) void gemm_proj4(const float* __restrict__ inQ,
                                                  const float* __restrict__ inK,
                                                  const float* __restrict__ inV,
                                                  const float* __restrict__ Wfc0,
                                                  const float* __restrict__ WQ,
                                                  const float* __restrict__ WK,
                                                  const float* __restrict__ WV)
{
    const float* A; const float* W;
    switch (blockIdx.y) {
        case 0:  A = inQ; W = Wfc0; break;
        case 1:  A = inQ; W = WQ;   break;
        case 2:  A = inK; W = WK;   break;
        default: A = inV; W = WV;   break;
    }

    __shared__ float sA[64][36];
    __shared__ float sW[32][132];
    __shared__ float sT[64][33];
    const int tid = threadIdx.x;
    const int tx = tid & 15, ty = tid >> 4;
    const int r0 = blockIdx.x * 64;

    float acc[4][8];
#pragma unroll
    for (int r = 0; r < 4; r++)
#pragma unroll
        for (int c = 0; c < 8; c++) acc[r][c] = 0.f;

    for (int kk = 0; kk < DM; kk += 32) {
        for (int t = tid; t < 64 * 32; t += 256) {
            int r = t >> 5, i = t & 31;
            sA[r][i] = A[(size_t)(r0 + r) * DM + kk + i];
        }
        for (int t = tid; t < 32 * 128; t += 256) {
            int i = t >> 7, c = t & 127;
            sW[i][c] = W[(size_t)(kk + i) * DM + c];
        }
        __syncthreads();
#pragma unroll
        for (int i = 0; i < 32; i++) {
            float a[4];
#pragma unroll
            for (int r = 0; r < 4; r++) a[r] = sA[ty * 4 + r][i];
            float4 w0 = *(const float4*)&sW[i][tx * 8];
            float4 w1 = *(const float4*)&sW[i][tx * 8 + 4];
            float wv[8] = {w0.x, w0.y, w0.z, w0.w, w1.x, w1.y, w1.z, w1.w};
#pragma unroll
            for (int r = 0; r < 4; r++)
#pragma unroll
                for (int c = 0; c < 8; c++) acc[r][c] += a[r] * wv[c];
        }
        __syncthreads();
    }

    if (blockIdx.y == 3) {
        // V: smem transpose per head, then coalesced g_Vt row writes.
        int b  = r0 / SEQ;
        int sblock = r0 - b * SEQ;
        for (int cg = 0; cg < 4; cg++) {
            if ((tx >> 2) == cg) {
#pragma unroll
                for (int r = 0; r < 4; r++)
#pragma unroll
                    for (int c = 0; c < 8; c++)
                        sT[ty * 4 + r][(tx & 3) * 8 + c] = acc[r][c];
            }
            __syncthreads();
            {
                int v   = tid >> 3;            // 0..31
                int seg = (tid & 7) * 8;       // 0..56
                uint32_t wv[4];
#pragma unroll
                for (int p = 0; p < 4; p++) {
                    uint32_t lo = bf16_rn_bits(sT[seg + p * 2][v]);
                    uint32_t hi = bf16_rn_bits(sT[seg + p * 2 + 1][v]);
                    wv[p] = lo | (hi << 16);
                }
                size_t off = ((size_t)(b * 4 + cg) * 32 + v) * SEQ + sblock + seg;
                *(uint4*)&g_Vt[off] = make_uint4(wv[0], wv[1], wv[2], wv[3]);
            }
            __syncthreads();
        }
        return;
    }

#pragma unroll
    for (int r = 0; r < 4; r++) {
        size_t row = (size_t)(r0 + ty * 4 + r);
        size_t off = row * DM + tx * 8;
        if (blockIdx.y == 0) {
            *(float4*)&g_R[off]     = make_float4(acc[r][0], acc[r][1], acc[r][2], acc[r][3]);
            *(float4*)&g_R[off + 4] = make_float4(acc[r][4], acc[r][5], acc[r][6], acc[r][7]);
        } else {
            __nv_bfloat16* H = (blockIdx.y == 1) ? g_Qh : g_Kh;
            __nv_bfloat16* L = (blockIdx.y == 1) ? g_Ql : g_Kl;
            uint32_t hw[4], lw[4];
#pragma unroll
            for (int c2 = 0; c2 < 4; c2++) {
                uint32_t h0 = bf16_rn_bits(acc[r][2 * c2]);
                uint32_t h1 = bf16_rn_bits(acc[r][2 * c2 + 1]);
                float l0 = acc[r][2 * c2]     - __uint_as_float(h0 << 16);
                float l1 = acc[r][2 * c2 + 1] - __uint_as_float(h1 << 16);
                hw[c2] = h0 | (h1 << 16);
                lw[c2] = bf16_rn_bits(l0) | (bf16_rn_bits(l1) << 16);
            }
            *(uint4*)&H[off] = make_uint4(hw[0], hw[1], hw[2], hw[3]);
            *(uint4*)&L[off] = make_uint4(lw[0], lw[1], lw[2], lw[3]);
        }
    }
}

// ---------------------------------------------------------------------------
// K2: tensor-core attention; 3-stage cp.async K/V pipeline, race-free order:
//   wait(chunk kc) -> barrier -> issue(chunk kc+2) -> MMA phase.
// The barrier separates iteration kc-1's readers of buffer (kc-1)%3 from the
// writes of chunk kc+2 (same buffer), and publishes chunk kc to all warps.
// ---------------------------------------------------------------------------
__global__ __launch_bounds__(256, 4) void attn_mma(const unsigned char* __restrict__ mask,
                                                   float* __restrict__ attn)
{
    extern __shared__ __nv_bfloat16 smb[];
    __shared__ float srow[128];

    const int tid  = threadIdx.x;
    const int w    = tid >> 5;
    const int lane = tid & 31;
    const int g    = lane >> 2;
    const int tig  = lane & 3;
    const int qb   = w * 16;

    const int bh = blockIdx.y;
    const int b = bh >> 2, h = bh & 3;
    const int q0 = blockIdx.x * TQ;
    const float CE = 1.4426950408889634f * 0.17677669529663689f; // log2e/sqrt(32)
    const int mmode = g_mask_mode;
    const size_t bS = (size_t)b * SEQ;

    // cp.async work assignment
    const int kj   = tid >> 2;            // K row 0..63
    const int kseg = (tid & 3) * 8;       // K col seg (bf16)
    const int vv   = tid >> 3;            // V row 0..31
    const int vseg = (tid & 7) * 8;       // V col seg (bf16)
    const __nv_bfloat16* gK_h = g_Kh + bS * DM + h * 32;
    const __nv_bfloat16* gK_l = g_Kl + bS * DM + h * 32;
    const __nv_bfloat16* gV_t = g_Vt + ((size_t)bh * 32 + vv) * SEQ;

    auto issue_chunk = [&](int kc) {
        __nv_bfloat16* kh = smb + (kc % 3) * BUF_SZ;
        __nv_bfloat16* kl = kh + 64 * QSTR;
        __nv_bfloat16* vh = kl + 64 * QSTR;
        size_t koff = (size_t)(kc * TK + kj) * DM + kseg;
        cp16(kh + kj * QSTR + kseg, gK_h + koff);
        cp16(kl + kj * QSTR + kseg, gK_l + koff);
        cp16(vh + vv * ESTR + vseg, gV_t + kc * TK + vseg);
    };

    // ---- prologue: 2-deep prefetch ----
    issue_chunk(0);
    cp_commit();
    issue_chunk(1);
    cp_commit();

    // ---- Q fragments straight from gmem ----
    uint32_t qh[2][4], ql[2][4];
    {
        const __nv_bfloat16* gQ_h = g_Qh + (bS + q0) * DM + h * 32;
        const __nv_bfloat16* gQ_l = g_Ql + (bS + q0) * DM + h * 32;
#pragma unroll
        for (int kk = 0; kk < 2; kk++) {
            int c0 = kk * 16 + tig * 2;
            size_t r0o = (size_t)(qb + g) * DM + c0;
            size_t r1o = (size_t)(qb + g + 8) * DM + c0;
            qh[kk][0] = *(const uint32_t*)&gQ_h[r0o];
            qh[kk][1] = *(const uint32_t*)&gQ_h[r1o];
            qh[kk][2] = *(const uint32_t*)&gQ_h[r0o + 8];
            qh[kk][3] = *(const uint32_t*)&gQ_h[r1o + 8];
            ql[kk][0] = *(const uint32_t*)&gQ_l[r0o];
            ql[kk][1] = *(const uint32_t*)&gQ_l[r1o];
            ql[kk][2] = *(const uint32_t*)&gQ_l[r0o + 8];
            ql[kk][3] = *(const uint32_t*)&gQ_l[r1o + 8];
        }
    }

    float rs0 = 0.f, rs1 = 0.f;
    float cacc[4][4];
#pragma unroll
    for (int n = 0; n < 4; n++)
#pragma unroll
        for (int i = 0; i < 4; i++) cacc[n][i] = 0.f;

    const int qg0 = q0 + qb + g;
    const size_t arow0 = ((size_t)bh * SEQ + qg0) * SEQ;
    const size_t arow1 = arow0 + 8 * SEQ;
    const size_t mrow0 = (bS + qg0) * SEQ;
    const size_t mrow1 = mrow0 + 8 * SEQ;

    for (int kc = 0; kc < NC; kc++) {
        const int k0 = kc * TK;

        cp_wait<1>();                // chunk kc's group complete (per-warp)
        __syncthreads();             // publish to all warps; close kc-1 readers
        if (kc + 2 < NC) issue_chunk(kc + 2);
        cp_commit();                 // one group per iteration (may be empty)

        const __nv_bfloat16* kh = smb + (kc % 3) * BUF_SZ;
        const __nv_bfloat16* kl = kh + 64 * QSTR;
        const __nv_bfloat16* vh = kl + 64 * QSTR;

#pragma unroll
        for (int jj = 0; jj < 4; jj++) {
            const int jm = jj * 16 + tig * 2;
            uint2 pmc[4];
            pmc[0] = load_mask2(mask, mrow0 + k0 + jm, mmode);
            pmc[1] = load_mask2(mask, mrow1 + k0 + jm, mmode);
            pmc[2] = load_mask2(mask, mrow0 + k0 + jm + 8, mmode);
            pmc[3] = load_mask2(mask, mrow1 + k0 + jm + 8, mmode);

            uint32_t eh[2][2];
#pragma unroll
            for (int s = 0; s < 2; s++) {
                const int j0 = jj * 16 + s * 8;
                float c[4] = {0.f, 0.f, 0.f, 0.f};
#pragma unroll
                for (int kk = 0; kk < 2; kk++) {
                    int dof = kk * 16 + tig * 2;
                    uint32_t bh0 = *(const uint32_t*)&kh[(j0 + g) * QSTR + dof];
                    uint32_t bh1 = *(const uint32_t*)&kh[(j0 + g) * QSTR + dof + 8];
                    uint32_t bl0 = *(const uint32_t*)&kl[(j0 + g) * QSTR + dof];
                    uint32_t bl1 = *(const uint32_t*)&kl[(j0 + g) * QSTR + dof + 8];
                    mma16816(c, qh[kk][0], qh[kk][1], qh[kk][2], qh[kk][3], bh0, bh1);
                    mma16816(c, qh[kk][0], qh[kk][1], qh[kk][2], qh[kk][3], bl0, bl1);
                    mma16816(c, ql[kk][0], ql[kk][1], ql[kk][2], ql[kk][3], bh0, bh1);
                }
                const int jgl = k0 + j0 + tig * 2;
                uint2 m0 = pmc[s * 2];
                uint2 m1 = pmc[s * 2 + 1];
                float e00 = m0.x ? 0.f : exp2_poly(c[0] * CE);
                float e01 = m0.y ? 0.f : exp2_poly(c[1] * CE);
                float e10 = m1.x ? 0.f : exp2_poly(c[2] * CE);
                float e11 = m1.y ? 0.f : exp2_poly(c[3] * CE);
                rs0 += e00 + e01;
                rs1 += e10 + e11;
                *(float2*)(attn + arow0 + jgl) = make_float2(e00, e01);
                *(float2*)(attn + arow1 + jgl) = make_float2(e10, e11);
                eh[s][0] = pack_bf16x2(e00, e01);
                eh[s][1] = pack_bf16x2(e10, e11);
            }
            const int c0 = jj * 16 + tig * 2;
#pragma unroll
            for (int nt2 = 0; nt2 < 4; nt2++) {
                int v0 = nt2 * 8;
                uint32_t vb0 = *(const uint32_t*)&vh[(v0 + g) * ESTR + c0];
                uint32_t vb1 = *(const uint32_t*)&vh[(v0 + g) * ESTR + c0 + 8];
                mma16816(cacc[nt2], eh[0][0], eh[0][1], eh[1][0], eh[1][1], vb0, vb1);
            }
        }
    }

    // ---- rowsum reduction and rinv ----
    rs0 += __shfl_xor_sync(0xffffffff, rs0, 1);
    rs0 += __shfl_xor_sync(0xffffffff, rs0, 2);
    rs1 += __shfl_xor_sync(0xffffffff, rs1, 1);
    rs1 += __shfl_xor_sync(0xffffffff, rs1, 2);
    __syncthreads();
    if (tig == 0) {
        srow[qb + g]     = rs0;
        srow[qb + g + 8] = rs1;
    }
    __syncthreads();
    if (tid < 128) {
        float r = 1.0f / srow[tid];
        g_rinv[(size_t)bh * SEQ + q0 + tid] = r;
        srow[tid] = r;
    }
    __syncthreads();

    // ---- normalized context write ----
    {
        float r0 = srow[qb + g];
        float r1 = srow[qb + g + 8];
        size_t row0 = (bS + q0 + qb + g) * (size_t)DM + h * 32;
        size_t row1 = row0 + 8 * DM;
#pragma unroll
        for (int nt = 0; nt < 4; nt++) {
            int v = nt * 8 + tig * 2;
            *(float2*)&g_ctx[row0 + v] = make_float2(cacc[nt][0] * r0, cacc[nt][1] * r0);
            *(float2*)&g_ctx[row1 + v] = make_float2(cacc[nt][2] * r1, cacc[nt][3] * r1);
        }
    }
}

// ---------------------------------------------------------------------------
// K3: attn *= rinv[row]
// ---------------------------------------------------------------------------
__global__ void norm_attn(float* __restrict__ attn)
{
    size_t i = (size_t)blockIdx.x * blockDim.x + threadIdx.x;
    size_t row = i >> 9;
    float r = __ldg(&g_rinv[row]);
    float4* p = (float4*)attn;
    float4 v = p[i];
    v.x *= r; v.y *= r; v.z *= r; v.w *= r;
    p[i] = v;
}

// ---------------------------------------------------------------------------
// K4: out = LayerNorm(g_ctx @ W_fc + g_R) * gamma + beta
// ---------------------------------------------------------------------------
__global__ __launch_bounds__(256) void out_ln(const float* __restrict__ Wfc,
                                              const float* __restrict__ gamma,
                                              const float* __restrict__ beta,
                                              float* __restrict__ out)
{
    __shared__ float sA[64][36];
    __shared__ float sW[32][132];
    __shared__ float red1[64][17];
    __shared__ float red2[64][17];
    __shared__ float smu[64];
    __shared__ float srs[64];

    const int tid = threadIdx.x;
    const int tx = tid & 15, ty = tid >> 4;
    const int r0 = blockIdx.x * 64;

    float acc[4][8];
#pragma unroll
    for (int r = 0; r < 4; r++)
#pragma unroll
        for (int c = 0; c < 8; c++) acc[r][c] = 0.f;

    for (int kk = 0; kk < DM; kk += 32) {
        for (int t = tid; t < 64 * 32; t += 256) {
            int r = t >> 5, i = t & 31;
            sA[r][i] = g_ctx[(size_t)(r0 + r) * DM + kk + i];
        }
        for (int t = tid; t < 32 * 128; t += 256) {
            int i = t >> 7, c = t & 127;
            sW[i][c] = Wfc[(size_t)(kk + i) * DM + c];
        }
        __syncthreads();
#pragma unroll
        for (int i = 0; i < 32; i++) {
            float a[4];
#pragma unroll
            for (int r = 0; r < 4; r++) a[r] = sA[ty * 4 + r][i];
            float4 w0 = *(const float4*)&sW[i][tx * 8];
            float4 w1 = *(const float4*)&sW[i][tx * 8 + 4];
            float wv[8] = {w0.x, w0.y, w0.z, w0.w, w1.x, w1.y, w1.z, w1.w};
#pragma unroll
            for (int r = 0; r < 4; r++)
#pragma unroll
                for (int c = 0; c < 8; c++) acc[r][c] += a[r] * wv[c];
        }
        __syncthreads();
    }

#pragma unroll
    for (int r = 0; r < 4; r++) {
        size_t row = (size_t)(r0 + ty * 4 + r);
        float4 rv0 = *(const float4*)&g_R[row * DM + tx * 8];
        float4 rv1 = *(const float4*)&g_R[row * DM + tx * 8 + 4];
        float rsv[8] = {rv0.x, rv0.y, rv0.z, rv0.w, rv1.x, rv1.y, rv1.z, rv1.w};
        float ps = 0.f, pq = 0.f;
#pragma unroll
        for (int c = 0; c < 8; c++) {
            acc[r][c] += rsv[c];
            ps += acc[r][c];
            pq += acc[r][c] * acc[r][c];
        }
        red1[ty * 4 + r][tx] = ps;
        red2[ty * 4 + r][tx] = pq;
    }
    __syncthreads();
    if (tid < 64) {
        float s = 0.f, q = 0.f;
#pragma unroll
        for (int j = 0; j < 16; j++) { s += red1[tid][j]; q += red2[tid][j]; }
        float mu = s * (1.0f / 128.0f);
        float var = q * (1.0f / 128.0f) - mu * mu;
        smu[tid] = mu;
        srs[tid] = rsqrtf(var + 1e-5f);
    }
    __syncthreads();

    float4 g0 = *(const float4*)&gamma[tx * 8];
    float4 g1 = *(const float4*)&gamma[tx * 8 + 4];
    float4 b0 = *(const float4*)&beta[tx * 8];
    float4 b1 = *(const float4*)&beta[tx * 8 + 4];
    float gs[8] = {g0.x, g0.y, g0.z, g0.w, g1.x, g1.y, g1.z, g1.w};
    float bs[8] = {b0.x, b0.y, b0.z, b0.w, b1.x, b1.y, b1.z, b1.w};

#pragma unroll
    for (int r = 0; r < 4; r++) {
        float mu = smu[ty * 4 + r];
        float rstd = srs[ty * 4 + r];
        size_t row = (size_t)(r0 + ty * 4 + r);
        float o[8];
#pragma unroll
        for (int c = 0; c < 8; c++) o[c] = (acc[r][c] - mu) * rstd * gs[c] + bs[c];
        *(float4*)&out[row * DM + tx * 8]     = make_float4(o[0], o[1], o[2], o[3]);
        *(float4*)&out[row * DM + tx * 8 + 4] = make_float4(o[4], o[5], o[6], o[7]);
    }
}

// ---------------------------------------------------------------------------
extern "C" void kernel_launch(void* const* d_in, const int* in_sizes, int n_in,
                              void* d_out, int out_size)
{
    const float* inQ  = (const float*)d_in[0];
    const float* inK  = (const float*)d_in[1];
    const float* inV  = (const float*)d_in[2];
    const unsigned char* mask = (const unsigned char*)d_in[3];
    const float* Wfc0 = (const float*)d_in[4];
    const float* WQ   = (const float*)d_in[5];
    const float* WK   = (const float*)d_in[6];
    const float* WV   = (const float*)d_in[7];
    const float* Wfc  = (const float*)d_in[8];
    const float* gam  = (const float*)d_in[9];
    const float* bet  = (const float*)d_in[10];
    float* out  = (float*)d_out;
    float* attn = out + OUT_ELEMS;

    detect_mask<<<1, 256>>>(mask);
    zero_rinv<<<BATCH * 4 * SEQ / 256, 256>>>();   // filler: keeps ncu window

    gemm_proj4<<<dim3(NR / 64, 4), 256>>>(inQ, inK, inV, Wfc0, WQ, WK, WV);

    cudaFuncSetAttribute(attn_mma, cudaFuncAttributeMaxDynamicSharedMemorySize,
                         (int)SMEM_BYTES);
    dim3 agrid(SEQ / TQ, BATCH * 4);
    attn_mma<<<agrid, 256, SMEM_BYTES>>>(mask, attn);

    size_t nf4 = (size_t)BATCH * 4 * SEQ * SEQ / 4;
    norm_attn<<<(unsigned)(nf4 / 256), 256>>>(attn);

    out_ln<<<NR / 64, 256>>>(Wfc, gam, bet, out);
}

// round 10
// speedup vs baseline: 1.3111x; 1.0472x over previous
#include <cuda_runtime.h>
#include <cuda_bf16.h>
#include <stdint.h>

// ---------------------------------------------------------------------------
// MultiHeadAttention: out = LN(ctx@W_fc + X@W_fc0), attn materialized.
// B=8, S=2048, D=128, H=4, dk=dv=32.
// Output layout: [out (8*2048*128)] then [attn (8*4*2048*2048)].
// Projections now run on tensor cores (bf16 3-product split); inputs/weights
// pre-split by tiny kernels. K2 unchanged from R9 (281us, race-free pipeline).
// ---------------------------------------------------------------------------

namespace {
constexpr int BATCH = 8;
constexpr int SEQ   = 2048;
constexpr int DM    = 128;
constexpr int NR    = BATCH * SEQ;                 // 16384 rows
constexpr size_t OUT_ELEMS = (size_t)NR * DM;      // 2,097,152
constexpr int TQ = 128;                            // q-tile per block (K2)
constexpr int TK = 64;                             // k-chunk (K2)
constexpr int NC = SEQ / TK;                       // 32 chunks

// K2 smem (bf16 units)
constexpr int QSTR = 40;
constexpr int ESTR = 72;
constexpr int BUF_SZ  = 64 * QSTR * 2 + 32 * ESTR;
constexpr int SMEM_BF16 = 3 * BUF_SZ;
constexpr size_t SMEM_BYTES = (size_t)SMEM_BF16 * 2;  // 44,544 B

// proj_tc smem (bf16 units), k sliced by 64, stride 72 (conflict-free frags)
constexpr int PSTR = 72;
constexpr int PA_H = 0;                    // sAh[64][72]
constexpr int PA_L = PA_H + 64 * PSTR;     // sAl
constexpr int PW_H = PA_L + 64 * PSTR;     // sWth[128][72]
constexpr int PW_L = PW_H + 128 * PSTR;    // sWtl
constexpr int P_BF16 = PW_L + 128 * PSTR;  // 27648 elems
constexpr size_t P_SMEM_BYTES = (size_t)P_BF16 * 2;   // 55,296 B
constexpr int VSTR = 136;                  // sV[64][136] staging (reuses sWth)
}

// Scratch (device globals: allocation-free rule)
__device__ float g_R  [NR * DM];
__device__ float g_ctx[NR * DM];
__device__ float g_rinv[BATCH * 4 * SEQ];
__device__ __nv_bfloat16 g_Xh[3 * NR * DM];   // inputs split hi (Q,K,V)
__device__ __nv_bfloat16 g_Xl[3 * NR * DM];   // inputs split lo
__device__ __nv_bfloat16 g_Wth[4 * DM * DM];  // weights, transposed [n][k], hi
__device__ __nv_bfloat16 g_Wtl[4 * DM * DM];  // weights, transposed [n][k], lo
__device__ __nv_bfloat16 g_Qh[NR * DM];
__device__ __nv_bfloat16 g_Ql[NR * DM];
__device__ __nv_bfloat16 g_Kh[NR * DM];
__device__ __nv_bfloat16 g_Kl[NR * DM];
__device__ __nv_bfloat16 g_Vt[(size_t)BATCH * 4 * 32 * SEQ];  // [bh][v][s]
__device__ int   g_mask_mode;   // 0=uint8, 1=int32, 2=float32

// ---------------------------------------------------------------------------
__device__ __forceinline__ float exp2_poly(float y)
{
    float t   = __fadd_rn(y, 12582912.0f);
    float n_f = __fsub_rn(t, 12582912.0f);
    float r   = __fsub_rn(y, n_f);
    int   n   = __float_as_int(t) - 0x4B400000;
    float p   = 1.333355815e-3f;
    p = __fmaf_rn(p, r, 9.618129107e-3f);
    p = __fmaf_rn(p, r, 5.550410866e-2f);
    p = __fmaf_rn(p, r, 2.402265070e-1f);
    p = __fmaf_rn(p, r, 6.931471806e-1f);
    p = __fmaf_rn(p, r, 1.0f);
    return __int_as_float(__float_as_int(p) + (n << 23));
}

__device__ __forceinline__ uint32_t pack_bf16x2(float lo, float hi)
{
    uint32_t r;
    asm("cvt.rn.bf16x2.f32 %0, %1, %2;" : "=r"(r) : "f"(hi), "f"(lo));
    return r;
}

__device__ __forceinline__ uint32_t bf16_rn_bits(float x)
{
    uint32_t b = __float_as_uint(x);
    return (b + 0x7fffu + ((b >> 16) & 1u)) >> 16;
}

__device__ __forceinline__ void mma16816(float c[4],
                                         uint32_t a0, uint32_t a1, uint32_t a2, uint32_t a3,
                                         uint32_t b0, uint32_t b1)
{
    asm volatile("mma.sync.aligned.m16n8k16.row.col.f32.bf16.bf16.f32 "
                 "{%0,%1,%2,%3}, {%4,%5,%6,%7}, {%8,%9}, {%0,%1,%2,%3};"
                 : "+f"(c[0]), "+f"(c[1]), "+f"(c[2]), "+f"(c[3])
                 : "r"(a0), "r"(a1), "r"(a2), "r"(a3), "r"(b0), "r"(b1));
}

__device__ __forceinline__ void cp16(const __nv_bfloat16* smem_dst, const void* gsrc)
{
    uint32_t d = (uint32_t)__cvta_generic_to_shared(smem_dst);
    asm volatile("cp.async.cg.shared.global [%0], [%1], 16;" :: "r"(d), "l"(gsrc));
}
__device__ __forceinline__ void cp_commit()
{
    asm volatile("cp.async.commit_group;");
}
template <int N>
__device__ __forceinline__ void cp_wait()
{
    asm volatile("cp.async.wait_group %0;" :: "n"(N));
}

// ---------------------------------------------------------------------------
// K0: detect mask dtype.
// ---------------------------------------------------------------------------
__global__ void detect_mask(const unsigned char* __restrict__ m)
{
    __shared__ int s_gt1, s_off;
    if (threadIdx.x == 0) { s_gt1 = 0; s_off = 0; }
    __syncthreads();
    int gt1 = 0, off = 0;
    for (int i = threadIdx.x; i < 4096; i += 256) {
        unsigned char v = m[i];
        if (v > 1) gt1 = 1;
        else if (v == 1 && (i & 3) != 0) off = 1;
    }
    if (gt1) atomicOr(&s_gt1, 1);
    if (off) atomicOr(&s_off, 1);
    __syncthreads();
    if (threadIdx.x == 0)
        g_mask_mode = s_gt1 ? 2 : (s_off ? 0 : 1);
}

// filler: keeps ncu -s 5 window on attn_mma (launch #6)
__global__ void zero_rinv()
{
    g_rinv[blockIdx.x * 256 + threadIdx.x] = 0.f;
}

__device__ __forceinline__ uint2 load_mask2(const unsigned char* __restrict__ mask,
                                            size_t idx, int mode)
{
    if (mode == 0) {
        uchar2 m = *(const uchar2*)(mask + idx);
        return make_uint2(m.x, m.y);
    } else if (mode == 1) {
        int2 m = *(const int2*)((const int*)mask + idx);
        return make_uint2((unsigned)m.x, (unsigned)m.y);
    } else {
        float2 m = *(const float2*)((const float*)mask + idx);
        return make_uint2(m.x != 0.f, m.y != 0.f);
    }
}

// ---------------------------------------------------------------------------
// P0: split inputs fp32 -> bf16 hi/lo.  grid (2048, 3), 256 threads, 4 f32/thr.
// ---------------------------------------------------------------------------
__global__ __launch_bounds__(256) void split_inputs(const float* __restrict__ inQ,
                                                    const float* __restrict__ inK,
                                                    const float* __restrict__ inV)
{
    const float* src = (blockIdx.y == 0) ? inQ : (blockIdx.y == 1) ? inK : inV;
    __nv_bfloat16* H = g_Xh + (size_t)blockIdx.y * NR * DM;
    __nv_bfloat16* L = g_Xl + (size_t)blockIdx.y * NR * DM;
    size_t i = ((size_t)blockIdx.x * 256 + threadIdx.x) * 4;
    float4 v = *(const float4*)&src[i];
    uint32_t hx = bf16_rn_bits(v.x), hy = bf16_rn_bits(v.y);
    uint32_t hz = bf16_rn_bits(v.z), hw = bf16_rn_bits(v.w);
    float lx = v.x - __uint_as_float(hx << 16);
    float ly = v.y - __uint_as_float(hy << 16);
    float lz = v.z - __uint_as_float(hz << 16);
    float lw = v.w - __uint_as_float(hw << 16);
    *(uint2*)&H[i] = make_uint2(hx | (hy << 16), hz | (hw << 16));
    *(uint2*)&L[i] = make_uint2(bf16_rn_bits(lx) | (bf16_rn_bits(ly) << 16),
                                bf16_rn_bits(lz) | (bf16_rn_bits(lw) << 16));
}

// ---------------------------------------------------------------------------
// P1: split + transpose weights: W[k][n] fp32 -> g_Wt{h,l}[g][n][k] bf16.
// grid (4), 256 threads.
// ---------------------------------------------------------------------------
__global__ __launch_bounds__(256) void split_weights(const float* __restrict__ Wfc0,
                                                     const float* __restrict__ WQ,
                                                     const float* __restrict__ WK,
                                                     const float* __restrict__ WV)
{
    const float* W;
    switch (blockIdx.x) {
        case 0:  W = Wfc0; break;
        case 1:  W = WQ;   break;
        case 2:  W = WK;   break;
        default: W = WV;   break;
    }
    __nv_bfloat16* H = g_Wth + blockIdx.x * DM * DM;
    __nv_bfloat16* L = g_Wtl + blockIdx.x * DM * DM;
    for (int idx = threadIdx.x; idx < DM * DM; idx += 256) {
        int k = idx >> 7, n = idx & 127;
        float x = W[idx];
        uint32_t hb = bf16_rn_bits(x);
        float lf = x - __uint_as_float(hb << 16);
        ((uint16_t*)H)[n * DM + k] = (uint16_t)hb;
        ((uint16_t*)L)[n * DM + k] = (uint16_t)bf16_rn_bits(lf);
    }
}

// ---------------------------------------------------------------------------
// P2: tensor-core projections. grid (NR/64, 4), 256 threads.
// Block: 64 rows x 128 cols of gemm blockIdx.y. Warp w: m-tile w>>1, n-half w&1.
// K in two 64-slices via cp.async. 3-product bf16 split MMA (~fp32 accuracy).
// ---------------------------------------------------------------------------
__global__ __launch_bounds__(256, 4) void proj_tc()
{
    extern __shared__ __nv_bfloat16 psm[];
    __nv_bfloat16* sAh  = psm + PA_H;
    __nv_bfloat16* sAl  = psm + PA_L;
    __nv_bfloat16* sWth = psm + PW_H;
    __nv_bfloat16* sWtl = psm + PW_L;

    const int tid  = threadIdx.x;
    const int w    = tid >> 5;
    const int lane = tid & 31;
    const int g    = lane >> 2;
    const int tig  = lane & 3;
    const int gm   = blockIdx.y;
    const int r0   = blockIdx.x * 64;

    // input selector: gemm 0 (R) and 1 (Q) read input 0; 2->K(1); 3->V(2)
    const int xsel = (gm <= 1) ? 0 : (gm - 1);
    const __nv_bfloat16* gXh = g_Xh + (size_t)xsel * NR * DM;
    const __nv_bfloat16* gXl = g_Xl + (size_t)xsel * NR * DM;
    const __nv_bfloat16* gWh = g_Wth + gm * DM * DM;
    const __nv_bfloat16* gWl = g_Wtl + gm * DM * DM;

    const int mt = w >> 1;            // 0..3
    const int nh = (w & 1) * 64;      // n offset
    const int m0 = mt * 16 + g;       // local rows
    const int m1 = m0 + 8;

    float acc[8][4];
#pragma unroll
    for (int nt = 0; nt < 8; nt++)
#pragma unroll
        for (int i = 0; i < 4; i++) acc[nt][i] = 0.f;

    for (int ks = 0; ks < 2; ks++) {
        if (ks) __syncthreads();          // previous slice's compute done
        // ---- cp.async load slice: A 64x64 hi/lo, Wt 128x64 hi/lo ----
        {
            // A: 512 16B tasks each (hi, lo) -> 2 per thread
#pragma unroll
            for (int it = 0; it < 2; it++) {
                int id = tid + it * 256;
                int row = id >> 3, seg = (id & 7) * 8;
                size_t src = (size_t)(r0 + row) * DM + ks * 64 + seg;
                cp16(sAh + row * PSTR + seg, gXh + src);
                cp16(sAl + row * PSTR + seg, gXl + src);
            }
            // Wt: 1024 tasks each -> 4 per thread
#pragma unroll
            for (int it = 0; it < 4; it++) {
                int id = tid + it * 256;
                int n = id >> 3, seg = (id & 7) * 8;
                size_t src = (size_t)n * DM + ks * 64 + seg;
                cp16(sWth + n * PSTR + seg, gWh + src);
                cp16(sWtl + n * PSTR + seg, gWl + src);
            }
        }
        cp_commit();
        cp_wait<0>();
        __syncthreads();

        // ---- compute slice ----
#pragma unroll
        for (int kk = 0; kk < 64; kk += 16) {
            const int dof = kk + tig * 2;
            uint32_t ah0 = *(const uint32_t*)&sAh[m0 * PSTR + dof];
            uint32_t ah1 = *(const uint32_t*)&sAh[m1 * PSTR + dof];
            uint32_t ah2 = *(const uint32_t*)&sAh[m0 * PSTR + dof + 8];
            uint32_t ah3 = *(const uint32_t*)&sAh[m1 * PSTR + dof + 8];
            uint32_t al0 = *(const uint32_t*)&sAl[m0 * PSTR + dof];
            uint32_t al1 = *(const uint32_t*)&sAl[m1 * PSTR + dof];
            uint32_t al2 = *(const uint32_t*)&sAl[m0 * PSTR + dof + 8];
            uint32_t al3 = *(const uint32_t*)&sAl[m1 * PSTR + dof + 8];
#pragma unroll
            for (int nt = 0; nt < 8; nt++) {
                int ncol = nh + nt * 8 + g;
                uint32_t bh0 = *(const uint32_t*)&sWth[ncol * PSTR + dof];
                uint32_t bh1 = *(const uint32_t*)&sWth[ncol * PSTR + dof + 8];
                uint32_t bl0 = *(const uint32_t*)&sWtl[ncol * PSTR + dof];
                uint32_t bl1 = *(const uint32_t*)&sWtl[ncol * PSTR + dof + 8];
                mma16816(acc[nt], ah0, ah1, ah2, ah3, bh0, bh1);
                mma16816(acc[nt], ah0, ah1, ah2, ah3, bl0, bl1);
                mma16816(acc[nt], al0, al1, al2, al3, bh0, bh1);
            }
        }
    }

    // ---- epilogue ----
    const size_t row0 = (size_t)(r0 + m0);
    const size_t row1 = row0 + 8;

    if (gm == 0) {                      // R: fp32
#pragma unroll
        for (int nt = 0; nt < 8; nt++) {
            int col = nh + nt * 8 + tig * 2;
            *(float2*)&g_R[row0 * DM + col] = make_float2(acc[nt][0], acc[nt][1]);
            *(float2*)&g_R[row1 * DM + col] = make_float2(acc[nt][2], acc[nt][3]);
        }
    } else if (gm == 1 || gm == 2) {    // Q/K: bf16 hi + lo
        __nv_bfloat16* H = (gm == 1) ? g_Qh : g_Kh;
        __nv_bfloat16* L = (gm == 1) ? g_Ql : g_Kl;
#pragma unroll
        for (int nt = 0; nt < 8; nt++) {
            int col = nh + nt * 8 + tig * 2;
#pragma unroll
            for (int rr = 0; rr < 2; rr++) {
                float f0 = acc[nt][rr * 2], f1 = acc[nt][rr * 2 + 1];
                uint32_t h0 = bf16_rn_bits(f0), h1 = bf16_rn_bits(f1);
                float l0 = f0 - __uint_as_float(h0 << 16);
                float l1 = f1 - __uint_as_float(h1 << 16);
                size_t off = (rr ? row1 : row0) * DM + col;
                *(uint32_t*)&H[off] = h0 | (h1 << 16);
                *(uint32_t*)&L[off] = bf16_rn_bits(l0) | (bf16_rn_bits(l1) << 16);
            }
        }
    } else {                            // V: stage bf16 in smem, transpose out
        uint16_t* sV = (uint16_t*)(psm + PW_H);   // reuse Wt area: [64][VSTR]
        __syncthreads();                // all warps done reading sWt
#pragma unroll
        for (int nt = 0; nt < 8; nt++) {
            int col = nh + nt * 8 + tig * 2;
            *(uint32_t*)&sV[m0 * VSTR + col] =
                bf16_rn_bits(acc[nt][0]) | (bf16_rn_bits(acc[nt][1]) << 16);
            *(uint32_t*)&sV[m1 * VSTR + col] =
                bf16_rn_bits(acc[nt][2]) | (bf16_rn_bits(acc[nt][3]) << 16);
        }
        __syncthreads();
        const int v   = tid >> 3;            // 0..31
        const int seg = (tid & 7) * 8;       // 0..56
        const int b   = r0 / SEQ;
        const int sblock = r0 % SEQ;
#pragma unroll
        for (int hd = 0; hd < 4; hd++) {
            uint32_t wv[4];
#pragma unroll
            for (int p = 0; p < 4; p++) {
                uint32_t lo = sV[(seg + p * 2) * VSTR + hd * 32 + v];
                uint32_t hi = sV[(seg + p * 2 + 1) * VSTR + hd * 32 + v];
                wv[p] = lo | (hi << 16);
            }
            size_t off = ((size_t)(b * 4 + hd) * 32 + v) * SEQ + sblock + seg;
            *(uint4*)&g_Vt[off] = make_uint4(wv[0], wv[1], wv[2], wv[3]);
        }
    }
}

// ---------------------------------------------------------------------------
// K2: tensor-core attention (unchanged from R9).
// ---------------------------------------------------------------------------
__global__ __launch_bounds__(256, 4) void attn_mma(const unsigned char* __restrict__ mask,
                                                   float* __restrict__ attn)
{
    extern __shared__ __nv_bfloat16 smb[];
    __shared__ float srow[128];

    const int tid  = threadIdx.x;
    const int w    = tid >> 5;
    const int lane = tid & 31;
    const int g    = lane >> 2;
    const int tig  = lane & 3;
    const int qb   = w * 16;

    const int bh = blockIdx.y;
    const int b = bh >> 2, h = bh & 3;
    const int q0 = blockIdx.x * TQ;
    const float CE = 1.4426950408889634f * 0.17677669529663689f;
    const int mmode = g_mask_mode;
    const size_t bS = (size_t)b * SEQ;

    const int kj   = tid >> 2;
    const int kseg = (tid & 3) * 8;
    const int vv   = tid >> 3;
    const int vseg = (tid & 7) * 8;
    const __nv_bfloat16* gK_h = g_Kh + bS * DM + h * 32;
    const __nv_bfloat16* gK_l = g_Kl + bS * DM + h * 32;
    const __nv_bfloat16* gV_t = g_Vt + ((size_t)bh * 32 + vv) * SEQ;

    auto issue_chunk = [&](int kc) {
        __nv_bfloat16* kh = smb + (kc % 3) * BUF_SZ;
        __nv_bfloat16* kl = kh + 64 * QSTR;
        __nv_bfloat16* vh = kl + 64 * QSTR;
        size_t koff = (size_t)(kc * TK + kj) * DM + kseg;
        cp16(kh + kj * QSTR + kseg, gK_h + koff);
        cp16(kl + kj * QSTR + kseg, gK_l + koff);
        cp16(vh + vv * ESTR + vseg, gV_t + kc * TK + vseg);
    };

    issue_chunk(0);
    cp_commit();
    issue_chunk(1);
    cp_commit();

    uint32_t qh[2][4], ql[2][4];
    {
        const __nv_bfloat16* gQ_h = g_Qh + (bS + q0) * DM + h * 32;
        const __nv_bfloat16* gQ_l = g_Ql + (bS + q0) * DM + h * 32;
#pragma unroll
        for (int kk = 0; kk < 2; kk++) {
            int c0 = kk * 16 + tig * 2;
            size_t r0o = (size_t)(qb + g) * DM + c0;
            size_t r1o = (size_t)(qb + g + 8) * DM + c0;
            qh[kk][0] = *(const uint32_t*)&gQ_h[r0o];
            qh[kk][1] = *(const uint32_t*)&gQ_h[r1o];
            qh[kk][2] = *(const uint32_t*)&gQ_h[r0o + 8];
            qh[kk][3] = *(const uint32_t*)&gQ_h[r1o + 8];
            ql[kk][0] = *(const uint32_t*)&gQ_l[r0o];
            ql[kk][1] = *(const uint32_t*)&gQ_l[r1o];
            ql[kk][2] = *(const uint32_t*)&gQ_l[r0o + 8];
            ql[kk][3] = *(const uint32_t*)&gQ_l[r1o + 8];
        }
    }

    float rs0 = 0.f, rs1 = 0.f;
    float cacc[4][4];
#pragma unroll
    for (int n = 0; n < 4; n++)
#pragma unroll
        for (int i = 0; i < 4; i++) cacc[n][i] = 0.f;

    const int qg0 = q0 + qb + g;
    const size_t arow0 = ((size_t)bh * SEQ + qg0) * SEQ;
    const size_t arow1 = arow0 + 8 * SEQ;
    const size_t mrow0 = (bS + qg0) * SEQ;
    const size_t mrow1 = mrow0 + 8 * SEQ;

    for (int kc = 0; kc < NC; kc++) {
        const int k0 = kc * TK;

        cp_wait<1>();
        __syncthreads();
        if (kc + 2 < NC) issue_chunk(kc + 2);
        cp_commit();

        const __nv_bfloat16* kh = smb + (kc % 3) * BUF_SZ;
        const __nv_bfloat16* kl = kh + 64 * QSTR;
        const __nv_bfloat16* vh = kl + 64 * QSTR;

#pragma unroll
        for (int jj = 0; jj < 4; jj++) {
            const int jm = jj * 16 + tig * 2;
            uint2 pmc[4];
            pmc[0] = load_mask2(mask, mrow0 + k0 + jm, mmode);
            pmc[1] = load_mask2(mask, mrow1 + k0 + jm, mmode);
            pmc[2] = load_mask2(mask, mrow0 + k0 + jm + 8, mmode);
            pmc[3] = load_mask2(mask, mrow1 + k0 + jm + 8, mmode);

            uint32_t eh[2][2];
#pragma unroll
            for (int s = 0; s < 2; s++) {
                const int j0 = jj * 16 + s * 8;
                float c[4] = {0.f, 0.f, 0.f, 0.f};
#pragma unroll
                for (int kk = 0; kk < 2; kk++) {
                    int dof = kk * 16 + tig * 2;
                    uint32_t bh0 = *(const uint32_t*)&kh[(j0 + g) * QSTR + dof];
                    uint32_t bh1 = *(const uint32_t*)&kh[(j0 + g) * QSTR + dof + 8];
                    uint32_t bl0 = *(const uint32_t*)&kl[(j0 + g) * QSTR + dof];
                    uint32_t bl1 = *(const uint32_t*)&kl[(j0 + g) * QSTR + dof + 8];
                    mma16816(c, qh[kk][0], qh[kk][1], qh[kk][2], qh[kk][3], bh0, bh1);
                    mma16816(c, qh[kk][0], qh[kk][1], qh[kk][2], qh[kk][3], bl0, bl1);
                    mma16816(c, ql[kk][0], ql[kk][1], ql[kk][2], ql[kk][3], bh0, bh1);
                }
                const int jgl = k0 + j0 + tig * 2;
                uint2 m0 = pmc[s * 2];
                uint2 m1 = pmc[s * 2 + 1];
                float e00 = m0.x ? 0.f : exp2_poly(c[0] * CE);
                float e01 = m0.y ? 0.f : exp2_poly(c[1] * CE);
                float e10 = m1.x ? 0.f : exp2_poly(c[2] * CE);
                float e11 = m1.y ? 0.f : exp2_poly(c[3] * CE);
                rs0 += e00 + e01;
                rs1 += e10 + e11;
                *(float2*)(attn + arow0 + jgl) = make_float2(e00, e01);
                *(float2*)(attn + arow1 + jgl) = make_float2(e10, e11);
                eh[s][0] = pack_bf16x2(e00, e01);
                eh[s][1] = pack_bf16x2(e10, e11);
            }
            const int c0 = jj * 16 + tig * 2;
#pragma unroll
            for (int nt2 = 0; nt2 < 4; nt2++) {
                int v0 = nt2 * 8;
                uint32_t vb0 = *(const uint32_t*)&vh[(v0 + g) * ESTR + c0];
                uint32_t vb1 = *(const uint32_t*)&vh[(v0 + g) * ESTR + c0 + 8];
                mma16816(cacc[nt2], eh[0][0], eh[0][1], eh[1][0], eh[1][1], vb0, vb1);
            }
        }
    }

    rs0 += __shfl_xor_sync(0xffffffff, rs0, 1);
    rs0 += __shfl_xor_sync(0xffffffff, rs0, 2);
    rs1 += __shfl_xor_sync(0xffffffff, rs1, 1);
    rs1 += __shfl_xor_sync(0xffffffff, rs1, 2);
    __syncthreads();
    if (tig == 0) {
        srow[qb + g]     = rs0;
        srow[qb + g + 8] = rs1;
    }
    __syncthreads();
    if (tid < 128) {
        float r = 1.0f / srow[tid];
        g_rinv[(size_t)bh * SEQ + q0 + tid] = r;
        srow[tid] = r;
    }
    __syncthreads();

    {
        float r0 = srow[qb + g];
        float r1 = srow[qb + g + 8];
        size_t row0 = (bS + q0 + qb + g) * (size_t)DM + h * 32;
        size_t row1 = row0 + 8 * DM;
#pragma unroll
        for (int nt = 0; nt < 4; nt++) {
            int v = nt * 8 + tig * 2;
            *(float2*)&g_ctx[row0 + v] = make_float2(cacc[nt][0] * r0, cacc[nt][1] * r0);
            *(float2*)&g_ctx[row1 + v] = make_float2(cacc[nt][2] * r1, cacc[nt][3] * r1);
        }
    }
}

// ---------------------------------------------------------------------------
// K3: attn *= rinv[row]
// ---------------------------------------------------------------------------
__global__ void norm_attn(float* __restrict__ attn)
{
    size_t i = (size_t)blockIdx.x * blockDim.x + threadIdx.x;
    size_t row = i >> 9;
    float r = __ldg(&g_rinv[row]);
    float4* p = (float4*)attn;
    float4 v = p[i];
    v.x *= r; v.y *= r; v.z *= r; v.w *= r;
    p[i] = v;
}

// ---------------------------------------------------------------------------
// K4: out = LayerNorm(g_ctx @ W_fc + g_R) * gamma + beta
// ---------------------------------------------------------------------------
__global__ __launch_bounds__(256) void out_ln(const float* __restrict__ Wfc,
                                              const float* __restrict__ gamma,
                                              const float* __restrict__ beta,
                                              float* __restrict__ out)
{
    __shared__ float sA[64][36];
    __shared__ float sW[32][132];
    __shared__ float red1[64][17];
    __shared__ float red2[64][17];
    __shared__ float smu[64];
    __shared__ float srs[64];

    const int tid = threadIdx.x;
    const int tx = tid & 15, ty = tid >> 4;
    const int r0 = blockIdx.x * 64;

    float acc[4][8];
#pragma unroll
    for (int r = 0; r < 4; r++)
#pragma unroll
        for (int c = 0; c < 8; c++) acc[r][c] = 0.f;

    for (int kk = 0; kk < DM; kk += 32) {
        for (int t = tid; t < 64 * 32; t += 256) {
            int r = t >> 5, i = t & 31;
            sA[r][i] = g_ctx[(size_t)(r0 + r) * DM + kk + i];
        }
        for (int t = tid; t < 32 * 128; t += 256) {
            int i = t >> 7, c = t & 127;
            sW[i][c] = Wfc[(size_t)(kk + i) * DM + c];
        }
        __syncthreads();
#pragma unroll
        for (int i = 0; i < 32; i++) {
            float a[4];
#pragma unroll
            for (int r = 0; r < 4; r++) a[r] = sA[ty * 4 + r][i];
            float4 w0 = *(const float4*)&sW[i][tx * 8];
            float4 w1 = *(const float4*)&sW[i][tx * 8 + 4];
            float wv[8] = {w0.x, w0.y, w0.z, w0.w, w1.x, w1.y, w1.z, w1.w};
#pragma unroll
            for (int r = 0; r < 4; r++)
#pragma unroll
                for (int c = 0; c < 8; c++) acc[r][c] += a[r] * wv[c];
        }
        __syncthreads();
    }

#pragma unroll
    for (int r = 0; r < 4; r++) {
        size_t row = (size_t)(r0 + ty * 4 + r);
        float4 rv0 = *(const float4*)&g_R[row * DM + tx * 8];
        float4 rv1 = *(const float4*)&g_R[row * DM + tx * 8 + 4];
        float rsv[8] = {rv0.x, rv0.y, rv0.z, rv0.w, rv1.x, rv1.y, rv1.z, rv1.w};
        float ps = 0.f, pq = 0.f;
#pragma unroll
        for (int c = 0; c < 8; c++) {
            acc[r][c] += rsv[c];
            ps += acc[r][c];
            pq += acc[r][c] * acc[r][c];
        }
        red1[ty * 4 + r][tx] = ps;
        red2[ty * 4 + r][tx] = pq;
    }
    __syncthreads();
    if (tid < 64) {
        float s = 0.f, q = 0.f;
#pragma unroll
        for (int j = 0; j < 16; j++) { s += red1[tid][j]; q += red2[tid][j]; }
        float mu = s * (1.0f / 128.0f);
        float var = q * (1.0f / 128.0f) - mu * mu;
        smu[tid] = mu;
        srs[tid] = rsqrtf(var + 1e-5f);
    }
    __syncthreads();

    float4 g0 = *(const float4*)&gamma[tx * 8];
    float4 g1 = *(const float4*)&gamma[tx * 8 + 4];
    float4 b0 = *(const float4*)&beta[tx * 8];
    float4 b1 = *(const float4*)&beta[tx * 8 + 4];
    float gs[8] = {g0.x, g0.y, g0.z, g0.w, g1.x, g1.y, g1.z, g1.w};
    float bs[8] = {b0.x, b0.y, b0.z, b0.w, b1.x, b1.y, b1.z, b1.w};

#pragma unroll
    for (int r = 0; r < 4; r++) {
        float mu = smu[ty * 4 + r];
        float rstd = srs[ty * 4 + r];
        size_t row = (size_t)(r0 + ty * 4 + r);
        float o[8];
#pragma unroll
        for (int c = 0; c < 8; c++) o[c] = (acc[r][c] - mu) * rstd * gs[c] + bs[c];
        *(float4*)&out[row * DM + tx * 8]     = make_float4(o[0], o[1], o[2], o[3]);
        *(float4*)&out[row * DM + tx * 8 + 4] = make_float4(o[4], o[5], o[6], o[7]);
    }
}

// ---------------------------------------------------------------------------
extern "C" void kernel_launch(void* const* d_in, const int* in_sizes, int n_in,
                              void* d_out, int out_size)
{
    const float* inQ  = (const float*)d_in[0];
    const float* inK  = (const float*)d_in[1];
    const float* inV  = (const float*)d_in[2];
    const unsigned char* mask = (const unsigned char*)d_in[3];
    const float* Wfc0 = (const float*)d_in[4];
    const float* WQ   = (const float*)d_in[5];
    const float* WK   = (const float*)d_in[6];
    const float* WV   = (const float*)d_in[7];
    const float* Wfc  = (const float*)d_in[8];
    const float* gam  = (const float*)d_in[9];
    const float* bet  = (const float*)d_in[10];
    float* out  = (float*)d_out;
    float* attn = out + OUT_ELEMS;

    detect_mask<<<1, 256>>>(mask);                             // launch 1
    split_inputs<<<dim3(NR * DM / 1024, 3), 256>>>(inQ, inK, inV);  // 2
    split_weights<<<4, 256>>>(Wfc0, WQ, WK, WV);               // 3
    zero_rinv<<<BATCH * 4 * SEQ / 256, 256>>>();               // 4 (filler)

    cudaFuncSetAttribute(proj_tc, cudaFuncAttributeMaxDynamicSharedMemorySize,
                         (int)P_SMEM_BYTES);
    proj_tc<<<dim3(NR / 64, 4), 256, P_SMEM_BYTES>>>();        // 5

    cudaFuncSetAttribute(attn_mma, cudaFuncAttributeMaxDynamicSharedMemorySize,
                         (int)SMEM_BYTES);
    dim3 agrid(SEQ / TQ, BATCH * 4);
    attn_mma<<<agrid, 256, SMEM_BYTES>>>(mask, attn);          // 6 (ncu window)

    size_t nf4 = (size_t)BATCH * 4 * SEQ * SEQ / 4;
    norm_attn<<<(unsigned)(nf4 / 256), 256>>>(attn);

    out_ln<<<NR / 64, 256>>>(Wfc, gam, bet, out);
}

// round 11
// speedup vs baseline: 1.3285x; 1.0133x over previous
#include <cuda_runtime.h>
#include <cuda_bf16.h>
#include <stdint.h>

// ---------------------------------------------------------------------------
// MultiHeadAttention: out = LN(ctx@W_fc + X@W_fc0), attn materialized.
// B=8, S=2048, D=128, H=4, dk=dv=32.
// Output layout: [out (8*2048*128)] then [attn (8*4*2048*2048)].
// R11: K2 exp moved to MUFU (ex2.approx) — frees ~220 FMA issue slots per
// thread per chunk; score MMA chain split into two accumulators (depth 6->3).
// ---------------------------------------------------------------------------

namespace {
constexpr int BATCH = 8;
constexpr int SEQ   = 2048;
constexpr int DM    = 128;
constexpr int NR    = BATCH * SEQ;                 // 16384 rows
constexpr size_t OUT_ELEMS = (size_t)NR * DM;      // 2,097,152
constexpr int TQ = 128;                            // q-tile per block (K2)
constexpr int TK = 64;                             // k-chunk (K2)
constexpr int NC = SEQ / TK;                       // 32 chunks

// K2 smem (bf16 units)
constexpr int QSTR = 40;
constexpr int ESTR = 72;
constexpr int BUF_SZ  = 64 * QSTR * 2 + 32 * ESTR;
constexpr int SMEM_BF16 = 3 * BUF_SZ;
constexpr size_t SMEM_BYTES = (size_t)SMEM_BF16 * 2;  // 44,544 B

// proj_tc smem (bf16 units)
constexpr int PSTR = 72;
constexpr int PA_H = 0;
constexpr int PA_L = PA_H + 64 * PSTR;
constexpr int PW_H = PA_L + 64 * PSTR;
constexpr int PW_L = PW_H + 128 * PSTR;
constexpr int P_BF16 = PW_L + 128 * PSTR;
constexpr size_t P_SMEM_BYTES = (size_t)P_BF16 * 2;   // 55,296 B
constexpr int VSTR = 136;
}

// Scratch (device globals: allocation-free rule)
__device__ float g_R  [NR * DM];
__device__ float g_ctx[NR * DM];
__device__ float g_rinv[BATCH * 4 * SEQ];
__device__ __nv_bfloat16 g_Xh[3 * NR * DM];
__device__ __nv_bfloat16 g_Xl[3 * NR * DM];
__device__ __nv_bfloat16 g_Wth[4 * DM * DM];
__device__ __nv_bfloat16 g_Wtl[4 * DM * DM];
__device__ __nv_bfloat16 g_Qh[NR * DM];
__device__ __nv_bfloat16 g_Ql[NR * DM];
__device__ __nv_bfloat16 g_Kh[NR * DM];
__device__ __nv_bfloat16 g_Kl[NR * DM];
__device__ __nv_bfloat16 g_Vt[(size_t)BATCH * 4 * 32 * SEQ];  // [bh][v][s]
__device__ int   g_mask_mode;   // 0=uint8, 1=int32, 2=float32

// ---------------------------------------------------------------------------
// MUFU exp2: 1 MUFU op (pipe otherwise idle in K2); rel err ~2^-21.
__device__ __forceinline__ float ex2(float y)
{
    float r;
    asm("ex2.approx.f32 %0, %1;" : "=f"(r) : "f"(y));
    return r;
}

__device__ __forceinline__ uint32_t pack_bf16x2(float lo, float hi)
{
    uint32_t r;
    asm("cvt.rn.bf16x2.f32 %0, %1, %2;" : "=r"(r) : "f"(hi), "f"(lo));
    return r;
}

__device__ __forceinline__ uint32_t bf16_rn_bits(float x)
{
    uint32_t b = __float_as_uint(x);
    return (b + 0x7fffu + ((b >> 16) & 1u)) >> 16;
}

__device__ __forceinline__ void mma16816(float c[4],
                                         uint32_t a0, uint32_t a1, uint32_t a2, uint32_t a3,
                                         uint32_t b0, uint32_t b1)
{
    asm volatile("mma.sync.aligned.m16n8k16.row.col.f32.bf16.bf16.f32 "
                 "{%0,%1,%2,%3}, {%4,%5,%6,%7}, {%8,%9}, {%0,%1,%2,%3};"
                 : "+f"(c[0]), "+f"(c[1]), "+f"(c[2]), "+f"(c[3])
                 : "r"(a0), "r"(a1), "r"(a2), "r"(a3), "r"(b0), "r"(b1));
}

__device__ __forceinline__ void cp16(const __nv_bfloat16* smem_dst, const void* gsrc)
{
    uint32_t d = (uint32_t)__cvta_generic_to_shared(smem_dst);
    asm volatile("cp.async.cg.shared.global [%0], [%1], 16;" :: "r"(d), "l"(gsrc));
}
__device__ __forceinline__ void cp_commit()
{
    asm volatile("cp.async.commit_group;");
}
template <int N>
__device__ __forceinline__ void cp_wait()
{
    asm volatile("cp.async.wait_group %0;" :: "n"(N));
}

// ---------------------------------------------------------------------------
// K0: detect mask dtype.
// ---------------------------------------------------------------------------
__global__ void detect_mask(const unsigned char* __restrict__ m)
{
    __shared__ int s_gt1, s_off;
    if (threadIdx.x == 0) { s_gt1 = 0; s_off = 0; }
    __syncthreads();
    int gt1 = 0, off = 0;
    for (int i = threadIdx.x; i < 4096; i += 256) {
        unsigned char v = m[i];
        if (v > 1) gt1 = 1;
        else if (v == 1 && (i & 3) != 0) off = 1;
    }
    if (gt1) atomicOr(&s_gt1, 1);
    if (off) atomicOr(&s_off, 1);
    __syncthreads();
    if (threadIdx.x == 0)
        g_mask_mode = s_gt1 ? 2 : (s_off ? 0 : 1);
}

// filler: keeps ncu -s 5 window on attn_mma (launch #6)
__global__ void zero_rinv()
{
    g_rinv[blockIdx.x * 256 + threadIdx.x] = 0.f;
}

__device__ __forceinline__ uint2 load_mask2(const unsigned char* __restrict__ mask,
                                            size_t idx, int mode)
{
    if (mode == 0) {
        uchar2 m = *(const uchar2*)(mask + idx);
        return make_uint2(m.x, m.y);
    } else if (mode == 1) {
        int2 m = *(const int2*)((const int*)mask + idx);
        return make_uint2((unsigned)m.x, (unsigned)m.y);
    } else {
        float2 m = *(const float2*)((const float*)mask + idx);
        return make_uint2(m.x != 0.f, m.y != 0.f);
    }
}

// ---------------------------------------------------------------------------
// P0: split inputs fp32 -> bf16 hi/lo.
// ---------------------------------------------------------------------------
__global__ __launch_bounds__(256) void split_inputs(const float* __restrict__ inQ,
                                                    const float* __restrict__ inK,
                                                    const float* __restrict__ inV)
{
    const float* src = (blockIdx.y == 0) ? inQ : (blockIdx.y == 1) ? inK : inV;
    __nv_bfloat16* H = g_Xh + (size_t)blockIdx.y * NR * DM;
    __nv_bfloat16* L = g_Xl + (size_t)blockIdx.y * NR * DM;
    size_t i = ((size_t)blockIdx.x * 256 + threadIdx.x) * 4;
    float4 v = *(const float4*)&src[i];
    uint32_t hx = bf16_rn_bits(v.x), hy = bf16_rn_bits(v.y);
    uint32_t hz = bf16_rn_bits(v.z), hw = bf16_rn_bits(v.w);
    float lx = v.x - __uint_as_float(hx << 16);
    float ly = v.y - __uint_as_float(hy << 16);
    float lz = v.z - __uint_as_float(hz << 16);
    float lw = v.w - __uint_as_float(hw << 16);
    *(uint2*)&H[i] = make_uint2(hx | (hy << 16), hz | (hw << 16));
    *(uint2*)&L[i] = make_uint2(bf16_rn_bits(lx) | (bf16_rn_bits(ly) << 16),
                                bf16_rn_bits(lz) | (bf16_rn_bits(lw) << 16));
}

// ---------------------------------------------------------------------------
// P1: split + transpose weights.
// ---------------------------------------------------------------------------
__global__ __launch_bounds__(256) void split_weights(const float* __restrict__ Wfc0,
                                                     const float* __restrict__ WQ,
                                                     const float* __restrict__ WK,
                                                     const float* __restrict__ WV)
{
    const float* W;
    switch (blockIdx.x) {
        case 0:  W = Wfc0; break;
        case 1:  W = WQ;   break;
        case 2:  W = WK;   break;
        default: W = WV;   break;
    }
    __nv_bfloat16* H = g_Wth + blockIdx.x * DM * DM;
    __nv_bfloat16* L = g_Wtl + blockIdx.x * DM * DM;
    for (int idx = threadIdx.x; idx < DM * DM; idx += 256) {
        int k = idx >> 7, n = idx & 127;
        float x = W[idx];
        uint32_t hb = bf16_rn_bits(x);
        float lf = x - __uint_as_float(hb << 16);
        ((uint16_t*)H)[n * DM + k] = (uint16_t)hb;
        ((uint16_t*)L)[n * DM + k] = (uint16_t)bf16_rn_bits(lf);
    }
}

// ---------------------------------------------------------------------------
// P2: tensor-core projections (unchanged from R10).
// ---------------------------------------------------------------------------
__global__ __launch_bounds__(256, 4) void proj_tc()
{
    extern __shared__ __nv_bfloat16 psm[];
    __nv_bfloat16* sAh  = psm + PA_H;
    __nv_bfloat16* sAl  = psm + PA_L;
    __nv_bfloat16* sWth = psm + PW_H;
    __nv_bfloat16* sWtl = psm + PW_L;

    const int tid  = threadIdx.x;
    const int w    = tid >> 5;
    const int lane = tid & 31;
    const int g    = lane >> 2;
    const int tig  = lane & 3;
    const int gm   = blockIdx.y;
    const int r0   = blockIdx.x * 64;

    const int xsel = (gm <= 1) ? 0 : (gm - 1);
    const __nv_bfloat16* gXh = g_Xh + (size_t)xsel * NR * DM;
    const __nv_bfloat16* gXl = g_Xl + (size_t)xsel * NR * DM;
    const __nv_bfloat16* gWh = g_Wth + gm * DM * DM;
    const __nv_bfloat16* gWl = g_Wtl + gm * DM * DM;

    const int mt = w >> 1;
    const int nh = (w & 1) * 64;
    const int m0 = mt * 16 + g;
    const int m1 = m0 + 8;

    float acc[8][4];
#pragma unroll
    for (int nt = 0; nt < 8; nt++)
#pragma unroll
        for (int i = 0; i < 4; i++) acc[nt][i] = 0.f;

    for (int ks = 0; ks < 2; ks++) {
        if (ks) __syncthreads();
        {
#pragma unroll
            for (int it = 0; it < 2; it++) {
                int id = tid + it * 256;
                int row = id >> 3, seg = (id & 7) * 8;
                size_t src = (size_t)(r0 + row) * DM + ks * 64 + seg;
                cp16(sAh + row * PSTR + seg, gXh + src);
                cp16(sAl + row * PSTR + seg, gXl + src);
            }
#pragma unroll
            for (int it = 0; it < 4; it++) {
                int id = tid + it * 256;
                int n = id >> 3, seg = (id & 7) * 8;
                size_t src = (size_t)n * DM + ks * 64 + seg;
                cp16(sWth + n * PSTR + seg, gWh + src);
                cp16(sWtl + n * PSTR + seg, gWl + src);
            }
        }
        cp_commit();
        cp_wait<0>();
        __syncthreads();

#pragma unroll
        for (int kk = 0; kk < 64; kk += 16) {
            const int dof = kk + tig * 2;
            uint32_t ah0 = *(const uint32_t*)&sAh[m0 * PSTR + dof];
            uint32_t ah1 = *(const uint32_t*)&sAh[m1 * PSTR + dof];
            uint32_t ah2 = *(const uint32_t*)&sAh[m0 * PSTR + dof + 8];
            uint32_t ah3 = *(const uint32_t*)&sAh[m1 * PSTR + dof + 8];
            uint32_t al0 = *(const uint32_t*)&sAl[m0 * PSTR + dof];
            uint32_t al1 = *(const uint32_t*)&sAl[m1 * PSTR + dof];
            uint32_t al2 = *(const uint32_t*)&sAl[m0 * PSTR + dof + 8];
            uint32_t al3 = *(const uint32_t*)&sAl[m1 * PSTR + dof + 8];
#pragma unroll
            for (int nt = 0; nt < 8; nt++) {
                int ncol = nh + nt * 8 + g;
                uint32_t bh0 = *(const uint32_t*)&sWth[ncol * PSTR + dof];
                uint32_t bh1 = *(const uint32_t*)&sWth[ncol * PSTR + dof + 8];
                uint32_t bl0 = *(const uint32_t*)&sWtl[ncol * PSTR + dof];
                uint32_t bl1 = *(const uint32_t*)&sWtl[ncol * PSTR + dof + 8];
                mma16816(acc[nt], ah0, ah1, ah2, ah3, bh0, bh1);
                mma16816(acc[nt], ah0, ah1, ah2, ah3, bl0, bl1);
                mma16816(acc[nt], al0, al1, al2, al3, bh0, bh1);
            }
        }
    }

    const size_t row0 = (size_t)(r0 + m0);
    const size_t row1 = row0 + 8;

    if (gm == 0) {
#pragma unroll
        for (int nt = 0; nt < 8; nt++) {
            int col = nh + nt * 8 + tig * 2;
            *(float2*)&g_R[row0 * DM + col] = make_float2(acc[nt][0], acc[nt][1]);
            *(float2*)&g_R[row1 * DM + col] = make_float2(acc[nt][2], acc[nt][3]);
        }
    } else if (gm == 1 || gm == 2) {
        __nv_bfloat16* H = (gm == 1) ? g_Qh : g_Kh;
        __nv_bfloat16* L = (gm == 1) ? g_Ql : g_Kl;
#pragma unroll
        for (int nt = 0; nt < 8; nt++) {
            int col = nh + nt * 8 + tig * 2;
#pragma unroll
            for (int rr = 0; rr < 2; rr++) {
                float f0 = acc[nt][rr * 2], f1 = acc[nt][rr * 2 + 1];
                uint32_t h0 = bf16_rn_bits(f0), h1 = bf16_rn_bits(f1);
                float l0 = f0 - __uint_as_float(h0 << 16);
                float l1 = f1 - __uint_as_float(h1 << 16);
                size_t off = (rr ? row1 : row0) * DM + col;
                *(uint32_t*)&H[off] = h0 | (h1 << 16);
                *(uint32_t*)&L[off] = bf16_rn_bits(l0) | (bf16_rn_bits(l1) << 16);
            }
        }
    } else {
        uint16_t* sV = (uint16_t*)(psm + PW_H);
        __syncthreads();
#pragma unroll
        for (int nt = 0; nt < 8; nt++) {
            int col = nh + nt * 8 + tig * 2;
            *(uint32_t*)&sV[m0 * VSTR + col] =
                bf16_rn_bits(acc[nt][0]) | (bf16_rn_bits(acc[nt][1]) << 16);
            *(uint32_t*)&sV[m1 * VSTR + col] =
                bf16_rn_bits(acc[nt][2]) | (bf16_rn_bits(acc[nt][3]) << 16);
        }
        __syncthreads();
        const int v   = tid >> 3;
        const int seg = (tid & 7) * 8;
        const int b   = r0 / SEQ;
        const int sblock = r0 % SEQ;
#pragma unroll
        for (int hd = 0; hd < 4; hd++) {
            uint32_t wv[4];
#pragma unroll
            for (int p = 0; p < 4; p++) {
                uint32_t lo = sV[(seg + p * 2) * VSTR + hd * 32 + v];
                uint32_t hi = sV[(seg + p * 2 + 1) * VSTR + hd * 32 + v];
                wv[p] = lo | (hi << 16);
            }
            size_t off = ((size_t)(b * 4 + hd) * 32 + v) * SEQ + sblock + seg;
            *(uint4*)&g_Vt[off] = make_uint4(wv[0], wv[1], wv[2], wv[3]);
        }
    }
}

// ---------------------------------------------------------------------------
// K2: tensor-core attention. MUFU exp; dual-accumulator score chains.
// ---------------------------------------------------------------------------
__global__ __launch_bounds__(256, 4) void attn_mma(const unsigned char* __restrict__ mask,
                                                   float* __restrict__ attn)
{
    extern __shared__ __nv_bfloat16 smb[];
    __shared__ float srow[128];

    const int tid  = threadIdx.x;
    const int w    = tid >> 5;
    const int lane = tid & 31;
    const int g    = lane >> 2;
    const int tig  = lane & 3;
    const int qb   = w * 16;

    const int bh = blockIdx.y;
    const int b = bh >> 2, h = bh & 3;
    const int q0 = blockIdx.x * TQ;
    const float CE = 1.4426950408889634f * 0.17677669529663689f;  // log2e/sqrt(32)
    const int mmode = g_mask_mode;
    const size_t bS = (size_t)b * SEQ;

    const int kj   = tid >> 2;
    const int kseg = (tid & 3) * 8;
    const int vv   = tid >> 3;
    const int vseg = (tid & 7) * 8;
    const __nv_bfloat16* gK_h = g_Kh + bS * DM + h * 32;
    const __nv_bfloat16* gK_l = g_Kl + bS * DM + h * 32;
    const __nv_bfloat16* gV_t = g_Vt + ((size_t)bh * 32 + vv) * SEQ;

    auto issue_chunk = [&](int kc) {
        __nv_bfloat16* kh = smb + (kc % 3) * BUF_SZ;
        __nv_bfloat16* kl = kh + 64 * QSTR;
        __nv_bfloat16* vh = kl + 64 * QSTR;
        size_t koff = (size_t)(kc * TK + kj) * DM + kseg;
        cp16(kh + kj * QSTR + kseg, gK_h + koff);
        cp16(kl + kj * QSTR + kseg, gK_l + koff);
        cp16(vh + vv * ESTR + vseg, gV_t + kc * TK + vseg);
    };

    issue_chunk(0);
    cp_commit();
    issue_chunk(1);
    cp_commit();

    uint32_t qh[2][4], ql[2][4];
    {
        const __nv_bfloat16* gQ_h = g_Qh + (bS + q0) * DM + h * 32;
        const __nv_bfloat16* gQ_l = g_Ql + (bS + q0) * DM + h * 32;
#pragma unroll
        for (int kk = 0; kk < 2; kk++) {
            int c0 = kk * 16 + tig * 2;
            size_t r0o = (size_t)(qb + g) * DM + c0;
            size_t r1o = (size_t)(qb + g + 8) * DM + c0;
            qh[kk][0] = *(const uint32_t*)&gQ_h[r0o];
            qh[kk][1] = *(const uint32_t*)&gQ_h[r1o];
            qh[kk][2] = *(const uint32_t*)&gQ_h[r0o + 8];
            qh[kk][3] = *(const uint32_t*)&gQ_h[r1o + 8];
            ql[kk][0] = *(const uint32_t*)&gQ_l[r0o];
            ql[kk][1] = *(const uint32_t*)&gQ_l[r1o];
            ql[kk][2] = *(const uint32_t*)&gQ_l[r0o + 8];
            ql[kk][3] = *(const uint32_t*)&gQ_l[r1o + 8];
        }
    }

    float rs0 = 0.f, rs1 = 0.f;
    float cacc[4][4];
#pragma unroll
    for (int n = 0; n < 4; n++)
#pragma unroll
        for (int i = 0; i < 4; i++) cacc[n][i] = 0.f;

    const int qg0 = q0 + qb + g;
    const size_t arow0 = ((size_t)bh * SEQ + qg0) * SEQ;
    const size_t arow1 = arow0 + 8 * SEQ;
    const size_t mrow0 = (bS + qg0) * SEQ;
    const size_t mrow1 = mrow0 + 8 * SEQ;

    for (int kc = 0; kc < NC; kc++) {
        const int k0 = kc * TK;

        cp_wait<1>();
        __syncthreads();
        if (kc + 2 < NC) issue_chunk(kc + 2);
        cp_commit();

        const __nv_bfloat16* kh = smb + (kc % 3) * BUF_SZ;
        const __nv_bfloat16* kl = kh + 64 * QSTR;
        const __nv_bfloat16* vh = kl + 64 * QSTR;

#pragma unroll
        for (int jj = 0; jj < 4; jj++) {
            const int jm = jj * 16 + tig * 2;
            uint2 pmc[4];
            pmc[0] = load_mask2(mask, mrow0 + k0 + jm, mmode);
            pmc[1] = load_mask2(mask, mrow1 + k0 + jm, mmode);
            pmc[2] = load_mask2(mask, mrow0 + k0 + jm + 8, mmode);
            pmc[3] = load_mask2(mask, mrow1 + k0 + jm + 8, mmode);

            uint32_t eh[2][2];
#pragma unroll
            for (int s = 0; s < 2; s++) {
                const int j0 = jj * 16 + s * 8;
                // dual accumulators: kk=0 chain -> c, kk=1 chain -> c2
                float c[4]  = {0.f, 0.f, 0.f, 0.f};
                float c2[4] = {0.f, 0.f, 0.f, 0.f};
                {
                    const int dof0 = tig * 2;
                    uint32_t bh0 = *(const uint32_t*)&kh[(j0 + g) * QSTR + dof0];
                    uint32_t bh1 = *(const uint32_t*)&kh[(j0 + g) * QSTR + dof0 + 8];
                    uint32_t bl0 = *(const uint32_t*)&kl[(j0 + g) * QSTR + dof0];
                    uint32_t bl1 = *(const uint32_t*)&kl[(j0 + g) * QSTR + dof0 + 8];
                    mma16816(c, qh[0][0], qh[0][1], qh[0][2], qh[0][3], bh0, bh1);
                    mma16816(c, qh[0][0], qh[0][1], qh[0][2], qh[0][3], bl0, bl1);
                    mma16816(c, ql[0][0], ql[0][1], ql[0][2], ql[0][3], bh0, bh1);
                }
                {
                    const int dof1 = 16 + tig * 2;
                    uint32_t bh0 = *(const uint32_t*)&kh[(j0 + g) * QSTR + dof1];
                    uint32_t bh1 = *(const uint32_t*)&kh[(j0 + g) * QSTR + dof1 + 8];
                    uint32_t bl0 = *(const uint32_t*)&kl[(j0 + g) * QSTR + dof1];
                    uint32_t bl1 = *(const uint32_t*)&kl[(j0 + g) * QSTR + dof1 + 8];
                    mma16816(c2, qh[1][0], qh[1][1], qh[1][2], qh[1][3], bh0, bh1);
                    mma16816(c2, qh[1][0], qh[1][1], qh[1][2], qh[1][3], bl0, bl1);
                    mma16816(c2, ql[1][0], ql[1][1], ql[1][2], ql[1][3], bh0, bh1);
                }
#pragma unroll
                for (int i = 0; i < 4; i++) c[i] += c2[i];

                const int jgl = k0 + j0 + tig * 2;
                uint2 m0 = pmc[s * 2];
                uint2 m1 = pmc[s * 2 + 1];
                float e00 = m0.x ? 0.f : ex2(c[0] * CE);
                float e01 = m0.y ? 0.f : ex2(c[1] * CE);
                float e10 = m1.x ? 0.f : ex2(c[2] * CE);
                float e11 = m1.y ? 0.f : ex2(c[3] * CE);
                rs0 += e00 + e01;
                rs1 += e10 + e11;
                *(float2*)(attn + arow0 + jgl) = make_float2(e00, e01);
                *(float2*)(attn + arow1 + jgl) = make_float2(e10, e11);
                eh[s][0] = pack_bf16x2(e00, e01);
                eh[s][1] = pack_bf16x2(e10, e11);
            }
            const int c0 = jj * 16 + tig * 2;
#pragma unroll
            for (int nt2 = 0; nt2 < 4; nt2++) {
                int v0 = nt2 * 8;
                uint32_t vb0 = *(const uint32_t*)&vh[(v0 + g) * ESTR + c0];
                uint32_t vb1 = *(const uint32_t*)&vh[(v0 + g) * ESTR + c0 + 8];
                mma16816(cacc[nt2], eh[0][0], eh[0][1], eh[1][0], eh[1][1], vb0, vb1);
            }
        }
    }

    rs0 += __shfl_xor_sync(0xffffffff, rs0, 1);
    rs0 += __shfl_xor_sync(0xffffffff, rs0, 2);
    rs1 += __shfl_xor_sync(0xffffffff, rs1, 1);
    rs1 += __shfl_xor_sync(0xffffffff, rs1, 2);
    __syncthreads();
    if (tig == 0) {
        srow[qb + g]     = rs0;
        srow[qb + g + 8] = rs1;
    }
    __syncthreads();
    if (tid < 128) {
        float r = 1.0f / srow[tid];
        g_rinv[(size_t)bh * SEQ + q0 + tid] = r;
        srow[tid] = r;
    }
    __syncthreads();

    {
        float r0 = srow[qb + g];
        float r1 = srow[qb + g + 8];
        size_t row0 = (bS + q0 + qb + g) * (size_t)DM + h * 32;
        size_t row1 = row0 + 8 * DM;
#pragma unroll
        for (int nt = 0; nt < 4; nt++) {
            int v = nt * 8 + tig * 2;
            *(float2*)&g_ctx[row0 + v] = make_float2(cacc[nt][0] * r0, cacc[nt][1] * r0);
            *(float2*)&g_ctx[row1 + v] = make_float2(cacc[nt][2] * r1, cacc[nt][3] * r1);
        }
    }
}

// ---------------------------------------------------------------------------
// K3: attn *= rinv[row]
// ---------------------------------------------------------------------------
__global__ void norm_attn(float* __restrict__ attn)
{
    size_t i = (size_t)blockIdx.x * blockDim.x + threadIdx.x;
    size_t row = i >> 9;
    float r = __ldg(&g_rinv[row]);
    float4* p = (float4*)attn;
    float4 v = p[i];
    v.x *= r; v.y *= r; v.z *= r; v.w *= r;
    p[i] = v;
}

// ---------------------------------------------------------------------------
// K4: out = LayerNorm(g_ctx @ W_fc + g_R) * gamma + beta
// ---------------------------------------------------------------------------
__global__ __launch_bounds__(256) void out_ln(const float* __restrict__ Wfc,
                                              const float* __restrict__ gamma,
                                              const float* __restrict__ beta,
                                              float* __restrict__ out)
{
    __shared__ float sA[64][36];
    __shared__ float sW[32][132];
    __shared__ float red1[64][17];
    __shared__ float red2[64][17];
    __shared__ float smu[64];
    __shared__ float srs[64];

    const int tid = threadIdx.x;
    const int tx = tid & 15, ty = tid >> 4;
    const int r0 = blockIdx.x * 64;

    float acc[4][8];
#pragma unroll
    for (int r = 0; r < 4; r++)
#pragma unroll
        for (int c = 0; c < 8; c++) acc[r][c] = 0.f;

    for (int kk = 0; kk < DM; kk += 32) {
        for (int t = tid; t < 64 * 32; t += 256) {
            int r = t >> 5, i = t & 31;
            sA[r][i] = g_ctx[(size_t)(r0 + r) * DM + kk + i];
        }
        for (int t = tid; t < 32 * 128; t += 256) {
            int i = t >> 7, c = t & 127;
            sW[i][c] = Wfc[(size_t)(kk + i) * DM + c];
        }
        __syncthreads();
#pragma unroll
        for (int i = 0; i < 32; i++) {
            float a[4];
#pragma unroll
            for (int r = 0; r < 4; r++) a[r] = sA[ty * 4 + r][i];
            float4 w0 = *(const float4*)&sW[i][tx * 8];
            float4 w1 = *(const float4*)&sW[i][tx * 8 + 4];
            float wv[8] = {w0.x, w0.y, w0.z, w0.w, w1.x, w1.y, w1.z, w1.w};
#pragma unroll
            for (int r = 0; r < 4; r++)
#pragma unroll
                for (int c = 0; c < 8; c++) acc[r][c] += a[r] * wv[c];
        }
        __syncthreads();
    }

#pragma unroll
    for (int r = 0; r < 4; r++) {
        size_t row = (size_t)(r0 + ty * 4 + r);
        float4 rv0 = *(const float4*)&g_R[row * DM + tx * 8];
        float4 rv1 = *(const float4*)&g_R[row * DM + tx * 8 + 4];
        float rsv[8] = {rv0.x, rv0.y, rv0.z, rv0.w, rv1.x, rv1.y, rv1.z, rv1.w};
        float ps = 0.f, pq = 0.f;
#pragma unroll
        for (int c = 0; c < 8; c++) {
            acc[r][c] += rsv[c];
            ps += acc[r][c];
            pq += acc[r][c] * acc[r][c];
        }
        red1[ty * 4 + r][tx] = ps;
        red2[ty * 4 + r][tx] = pq;
    }
    __syncthreads();
    if (tid < 64) {
        float s = 0.f, q = 0.f;
#pragma unroll
        for (int j = 0; j < 16; j++) { s += red1[tid][j]; q += red2[tid][j]; }
        float mu = s * (1.0f / 128.0f);
        float var = q * (1.0f / 128.0f) - mu * mu;
        smu[tid] = mu;
        srs[tid] = rsqrtf(var + 1e-5f);
    }
    __syncthreads();

    float4 g0 = *(const float4*)&gamma[tx * 8];
    float4 g1 = *(const float4*)&gamma[tx * 8 + 4];
    float4 b0 = *(const float4*)&beta[tx * 8];
    float4 b1 = *(const float4*)&beta[tx * 8 + 4];
    float gs[8] = {g0.x, g0.y, g0.z, g0.w, g1.x, g1.y, g1.z, g1.w};
    float bs[8] = {b0.x, b0.y, b0.z, b0.w, b1.x, b1.y, b1.z, b1.w};

#pragma unroll
    for (int r = 0; r < 4; r++) {
        float mu = smu[ty * 4 + r];
        float rstd = srs[ty * 4 + r];
        size_t row = (size_t)(r0 + ty * 4 + r);
        float o[8];
#pragma unroll
        for (int c = 0; c < 8; c++) o[c] = (acc[r][c] - mu) * rstd * gs[c] + bs[c];
        *(float4*)&out[row * DM + tx * 8]     = make_float4(o[0], o[1], o[2], o[3]);
        *(float4*)&out[row * DM + tx * 8 + 4] = make_float4(o[4], o[5], o[6], o[7]);
    }
}

// ---------------------------------------------------------------------------
extern "C" void kernel_launch(void* const* d_in, const int* in_sizes, int n_in,
                              void* d_out, int out_size)
{
    const float* inQ  = (const float*)d_in[0];
    const float* inK  = (const float*)d_in[1];
    const float* inV  = (const float*)d_in[2];
    const unsigned char* mask = (const unsigned char*)d_in[3];
    const float* Wfc0 = (const float*)d_in[4];
    const float* WQ   = (const float*)d_in[5];
    const float* WK   = (const float*)d_in[6];
    const float* WV   = (const float*)d_in[7];
    const float* Wfc  = (const float*)d_in[8];
    const float* gam  = (const float*)d_in[9];
    const float* bet  = (const float*)d_in[10];
    float* out  = (float*)d_out;
    float* attn = out + OUT_ELEMS;

    detect_mask<<<1, 256>>>(mask);                             // launch 1
    split_inputs<<<dim3(NR * DM / 1024, 3), 256>>>(inQ, inK, inV);  // 2
    split_weights<<<4, 256>>>(Wfc0, WQ, WK, WV);               // 3
    zero_rinv<<<BATCH * 4 * SEQ / 256, 256>>>();               // 4 (filler)

    cudaFuncSetAttribute(proj_tc, cudaFuncAttributeMaxDynamicSharedMemorySize,
                         (int)P_SMEM_BYTES);
    proj_tc<<<dim3(NR / 64, 4), 256, P_SMEM_BYTES>>>();        // 5

    cudaFuncSetAttribute(attn_mma, cudaFuncAttributeMaxDynamicSharedMemorySize,
                         (int)SMEM_BYTES);
    dim3 agrid(SEQ / TQ, BATCH * 4);
    attn_mma<<<agrid, 256, SMEM_BYTES>>>(mask, attn);          // 6 (ncu window)

    size_t nf4 = (size_t)BATCH * 4 * SEQ * SEQ / 4;
    norm_attn<<<(unsigned)(nf4 / 256), 256>>>(attn);

    out_ln<<<NR / 64, 256>>>(Wfc, gam, bet, out);
}

// round 12
// speedup vs baseline: 1.4111x; 1.0622x over previous
#include <cuda_runtime.h>
#include <cuda_bf16.h>
#include <stdint.h>

// ---------------------------------------------------------------------------
// MultiHeadAttention: out = LN(ctx@W_fc + X@W_fc0), attn materialized.
// B=8, S=2048, D=128, H=4, dk=dv=32.
// Output layout: [out (8*2048*128)] then [attn (8*4*2048*2048)].
// R12: rowsum pre-pass (1-product bf16 scores) -> attn written NORMALIZED in
// one pass; norm_attn kernel (156us of pure DRAM) deleted.
// ---------------------------------------------------------------------------

namespace {
constexpr int BATCH = 8;
constexpr int SEQ   = 2048;
constexpr int DM    = 128;
constexpr int NR    = BATCH * SEQ;                 // 16384 rows
constexpr size_t OUT_ELEMS = (size_t)NR * DM;      // 2,097,152
constexpr int TQ = 128;                            // q-tile per block (K2)
constexpr int TK = 64;                             // k-chunk (K2)
constexpr int NC = SEQ / TK;                       // 32 chunks

// K2 smem (bf16 units)
constexpr int QSTR = 40;
constexpr int ESTR = 72;
constexpr int BUF_SZ  = 64 * QSTR * 2 + 32 * ESTR;
constexpr int SMEM_BF16 = 3 * BUF_SZ;
constexpr size_t SMEM_BYTES = (size_t)SMEM_BF16 * 2;  // 44,544 B

// rowsum_pass smem: K-hi only, 3 buffers
constexpr int KBUF = 64 * QSTR;                    // 2560
constexpr size_t RS_SMEM_BYTES = (size_t)(3 * KBUF) * 2;  // 15,360 B

// proj_tc smem (bf16 units)
constexpr int PSTR = 72;
constexpr int PA_H = 0;
constexpr int PA_L = PA_H + 64 * PSTR;
constexpr int PW_H = PA_L + 64 * PSTR;
constexpr int PW_L = PW_H + 128 * PSTR;
constexpr int P_BF16 = PW_L + 128 * PSTR;
constexpr size_t P_SMEM_BYTES = (size_t)P_BF16 * 2;   // 55,296 B
constexpr int VSTR = 136;
}

// Scratch (device globals: allocation-free rule)
__device__ float g_R  [NR * DM];
__device__ float g_ctx[NR * DM];
__device__ float g_rinv[BATCH * 4 * SEQ];
__device__ __nv_bfloat16 g_Xh[3 * NR * DM];
__device__ __nv_bfloat16 g_Xl[3 * NR * DM];
__device__ __nv_bfloat16 g_Wth[4 * DM * DM];
__device__ __nv_bfloat16 g_Wtl[4 * DM * DM];
__device__ __nv_bfloat16 g_Qh[NR * DM];
__device__ __nv_bfloat16 g_Ql[NR * DM];
__device__ __nv_bfloat16 g_Kh[NR * DM];
__device__ __nv_bfloat16 g_Kl[NR * DM];
__device__ __nv_bfloat16 g_Vt[(size_t)BATCH * 4 * 32 * SEQ];  // [bh][v][s]
__device__ int   g_mask_mode;   // 0=uint8, 1=int32, 2=float32

// ---------------------------------------------------------------------------
__device__ __forceinline__ float ex2(float y)
{
    float r;
    asm("ex2.approx.f32 %0, %1;" : "=f"(r) : "f"(y));
    return r;
}

__device__ __forceinline__ uint32_t pack_bf16x2(float lo, float hi)
{
    uint32_t r;
    asm("cvt.rn.bf16x2.f32 %0, %1, %2;" : "=r"(r) : "f"(hi), "f"(lo));
    return r;
}

__device__ __forceinline__ uint32_t bf16_rn_bits(float x)
{
    uint32_t b = __float_as_uint(x);
    return (b + 0x7fffu + ((b >> 16) & 1u)) >> 16;
}

__device__ __forceinline__ void mma16816(float c[4],
                                         uint32_t a0, uint32_t a1, uint32_t a2, uint32_t a3,
                                         uint32_t b0, uint32_t b1)
{
    asm volatile("mma.sync.aligned.m16n8k16.row.col.f32.bf16.bf16.f32 "
                 "{%0,%1,%2,%3}, {%4,%5,%6,%7}, {%8,%9}, {%0,%1,%2,%3};"
                 : "+f"(c[0]), "+f"(c[1]), "+f"(c[2]), "+f"(c[3])
                 : "r"(a0), "r"(a1), "r"(a2), "r"(a3), "r"(b0), "r"(b1));
}

__device__ __forceinline__ void cp16(const __nv_bfloat16* smem_dst, const void* gsrc)
{
    uint32_t d = (uint32_t)__cvta_generic_to_shared(smem_dst);
    asm volatile("cp.async.cg.shared.global [%0], [%1], 16;" :: "r"(d), "l"(gsrc));
}
__device__ __forceinline__ void cp_commit()
{
    asm volatile("cp.async.commit_group;");
}
template <int N>
__device__ __forceinline__ void cp_wait()
{
    asm volatile("cp.async.wait_group %0;" :: "n"(N));
}

// ---------------------------------------------------------------------------
// K0: detect mask dtype.
// ---------------------------------------------------------------------------
__global__ void detect_mask(const unsigned char* __restrict__ m)
{
    __shared__ int s_gt1, s_off;
    if (threadIdx.x == 0) { s_gt1 = 0; s_off = 0; }
    __syncthreads();
    int gt1 = 0, off = 0;
    for (int i = threadIdx.x; i < 4096; i += 256) {
        unsigned char v = m[i];
        if (v > 1) gt1 = 1;
        else if (v == 1 && (i & 3) != 0) off = 1;
    }
    if (gt1) atomicOr(&s_gt1, 1);
    if (off) atomicOr(&s_off, 1);
    __syncthreads();
    if (threadIdx.x == 0)
        g_mask_mode = s_gt1 ? 2 : (s_off ? 0 : 1);
}

__device__ __forceinline__ uint2 load_mask2(const unsigned char* __restrict__ mask,
                                            size_t idx, int mode)
{
    if (mode == 0) {
        uchar2 m = *(const uchar2*)(mask + idx);
        return make_uint2(m.x, m.y);
    } else if (mode == 1) {
        int2 m = *(const int2*)((const int*)mask + idx);
        return make_uint2((unsigned)m.x, (unsigned)m.y);
    } else {
        float2 m = *(const float2*)((const float*)mask + idx);
        return make_uint2(m.x != 0.f, m.y != 0.f);
    }
}

// ---------------------------------------------------------------------------
// P0: split inputs fp32 -> bf16 hi/lo.
// ---------------------------------------------------------------------------
__global__ __launch_bounds__(256) void split_inputs(const float* __restrict__ inQ,
                                                    const float* __restrict__ inK,
                                                    const float* __restrict__ inV)
{
    const float* src = (blockIdx.y == 0) ? inQ : (blockIdx.y == 1) ? inK : inV;
    __nv_bfloat16* H = g_Xh + (size_t)blockIdx.y * NR * DM;
    __nv_bfloat16* L = g_Xl + (size_t)blockIdx.y * NR * DM;
    size_t i = ((size_t)blockIdx.x * 256 + threadIdx.x) * 4;
    float4 v = *(const float4*)&src[i];
    uint32_t hx = bf16_rn_bits(v.x), hy = bf16_rn_bits(v.y);
    uint32_t hz = bf16_rn_bits(v.z), hw = bf16_rn_bits(v.w);
    float lx = v.x - __uint_as_float(hx << 16);
    float ly = v.y - __uint_as_float(hy << 16);
    float lz = v.z - __uint_as_float(hz << 16);
    float lw = v.w - __uint_as_float(hw << 16);
    *(uint2*)&H[i] = make_uint2(hx | (hy << 16), hz | (hw << 16));
    *(uint2*)&L[i] = make_uint2(bf16_rn_bits(lx) | (bf16_rn_bits(ly) << 16),
                                bf16_rn_bits(lz) | (bf16_rn_bits(lw) << 16));
}

// ---------------------------------------------------------------------------
// P1: split + transpose weights.
// ---------------------------------------------------------------------------
__global__ __launch_bounds__(256) void split_weights(const float* __restrict__ Wfc0,
                                                     const float* __restrict__ WQ,
                                                     const float* __restrict__ WK,
                                                     const float* __restrict__ WV)
{
    const float* W;
    switch (blockIdx.x) {
        case 0:  W = Wfc0; break;
        case 1:  W = WQ;   break;
        case 2:  W = WK;   break;
        default: W = WV;   break;
    }
    __nv_bfloat16* H = g_Wth + blockIdx.x * DM * DM;
    __nv_bfloat16* L = g_Wtl + blockIdx.x * DM * DM;
    for (int idx = threadIdx.x; idx < DM * DM; idx += 256) {
        int k = idx >> 7, n = idx & 127;
        float x = W[idx];
        uint32_t hb = bf16_rn_bits(x);
        float lf = x - __uint_as_float(hb << 16);
        ((uint16_t*)H)[n * DM + k] = (uint16_t)hb;
        ((uint16_t*)L)[n * DM + k] = (uint16_t)bf16_rn_bits(lf);
    }
}

// ---------------------------------------------------------------------------
// P2: tensor-core projections (unchanged).
// ---------------------------------------------------------------------------
__global__ __launch_bounds__(256, 4) void proj_tc()
{
    extern __shared__ __nv_bfloat16 psm[];
    __nv_bfloat16* sAh  = psm + PA_H;
    __nv_bfloat16* sAl  = psm + PA_L;
    __nv_bfloat16* sWth = psm + PW_H;
    __nv_bfloat16* sWtl = psm + PW_L;

    const int tid  = threadIdx.x;
    const int w    = tid >> 5;
    const int lane = tid & 31;
    const int g    = lane >> 2;
    const int tig  = lane & 3;
    const int gm   = blockIdx.y;
    const int r0   = blockIdx.x * 64;

    const int xsel = (gm <= 1) ? 0 : (gm - 1);
    const __nv_bfloat16* gXh = g_Xh + (size_t)xsel * NR * DM;
    const __nv_bfloat16* gXl = g_Xl + (size_t)xsel * NR * DM;
    const __nv_bfloat16* gWh = g_Wth + gm * DM * DM;
    const __nv_bfloat16* gWl = g_Wtl + gm * DM * DM;

    const int mt = w >> 1;
    const int nh = (w & 1) * 64;
    const int m0 = mt * 16 + g;
    const int m1 = m0 + 8;

    float acc[8][4];
#pragma unroll
    for (int nt = 0; nt < 8; nt++)
#pragma unroll
        for (int i = 0; i < 4; i++) acc[nt][i] = 0.f;

    for (int ks = 0; ks < 2; ks++) {
        if (ks) __syncthreads();
        {
#pragma unroll
            for (int it = 0; it < 2; it++) {
                int id = tid + it * 256;
                int row = id >> 3, seg = (id & 7) * 8;
                size_t src = (size_t)(r0 + row) * DM + ks * 64 + seg;
                cp16(sAh + row * PSTR + seg, gXh + src);
                cp16(sAl + row * PSTR + seg, gXl + src);
            }
#pragma unroll
            for (int it = 0; it < 4; it++) {
                int id = tid + it * 256;
                int n = id >> 3, seg = (id & 7) * 8;
                size_t src = (size_t)n * DM + ks * 64 + seg;
                cp16(sWth + n * PSTR + seg, gWh + src);
                cp16(sWtl + n * PSTR + seg, gWl + src);
            }
        }
        cp_commit();
        cp_wait<0>();
        __syncthreads();

#pragma unroll
        for (int kk = 0; kk < 64; kk += 16) {
            const int dof = kk + tig * 2;
            uint32_t ah0 = *(const uint32_t*)&sAh[m0 * PSTR + dof];
            uint32_t ah1 = *(const uint32_t*)&sAh[m1 * PSTR + dof];
            uint32_t ah2 = *(const uint32_t*)&sAh[m0 * PSTR + dof + 8];
            uint32_t ah3 = *(const uint32_t*)&sAh[m1 * PSTR + dof + 8];
            uint32_t al0 = *(const uint32_t*)&sAl[m0 * PSTR + dof];
            uint32_t al1 = *(const uint32_t*)&sAl[m1 * PSTR + dof];
            uint32_t al2 = *(const uint32_t*)&sAl[m0 * PSTR + dof + 8];
            uint32_t al3 = *(const uint32_t*)&sAl[m1 * PSTR + dof + 8];
#pragma unroll
            for (int nt = 0; nt < 8; nt++) {
                int ncol = nh + nt * 8 + g;
                uint32_t bh0 = *(const uint32_t*)&sWth[ncol * PSTR + dof];
                uint32_t bh1 = *(const uint32_t*)&sWth[ncol * PSTR + dof + 8];
                uint32_t bl0 = *(const uint32_t*)&sWtl[ncol * PSTR + dof];
                uint32_t bl1 = *(const uint32_t*)&sWtl[ncol * PSTR + dof + 8];
                mma16816(acc[nt], ah0, ah1, ah2, ah3, bh0, bh1);
                mma16816(acc[nt], ah0, ah1, ah2, ah3, bl0, bl1);
                mma16816(acc[nt], al0, al1, al2, al3, bh0, bh1);
            }
        }
    }

    const size_t row0 = (size_t)(r0 + m0);
    const size_t row1 = row0 + 8;

    if (gm == 0) {
#pragma unroll
        for (int nt = 0; nt < 8; nt++) {
            int col = nh + nt * 8 + tig * 2;
            *(float2*)&g_R[row0 * DM + col] = make_float2(acc[nt][0], acc[nt][1]);
            *(float2*)&g_R[row1 * DM + col] = make_float2(acc[nt][2], acc[nt][3]);
        }
    } else if (gm == 1 || gm == 2) {
        __nv_bfloat16* H = (gm == 1) ? g_Qh : g_Kh;
        __nv_bfloat16* L = (gm == 1) ? g_Ql : g_Kl;
#pragma unroll
        for (int nt = 0; nt < 8; nt++) {
            int col = nh + nt * 8 + tig * 2;
#pragma unroll
            for (int rr = 0; rr < 2; rr++) {
                float f0 = acc[nt][rr * 2], f1 = acc[nt][rr * 2 + 1];
                uint32_t h0 = bf16_rn_bits(f0), h1 = bf16_rn_bits(f1);
                float l0 = f0 - __uint_as_float(h0 << 16);
                float l1 = f1 - __uint_as_float(h1 << 16);
                size_t off = (rr ? row1 : row0) * DM + col;
                *(uint32_t*)&H[off] = h0 | (h1 << 16);
                *(uint32_t*)&L[off] = bf16_rn_bits(l0) | (bf16_rn_bits(l1) << 16);
            }
        }
    } else {
        uint16_t* sV = (uint16_t*)(psm + PW_H);
        __syncthreads();
#pragma unroll
        for (int nt = 0; nt < 8; nt++) {
            int col = nh + nt * 8 + tig * 2;
            *(uint32_t*)&sV[m0 * VSTR + col] =
                bf16_rn_bits(acc[nt][0]) | (bf16_rn_bits(acc[nt][1]) << 16);
            *(uint32_t*)&sV[m1 * VSTR + col] =
                bf16_rn_bits(acc[nt][2]) | (bf16_rn_bits(acc[nt][3]) << 16);
        }
        __syncthreads();
        const int v   = tid >> 3;
        const int seg = (tid & 7) * 8;
        const int b   = r0 / SEQ;
        const int sblock = r0 % SEQ;
#pragma unroll
        for (int hd = 0; hd < 4; hd++) {
            uint32_t wv[4];
#pragma unroll
            for (int p = 0; p < 4; p++) {
                uint32_t lo = sV[(seg + p * 2) * VSTR + hd * 32 + v];
                uint32_t hi = sV[(seg + p * 2 + 1) * VSTR + hd * 32 + v];
                wv[p] = lo | (hi << 16);
            }
            size_t off = ((size_t)(b * 4 + hd) * 32 + v) * SEQ + sblock + seg;
            *(uint4*)&g_Vt[off] = make_uint4(wv[0], wv[1], wv[2], wv[3]);
        }
    }
}

// ---------------------------------------------------------------------------
// K1.5: rowsum pre-pass. 1-product bf16 scores (Q_hi x K_hi), exp, rowsum.
// Rowsum rel err ~1e-4 (averages over ~680 effective terms). Writes g_rinv.
// ---------------------------------------------------------------------------
__global__ __launch_bounds__(256, 4) void rowsum_pass(const unsigned char* __restrict__ mask)
{
    extern __shared__ __nv_bfloat16 smb[];
    __shared__ float srow[128];

    const int tid  = threadIdx.x;
    const int w    = tid >> 5;
    const int lane = tid & 31;
    const int g    = lane >> 2;
    const int tig  = lane & 3;
    const int qb   = w * 16;

    const int bh = blockIdx.y;
    const int b = bh >> 2, h = bh & 3;
    const int q0 = blockIdx.x * TQ;
    const float CE = 1.4426950408889634f * 0.17677669529663689f;
    const int mmode = g_mask_mode;
    const size_t bS = (size_t)b * SEQ;

    const int kj   = tid >> 2;
    const int kseg = (tid & 3) * 8;
    const __nv_bfloat16* gK_h = g_Kh + bS * DM + h * 32;

    auto issue_chunk = [&](int kc) {
        cp16(smb + (kc % 3) * KBUF + kj * QSTR + kseg,
             gK_h + (size_t)(kc * TK + kj) * DM + kseg);
    };
    issue_chunk(0);
    cp_commit();
    issue_chunk(1);
    cp_commit();

    // Q hi fragments only
    uint32_t qh[2][4];
    {
        const __nv_bfloat16* gQ_h = g_Qh + (bS + q0) * DM + h * 32;
#pragma unroll
        for (int kk = 0; kk < 2; kk++) {
            int c0 = kk * 16 + tig * 2;
            size_t r0o = (size_t)(qb + g) * DM + c0;
            size_t r1o = (size_t)(qb + g + 8) * DM + c0;
            qh[kk][0] = *(const uint32_t*)&gQ_h[r0o];
            qh[kk][1] = *(const uint32_t*)&gQ_h[r1o];
            qh[kk][2] = *(const uint32_t*)&gQ_h[r0o + 8];
            qh[kk][3] = *(const uint32_t*)&gQ_h[r1o + 8];
        }
    }

    float rs0 = 0.f, rs1 = 0.f;
    const int qg0 = q0 + qb + g;
    const size_t mrow0 = (bS + qg0) * SEQ;
    const size_t mrow1 = mrow0 + 8 * SEQ;

    for (int kc = 0; kc < NC; kc++) {
        const int k0 = kc * TK;

        cp_wait<1>();
        __syncthreads();
        if (kc + 2 < NC) issue_chunk(kc + 2);
        cp_commit();

        const __nv_bfloat16* kh = smb + (kc % 3) * KBUF;

#pragma unroll
        for (int jj = 0; jj < 4; jj++) {
            const int jm = jj * 16 + tig * 2;
            uint2 pmc[4];
            pmc[0] = load_mask2(mask, mrow0 + k0 + jm, mmode);
            pmc[1] = load_mask2(mask, mrow1 + k0 + jm, mmode);
            pmc[2] = load_mask2(mask, mrow0 + k0 + jm + 8, mmode);
            pmc[3] = load_mask2(mask, mrow1 + k0 + jm + 8, mmode);

#pragma unroll
            for (int s = 0; s < 2; s++) {
                const int j0 = jj * 16 + s * 8;
                float c[4]  = {0.f, 0.f, 0.f, 0.f};
                float c2[4] = {0.f, 0.f, 0.f, 0.f};
                {
                    const int dof0 = tig * 2;
                    uint32_t bh0 = *(const uint32_t*)&kh[(j0 + g) * QSTR + dof0];
                    uint32_t bh1 = *(const uint32_t*)&kh[(j0 + g) * QSTR + dof0 + 8];
                    mma16816(c, qh[0][0], qh[0][1], qh[0][2], qh[0][3], bh0, bh1);
                }
                {
                    const int dof1 = 16 + tig * 2;
                    uint32_t bh0 = *(const uint32_t*)&kh[(j0 + g) * QSTR + dof1];
                    uint32_t bh1 = *(const uint32_t*)&kh[(j0 + g) * QSTR + dof1 + 8];
                    mma16816(c2, qh[1][0], qh[1][1], qh[1][2], qh[1][3], bh0, bh1);
                }
#pragma unroll
                for (int i = 0; i < 4; i++) c[i] += c2[i];
                uint2 m0 = pmc[s * 2];
                uint2 m1 = pmc[s * 2 + 1];
                rs0 += (m0.x ? 0.f : ex2(c[0] * CE)) + (m0.y ? 0.f : ex2(c[1] * CE));
                rs1 += (m1.x ? 0.f : ex2(c[2] * CE)) + (m1.y ? 0.f : ex2(c[3] * CE));
            }
        }
    }

    rs0 += __shfl_xor_sync(0xffffffff, rs0, 1);
    rs0 += __shfl_xor_sync(0xffffffff, rs0, 2);
    rs1 += __shfl_xor_sync(0xffffffff, rs1, 1);
    rs1 += __shfl_xor_sync(0xffffffff, rs1, 2);
    __syncthreads();
    if (tig == 0) {
        srow[qb + g]     = rs0;
        srow[qb + g + 8] = rs1;
    }
    __syncthreads();
    if (tid < 128)
        g_rinv[(size_t)bh * SEQ + q0 + tid] = 1.0f / srow[tid];
}

// ---------------------------------------------------------------------------
// K2: tensor-core attention; rinv known up front -> attn written NORMALIZED.
// ---------------------------------------------------------------------------
__global__ __launch_bounds__(256, 4) void attn_mma(const unsigned char* __restrict__ mask,
                                                   float* __restrict__ attn)
{
    extern __shared__ __nv_bfloat16 smb[];

    const int tid  = threadIdx.x;
    const int w    = tid >> 5;
    const int lane = tid & 31;
    const int g    = lane >> 2;
    const int tig  = lane & 3;
    const int qb   = w * 16;

    const int bh = blockIdx.y;
    const int b = bh >> 2, h = bh & 3;
    const int q0 = blockIdx.x * TQ;
    const float CE = 1.4426950408889634f * 0.17677669529663689f;
    const int mmode = g_mask_mode;
    const size_t bS = (size_t)b * SEQ;

    const int kj   = tid >> 2;
    const int kseg = (tid & 3) * 8;
    const int vv   = tid >> 3;
    const int vseg = (tid & 7) * 8;
    const __nv_bfloat16* gK_h = g_Kh + bS * DM + h * 32;
    const __nv_bfloat16* gK_l = g_Kl + bS * DM + h * 32;
    const __nv_bfloat16* gV_t = g_Vt + ((size_t)bh * 32 + vv) * SEQ;

    auto issue_chunk = [&](int kc) {
        __nv_bfloat16* kh = smb + (kc % 3) * BUF_SZ;
        __nv_bfloat16* kl = kh + 64 * QSTR;
        __nv_bfloat16* vh = kl + 64 * QSTR;
        size_t koff = (size_t)(kc * TK + kj) * DM + kseg;
        cp16(kh + kj * QSTR + kseg, gK_h + koff);
        cp16(kl + kj * QSTR + kseg, gK_l + koff);
        cp16(vh + vv * ESTR + vseg, gV_t + kc * TK + vseg);
    };

    issue_chunk(0);
    cp_commit();
    issue_chunk(1);
    cp_commit();

    uint32_t qh[2][4], ql[2][4];
    {
        const __nv_bfloat16* gQ_h = g_Qh + (bS + q0) * DM + h * 32;
        const __nv_bfloat16* gQ_l = g_Ql + (bS + q0) * DM + h * 32;
#pragma unroll
        for (int kk = 0; kk < 2; kk++) {
            int c0 = kk * 16 + tig * 2;
            size_t r0o = (size_t)(qb + g) * DM + c0;
            size_t r1o = (size_t)(qb + g + 8) * DM + c0;
            qh[kk][0] = *(const uint32_t*)&gQ_h[r0o];
            qh[kk][1] = *(const uint32_t*)&gQ_h[r1o];
            qh[kk][2] = *(const uint32_t*)&gQ_h[r0o + 8];
            qh[kk][3] = *(const uint32_t*)&gQ_h[r1o + 8];
            ql[kk][0] = *(const uint32_t*)&gQ_l[r0o];
            ql[kk][1] = *(const uint32_t*)&gQ_l[r1o];
            ql[kk][2] = *(const uint32_t*)&gQ_l[r0o + 8];
            ql[kk][3] = *(const uint32_t*)&gQ_l[r1o + 8];
        }
    }

    const int qg0 = q0 + qb + g;
    // rinv from pre-pass (rowsum_pass completed before this kernel)
    const float rinv0 = g_rinv[(size_t)bh * SEQ + qg0];
    const float rinv1 = g_rinv[(size_t)bh * SEQ + qg0 + 8];

    float cacc[4][4];
#pragma unroll
    for (int n = 0; n < 4; n++)
#pragma unroll
        for (int i = 0; i < 4; i++) cacc[n][i] = 0.f;

    const size_t arow0 = ((size_t)bh * SEQ + qg0) * SEQ;
    const size_t arow1 = arow0 + 8 * SEQ;
    const size_t mrow0 = (bS + qg0) * SEQ;
    const size_t mrow1 = mrow0 + 8 * SEQ;

    for (int kc = 0; kc < NC; kc++) {
        const int k0 = kc * TK;

        cp_wait<1>();
        __syncthreads();
        if (kc + 2 < NC) issue_chunk(kc + 2);
        cp_commit();

        const __nv_bfloat16* kh = smb + (kc % 3) * BUF_SZ;
        const __nv_bfloat16* kl = kh + 64 * QSTR;
        const __nv_bfloat16* vh = kl + 64 * QSTR;

#pragma unroll
        for (int jj = 0; jj < 4; jj++) {
            const int jm = jj * 16 + tig * 2;
            uint2 pmc[4];
            pmc[0] = load_mask2(mask, mrow0 + k0 + jm, mmode);
            pmc[1] = load_mask2(mask, mrow1 + k0 + jm, mmode);
            pmc[2] = load_mask2(mask, mrow0 + k0 + jm + 8, mmode);
            pmc[3] = load_mask2(mask, mrow1 + k0 + jm + 8, mmode);

            uint32_t eh[2][2];
#pragma unroll
            for (int s = 0; s < 2; s++) {
                const int j0 = jj * 16 + s * 8;
                float c[4]  = {0.f, 0.f, 0.f, 0.f};
                float c2[4] = {0.f, 0.f, 0.f, 0.f};
                {
                    const int dof0 = tig * 2;
                    uint32_t bh0 = *(const uint32_t*)&kh[(j0 + g) * QSTR + dof0];
                    uint32_t bh1 = *(const uint32_t*)&kh[(j0 + g) * QSTR + dof0 + 8];
                    uint32_t bl0 = *(const uint32_t*)&kl[(j0 + g) * QSTR + dof0];
                    uint32_t bl1 = *(const uint32_t*)&kl[(j0 + g) * QSTR + dof0 + 8];
                    mma16816(c, qh[0][0], qh[0][1], qh[0][2], qh[0][3], bh0, bh1);
                    mma16816(c, qh[0][0], qh[0][1], qh[0][2], qh[0][3], bl0, bl1);
                    mma16816(c, ql[0][0], ql[0][1], ql[0][2], ql[0][3], bh0, bh1);
                }
                {
                    const int dof1 = 16 + tig * 2;
                    uint32_t bh0 = *(const uint32_t*)&kh[(j0 + g) * QSTR + dof1];
                    uint32_t bh1 = *(const uint32_t*)&kh[(j0 + g) * QSTR + dof1 + 8];
                    uint32_t bl0 = *(const uint32_t*)&kl[(j0 + g) * QSTR + dof1];
                    uint32_t bl1 = *(const uint32_t*)&kl[(j0 + g) * QSTR + dof1 + 8];
                    mma16816(c2, qh[1][0], qh[1][1], qh[1][2], qh[1][3], bh0, bh1);
                    mma16816(c2, qh[1][0], qh[1][1], qh[1][2], qh[1][3], bl0, bl1);
                    mma16816(c2, ql[1][0], ql[1][1], ql[1][2], ql[1][3], bh0, bh1);
                }
#pragma unroll
                for (int i = 0; i < 4; i++) c[i] += c2[i];

                const int jgl = k0 + j0 + tig * 2;
                uint2 m0 = pmc[s * 2];
                uint2 m1 = pmc[s * 2 + 1];
                // normalized on the fly: e = exp(s)*rinv
                float e00 = m0.x ? 0.f : ex2(c[0] * CE) * rinv0;
                float e01 = m0.y ? 0.f : ex2(c[1] * CE) * rinv0;
                float e10 = m1.x ? 0.f : ex2(c[2] * CE) * rinv1;
                float e11 = m1.y ? 0.f : ex2(c[3] * CE) * rinv1;
                *(float2*)(attn + arow0 + jgl) = make_float2(e00, e01);
                *(float2*)(attn + arow1 + jgl) = make_float2(e10, e11);
                eh[s][0] = pack_bf16x2(e00, e01);
                eh[s][1] = pack_bf16x2(e10, e11);
            }
            const int c0 = jj * 16 + tig * 2;
#pragma unroll
            for (int nt2 = 0; nt2 < 4; nt2++) {
                int v0 = nt2 * 8;
                uint32_t vb0 = *(const uint32_t*)&vh[(v0 + g) * ESTR + c0];
                uint32_t vb1 = *(const uint32_t*)&vh[(v0 + g) * ESTR + c0 + 8];
                mma16816(cacc[nt2], eh[0][0], eh[0][1], eh[1][0], eh[1][1], vb0, vb1);
            }
        }
    }

    // ---- context write (already normalized) ----
    {
        size_t row0 = (bS + q0 + qb + g) * (size_t)DM + h * 32;
        size_t row1 = row0 + 8 * DM;
#pragma unroll
        for (int nt = 0; nt < 4; nt++) {
            int v = nt * 8 + tig * 2;
            *(float2*)&g_ctx[row0 + v] = make_float2(cacc[nt][0], cacc[nt][1]);
            *(float2*)&g_ctx[row1 + v] = make_float2(cacc[nt][2], cacc[nt][3]);
        }
    }
}

// ---------------------------------------------------------------------------
// K4: out = LayerNorm(g_ctx @ W_fc + g_R) * gamma + beta
// ---------------------------------------------------------------------------
__global__ __launch_bounds__(256) void out_ln(const float* __restrict__ Wfc,
                                              const float* __restrict__ gamma,
                                              const float* __restrict__ beta,
                                              float* __restrict__ out)
{
    __shared__ float sA[64][36];
    __shared__ float sW[32][132];
    __shared__ float red1[64][17];
    __shared__ float red2[64][17];
    __shared__ float smu[64];
    __shared__ float srs[64];

    const int tid = threadIdx.x;
    const int tx = tid & 15, ty = tid >> 4;
    const int r0 = blockIdx.x * 64;

    float acc[4][8];
#pragma unroll
    for (int r = 0; r < 4; r++)
#pragma unroll
        for (int c = 0; c < 8; c++) acc[r][c] = 0.f;

    for (int kk = 0; kk < DM; kk += 32) {
        for (int t = tid; t < 64 * 32; t += 256) {
            int r = t >> 5, i = t & 31;
            sA[r][i] = g_ctx[(size_t)(r0 + r) * DM + kk + i];
        }
        for (int t = tid; t < 32 * 128; t += 256) {
            int i = t >> 7, c = t & 127;
            sW[i][c] = Wfc[(size_t)(kk + i) * DM + c];
        }
        __syncthreads();
#pragma unroll
        for (int i = 0; i < 32; i++) {
            float a[4];
#pragma unroll
            for (int r = 0; r < 4; r++) a[r] = sA[ty * 4 + r][i];
            float4 w0 = *(const float4*)&sW[i][tx * 8];
            float4 w1 = *(const float4*)&sW[i][tx * 8 + 4];
            float wv[8] = {w0.x, w0.y, w0.z, w0.w, w1.x, w1.y, w1.z, w1.w};
#pragma unroll
            for (int r = 0; r < 4; r++)
#pragma unroll
                for (int c = 0; c < 8; c++) acc[r][c] += a[r] * wv[c];
        }
        __syncthreads();
    }

#pragma unroll
    for (int r = 0; r < 4; r++) {
        size_t row = (size_t)(r0 + ty * 4 + r);
        float4 rv0 = *(const float4*)&g_R[row * DM + tx * 8];
        float4 rv1 = *(const float4*)&g_R[row * DM + tx * 8 + 4];
        float rsv[8] = {rv0.x, rv0.y, rv0.z, rv0.w, rv1.x, rv1.y, rv1.z, rv1.w};
        float ps = 0.f, pq = 0.f;
#pragma unroll
        for (int c = 0; c < 8; c++) {
            acc[r][c] += rsv[c];
            ps += acc[r][c];
            pq += acc[r][c] * acc[r][c];
        }
        red1[ty * 4 + r][tx] = ps;
        red2[ty * 4 + r][tx] = pq;
    }
    __syncthreads();
    if (tid < 64) {
        float s = 0.f, q = 0.f;
#pragma unroll
        for (int j = 0; j < 16; j++) { s += red1[tid][j]; q += red2[tid][j]; }
        float mu = s * (1.0f / 128.0f);
        float var = q * (1.0f / 128.0f) - mu * mu;
        smu[tid] = mu;
        srs[tid] = rsqrtf(var + 1e-5f);
    }
    __syncthreads();

    float4 g0 = *(const float4*)&gamma[tx * 8];
    float4 g1 = *(const float4*)&gamma[tx * 8 + 4];
    float4 b0 = *(const float4*)&beta[tx * 8];
    float4 b1 = *(const float4*)&beta[tx * 8 + 4];
    float gs[8] = {g0.x, g0.y, g0.z, g0.w, g1.x, g1.y, g1.z, g1.w};
    float bs[8] = {b0.x, b0.y, b0.z, b0.w, b1.x, b1.y, b1.z, b1.w};

#pragma unroll
    for (int r = 0; r < 4; r++) {
        float mu = smu[ty * 4 + r];
        float rstd = srs[ty * 4 + r];
        size_t row = (size_t)(r0 + ty * 4 + r);
        float o[8];
#pragma unroll
        for (int c = 0; c < 8; c++) o[c] = (acc[r][c] - mu) * rstd * gs[c] + bs[c];
        *(float4*)&out[row * DM + tx * 8]     = make_float4(o[0], o[1], o[2], o[3]);
        *(float4*)&out[row * DM + tx * 8 + 4] = make_float4(o[4], o[5], o[6], o[7]);
    }
}

// ---------------------------------------------------------------------------
extern "C" void kernel_launch(void* const* d_in, const int* in_sizes, int n_in,
                              void* d_out, int out_size)
{
    const float* inQ  = (const float*)d_in[0];
    const float* inK  = (const float*)d_in[1];
    const float* inV  = (const float*)d_in[2];
    const unsigned char* mask = (const unsigned char*)d_in[3];
    const float* Wfc0 = (const float*)d_in[4];
    const float* WQ   = (const float*)d_in[5];
    const float* WK   = (const float*)d_in[6];
    const float* WV   = (const float*)d_in[7];
    const float* Wfc  = (const float*)d_in[8];
    const float* gam  = (const float*)d_in[9];
    const float* bet  = (const float*)d_in[10];
    float* out  = (float*)d_out;
    float* attn = out + OUT_ELEMS;

    detect_mask<<<1, 256>>>(mask);                                  // 1
    split_inputs<<<dim3(NR * DM / 1024, 3), 256>>>(inQ, inK, inV);  // 2
    split_weights<<<4, 256>>>(Wfc0, WQ, WK, WV);                    // 3

    cudaFuncSetAttribute(proj_tc, cudaFuncAttributeMaxDynamicSharedMemorySize,
                         (int)P_SMEM_BYTES);
    proj_tc<<<dim3(NR / 64, 4), 256, P_SMEM_BYTES>>>();             // 4

    dim3 agrid(SEQ / TQ, BATCH * 4);
    cudaFuncSetAttribute(rowsum_pass, cudaFuncAttributeMaxDynamicSharedMemorySize,
                         (int)RS_SMEM_BYTES);
    rowsum_pass<<<agrid, 256, RS_SMEM_BYTES>>>(mask);               // 5

    cudaFuncSetAttribute(attn_mma, cudaFuncAttributeMaxDynamicSharedMemorySize,
                         (int)SMEM_BYTES);
    attn_mma<<<agrid, 256, SMEM_BYTES>>>(mask, attn);               // 6 (ncu)

    out_ln<<<NR / 64, 256>>>(Wfc, gam, bet, out);
}

// round 13
// speedup vs baseline: 1.4486x; 1.0266x over previous
#include <cuda_runtime.h>
#include <cuda_bf16.h>
#include <stdint.h>

// ---------------------------------------------------------------------------
// MultiHeadAttention: out = LN(ctx@W_fc + X@W_fc0), attn materialized.
// B=8, S=2048, D=128, H=4, dk=dv=32.
// Output layout: [out (8*2048*128)] then [attn (8*4*2048*2048)].
// R13: rowsum pass upgraded to 2-product (cancels correlated Q-rounding err,
// rel_err 6e-4 -> ~1e-4); out_ln moved to tensor cores (ctx stored bf16 hi/lo).
// ---------------------------------------------------------------------------

namespace {
constexpr int BATCH = 8;
constexpr int SEQ   = 2048;
constexpr int DM    = 128;
constexpr int NR    = BATCH * SEQ;                 // 16384 rows
constexpr size_t OUT_ELEMS = (size_t)NR * DM;      // 2,097,152
constexpr int TQ = 128;                            // q-tile per block (K2)
constexpr int TK = 64;                             // k-chunk (K2)
constexpr int NC = SEQ / TK;                       // 32 chunks

// K2 smem (bf16 units)
constexpr int QSTR = 40;
constexpr int ESTR = 72;
constexpr int BUF_SZ  = 64 * QSTR * 2 + 32 * ESTR;
constexpr int SMEM_BF16 = 3 * BUF_SZ;
constexpr size_t SMEM_BYTES = (size_t)SMEM_BF16 * 2;  // 44,544 B

// rowsum_pass smem: K-hi only, 3 buffers
constexpr int KBUF = 64 * QSTR;                    // 2560
constexpr size_t RS_SMEM_BYTES = (size_t)(3 * KBUF) * 2;  // 15,360 B

// proj_tc / out_ln_tc smem (bf16 units)
constexpr int PSTR = 72;
constexpr int PA_H = 0;
constexpr int PA_L = PA_H + 64 * PSTR;
constexpr int PW_H = PA_L + 64 * PSTR;
constexpr int PW_L = PW_H + 128 * PSTR;
constexpr int P_BF16 = PW_L + 128 * PSTR;
constexpr size_t P_SMEM_BYTES = (size_t)P_BF16 * 2;   // 55,296 B
constexpr int VSTR = 136;
}

// Scratch (device globals: allocation-free rule)
__device__ float g_R  [NR * DM];
__device__ float g_rinv[BATCH * 4 * SEQ];
__device__ __nv_bfloat16 g_Xh[3 * NR * DM];
__device__ __nv_bfloat16 g_Xl[3 * NR * DM];
__device__ __nv_bfloat16 g_Wth[5 * DM * DM];  // 4 proj weights + W_fc, [n][k]
__device__ __nv_bfloat16 g_Wtl[5 * DM * DM];
__device__ __nv_bfloat16 g_Qh[NR * DM];
__device__ __nv_bfloat16 g_Ql[NR * DM];
__device__ __nv_bfloat16 g_Kh[NR * DM];
__device__ __nv_bfloat16 g_Kl[NR * DM];
__device__ __nv_bfloat16 g_Ch[NR * DM];       // ctx hi
__device__ __nv_bfloat16 g_Cl[NR * DM];       // ctx lo
__device__ __nv_bfloat16 g_Vt[(size_t)BATCH * 4 * 32 * SEQ];  // [bh][v][s]
__device__ int   g_mask_mode;   // 0=uint8, 1=int32, 2=float32

// ---------------------------------------------------------------------------
__device__ __forceinline__ float ex2(float y)
{
    float r;
    asm("ex2.approx.f32 %0, %1;" : "=f"(r) : "f"(y));
    return r;
}

__device__ __forceinline__ uint32_t pack_bf16x2(float lo, float hi)
{
    uint32_t r;
    asm("cvt.rn.bf16x2.f32 %0, %1, %2;" : "=r"(r) : "f"(hi), "f"(lo));
    return r;
}

__device__ __forceinline__ uint32_t bf16_rn_bits(float x)
{
    uint32_t b = __float_as_uint(x);
    return (b + 0x7fffu + ((b >> 16) & 1u)) >> 16;
}

__device__ __forceinline__ void mma16816(float c[4],
                                         uint32_t a0, uint32_t a1, uint32_t a2, uint32_t a3,
                                         uint32_t b0, uint32_t b1)
{
    asm volatile("mma.sync.aligned.m16n8k16.row.col.f32.bf16.bf16.f32 "
                 "{%0,%1,%2,%3}, {%4,%5,%6,%7}, {%8,%9}, {%0,%1,%2,%3};"
                 : "+f"(c[0]), "+f"(c[1]), "+f"(c[2]), "+f"(c[3])
                 : "r"(a0), "r"(a1), "r"(a2), "r"(a3), "r"(b0), "r"(b1));
}

__device__ __forceinline__ void cp16(const __nv_bfloat16* smem_dst, const void* gsrc)
{
    uint32_t d = (uint32_t)__cvta_generic_to_shared(smem_dst);
    asm volatile("cp.async.cg.shared.global [%0], [%1], 16;" :: "r"(d), "l"(gsrc));
}
__device__ __forceinline__ void cp_commit()
{
    asm volatile("cp.async.commit_group;");
}
template <int N>
__device__ __forceinline__ void cp_wait()
{
    asm volatile("cp.async.wait_group %0;" :: "n"(N));
}

// ---------------------------------------------------------------------------
// K0: detect mask dtype.
// ---------------------------------------------------------------------------
__global__ void detect_mask(const unsigned char* __restrict__ m)
{
    __shared__ int s_gt1, s_off;
    if (threadIdx.x == 0) { s_gt1 = 0; s_off = 0; }
    __syncthreads();
    int gt1 = 0, off = 0;
    for (int i = threadIdx.x; i < 4096; i += 256) {
        unsigned char v = m[i];
        if (v > 1) gt1 = 1;
        else if (v == 1 && (i & 3) != 0) off = 1;
    }
    if (gt1) atomicOr(&s_gt1, 1);
    if (off) atomicOr(&s_off, 1);
    __syncthreads();
    if (threadIdx.x == 0)
        g_mask_mode = s_gt1 ? 2 : (s_off ? 0 : 1);
}

__device__ __forceinline__ uint2 load_mask2(const unsigned char* __restrict__ mask,
                                            size_t idx, int mode)
{
    if (mode == 0) {
        uchar2 m = *(const uchar2*)(mask + idx);
        return make_uint2(m.x, m.y);
    } else if (mode == 1) {
        int2 m = *(const int2*)((const int*)mask + idx);
        return make_uint2((unsigned)m.x, (unsigned)m.y);
    } else {
        float2 m = *(const float2*)((const float*)mask + idx);
        return make_uint2(m.x != 0.f, m.y != 0.f);
    }
}

// ---------------------------------------------------------------------------
// P0: split inputs fp32 -> bf16 hi/lo.
// ---------------------------------------------------------------------------
__global__ __launch_bounds__(256) void split_inputs(const float* __restrict__ inQ,
                                                    const float* __restrict__ inK,
                                                    const float* __restrict__ inV)
{
    const float* src = (blockIdx.y == 0) ? inQ : (blockIdx.y == 1) ? inK : inV;
    __nv_bfloat16* H = g_Xh + (size_t)blockIdx.y * NR * DM;
    __nv_bfloat16* L = g_Xl + (size_t)blockIdx.y * NR * DM;
    size_t i = ((size_t)blockIdx.x * 256 + threadIdx.x) * 4;
    float4 v = *(const float4*)&src[i];
    uint32_t hx = bf16_rn_bits(v.x), hy = bf16_rn_bits(v.y);
    uint32_t hz = bf16_rn_bits(v.z), hw = bf16_rn_bits(v.w);
    float lx = v.x - __uint_as_float(hx << 16);
    float ly = v.y - __uint_as_float(hy << 16);
    float lz = v.z - __uint_as_float(hz << 16);
    float lw = v.w - __uint_as_float(hw << 16);
    *(uint2*)&H[i] = make_uint2(hx | (hy << 16), hz | (hw << 16));
    *(uint2*)&L[i] = make_uint2(bf16_rn_bits(lx) | (bf16_rn_bits(ly) << 16),
                                bf16_rn_bits(lz) | (bf16_rn_bits(lw) << 16));
}

// ---------------------------------------------------------------------------
// P1: split + transpose weights (5 gemms: Wfc0, WQ, WK, WV, Wfc).
// ---------------------------------------------------------------------------
__global__ __launch_bounds__(256) void split_weights(const float* __restrict__ Wfc0,
                                                     const float* __restrict__ WQ,
                                                     const float* __restrict__ WK,
                                                     const float* __restrict__ WV,
                                                     const float* __restrict__ Wfc)
{
    const float* W;
    switch (blockIdx.x) {
        case 0:  W = Wfc0; break;
        case 1:  W = WQ;   break;
        case 2:  W = WK;   break;
        case 3:  W = WV;   break;
        default: W = Wfc;  break;
    }
    __nv_bfloat16* H = g_Wth + blockIdx.x * DM * DM;
    __nv_bfloat16* L = g_Wtl + blockIdx.x * DM * DM;
    for (int idx = threadIdx.x; idx < DM * DM; idx += 256) {
        int k = idx >> 7, n = idx & 127;
        float x = W[idx];
        uint32_t hb = bf16_rn_bits(x);
        float lf = x - __uint_as_float(hb << 16);
        ((uint16_t*)H)[n * DM + k] = (uint16_t)hb;
        ((uint16_t*)L)[n * DM + k] = (uint16_t)bf16_rn_bits(lf);
    }
}

// ---------------------------------------------------------------------------
// P2: tensor-core projections (unchanged from R12).
// ---------------------------------------------------------------------------
__global__ __launch_bounds__(256, 4) void proj_tc()
{
    extern __shared__ __nv_bfloat16 psm[];
    __nv_bfloat16* sAh  = psm + PA_H;
    __nv_bfloat16* sAl  = psm + PA_L;
    __nv_bfloat16* sWth = psm + PW_H;
    __nv_bfloat16* sWtl = psm + PW_L;

    const int tid  = threadIdx.x;
    const int w    = tid >> 5;
    const int lane = tid & 31;
    const int g    = lane >> 2;
    const int tig  = lane & 3;
    const int gm   = blockIdx.y;
    const int r0   = blockIdx.x * 64;

    const int xsel = (gm <= 1) ? 0 : (gm - 1);
    const __nv_bfloat16* gXh = g_Xh + (size_t)xsel * NR * DM;
    const __nv_bfloat16* gXl = g_Xl + (size_t)xsel * NR * DM;
    const __nv_bfloat16* gWh = g_Wth + gm * DM * DM;
    const __nv_bfloat16* gWl = g_Wtl + gm * DM * DM;

    const int mt = w >> 1;
    const int nh = (w & 1) * 64;
    const int m0 = mt * 16 + g;
    const int m1 = m0 + 8;

    float acc[8][4];
#pragma unroll
    for (int nt = 0; nt < 8; nt++)
#pragma unroll
        for (int i = 0; i < 4; i++) acc[nt][i] = 0.f;

    for (int ks = 0; ks < 2; ks++) {
        if (ks) __syncthreads();
        {
#pragma unroll
            for (int it = 0; it < 2; it++) {
                int id = tid + it * 256;
                int row = id >> 3, seg = (id & 7) * 8;
                size_t src = (size_t)(r0 + row) * DM + ks * 64 + seg;
                cp16(sAh + row * PSTR + seg, gXh + src);
                cp16(sAl + row * PSTR + seg, gXl + src);
            }
#pragma unroll
            for (int it = 0; it < 4; it++) {
                int id = tid + it * 256;
                int n = id >> 3, seg = (id & 7) * 8;
                size_t src = (size_t)n * DM + ks * 64 + seg;
                cp16(sWth + n * PSTR + seg, gWh + src);
                cp16(sWtl + n * PSTR + seg, gWl + src);
            }
        }
        cp_commit();
        cp_wait<0>();
        __syncthreads();

#pragma unroll
        for (int kk = 0; kk < 64; kk += 16) {
            const int dof = kk + tig * 2;
            uint32_t ah0 = *(const uint32_t*)&sAh[m0 * PSTR + dof];
            uint32_t ah1 = *(const uint32_t*)&sAh[m1 * PSTR + dof];
            uint32_t ah2 = *(const uint32_t*)&sAh[m0 * PSTR + dof + 8];
            uint32_t ah3 = *(const uint32_t*)&sAh[m1 * PSTR + dof + 8];
            uint32_t al0 = *(const uint32_t*)&sAl[m0 * PSTR + dof];
            uint32_t al1 = *(const uint32_t*)&sAl[m1 * PSTR + dof];
            uint32_t al2 = *(const uint32_t*)&sAl[m0 * PSTR + dof + 8];
            uint32_t al3 = *(const uint32_t*)&sAl[m1 * PSTR + dof + 8];
#pragma unroll
            for (int nt = 0; nt < 8; nt++) {
                int ncol = nh + nt * 8 + g;
                uint32_t bh0 = *(const uint32_t*)&sWth[ncol * PSTR + dof];
                uint32_t bh1 = *(const uint32_t*)&sWth[ncol * PSTR + dof + 8];
                uint32_t bl0 = *(const uint32_t*)&sWtl[ncol * PSTR + dof];
                uint32_t bl1 = *(const uint32_t*)&sWtl[ncol * PSTR + dof + 8];
                mma16816(acc[nt], ah0, ah1, ah2, ah3, bh0, bh1);
                mma16816(acc[nt], ah0, ah1, ah2, ah3, bl0, bl1);
                mma16816(acc[nt], al0, al1, al2, al3, bh0, bh1);
            }
        }
    }

    const size_t row0 = (size_t)(r0 + m0);
    const size_t row1 = row0 + 8;

    if (gm == 0) {
#pragma unroll
        for (int nt = 0; nt < 8; nt++) {
            int col = nh + nt * 8 + tig * 2;
            *(float2*)&g_R[row0 * DM + col] = make_float2(acc[nt][0], acc[nt][1]);
            *(float2*)&g_R[row1 * DM + col] = make_float2(acc[nt][2], acc[nt][3]);
        }
    } else if (gm == 1 || gm == 2) {
        __nv_bfloat16* H = (gm == 1) ? g_Qh : g_Kh;
        __nv_bfloat16* L = (gm == 1) ? g_Ql : g_Kl;
#pragma unroll
        for (int nt = 0; nt < 8; nt++) {
            int col = nh + nt * 8 + tig * 2;
#pragma unroll
            for (int rr = 0; rr < 2; rr++) {
                float f0 = acc[nt][rr * 2], f1 = acc[nt][rr * 2 + 1];
                uint32_t h0 = bf16_rn_bits(f0), h1 = bf16_rn_bits(f1);
                float l0 = f0 - __uint_as_float(h0 << 16);
                float l1 = f1 - __uint_as_float(h1 << 16);
                size_t off = (rr ? row1 : row0) * DM + col;
                *(uint32_t*)&H[off] = h0 | (h1 << 16);
                *(uint32_t*)&L[off] = bf16_rn_bits(l0) | (bf16_rn_bits(l1) << 16);
            }
        }
    } else {
        uint16_t* sV = (uint16_t*)(psm + PW_H);
        __syncthreads();
#pragma unroll
        for (int nt = 0; nt < 8; nt++) {
            int col = nh + nt * 8 + tig * 2;
            *(uint32_t*)&sV[m0 * VSTR + col] =
                bf16_rn_bits(acc[nt][0]) | (bf16_rn_bits(acc[nt][1]) << 16);
            *(uint32_t*)&sV[m1 * VSTR + col] =
                bf16_rn_bits(acc[nt][2]) | (bf16_rn_bits(acc[nt][3]) << 16);
        }
        __syncthreads();
        const int v   = tid >> 3;
        const int seg = (tid & 7) * 8;
        const int b   = r0 / SEQ;
        const int sblock = r0 % SEQ;
#pragma unroll
        for (int hd = 0; hd < 4; hd++) {
            uint32_t wv[4];
#pragma unroll
            for (int p = 0; p < 4; p++) {
                uint32_t lo = sV[(seg + p * 2) * VSTR + hd * 32 + v];
                uint32_t hi = sV[(seg + p * 2 + 1) * VSTR + hd * 32 + v];
                wv[p] = lo | (hi << 16);
            }
            size_t off = ((size_t)(b * 4 + hd) * 32 + v) * SEQ + sblock + seg;
            *(uint4*)&g_Vt[off] = make_uint4(wv[0], wv[1], wv[2], wv[3]);
        }
    }
}

// ---------------------------------------------------------------------------
// K1.5: rowsum pre-pass, 2-PRODUCT scores (Qh*Kh + Ql*Kh): cancels the
// correlated Q-rounding error; remaining K-lo error averages out (~1e-5).
// ---------------------------------------------------------------------------
__global__ __launch_bounds__(256, 4) void rowsum_pass(const unsigned char* __restrict__ mask)
{
    extern __shared__ __nv_bfloat16 smb[];
    __shared__ float srow[128];

    const int tid  = threadIdx.x;
    const int w    = tid >> 5;
    const int lane = tid & 31;
    const int g    = lane >> 2;
    const int tig  = lane & 3;
    const int qb   = w * 16;

    const int bh = blockIdx.y;
    const int b = bh >> 2, h = bh & 3;
    const int q0 = blockIdx.x * TQ;
    const float CE = 1.4426950408889634f * 0.17677669529663689f;
    const int mmode = g_mask_mode;
    const size_t bS = (size_t)b * SEQ;

    const int kj   = tid >> 2;
    const int kseg = (tid & 3) * 8;
    const __nv_bfloat16* gK_h = g_Kh + bS * DM + h * 32;

    auto issue_chunk = [&](int kc) {
        cp16(smb + (kc % 3) * KBUF + kj * QSTR + kseg,
             gK_h + (size_t)(kc * TK + kj) * DM + kseg);
    };
    issue_chunk(0);
    cp_commit();
    issue_chunk(1);
    cp_commit();

    uint32_t qh[2][4], ql[2][4];
    {
        const __nv_bfloat16* gQ_h = g_Qh + (bS + q0) * DM + h * 32;
        const __nv_bfloat16* gQ_l = g_Ql + (bS + q0) * DM + h * 32;
#pragma unroll
        for (int kk = 0; kk < 2; kk++) {
            int c0 = kk * 16 + tig * 2;
            size_t r0o = (size_t)(qb + g) * DM + c0;
            size_t r1o = (size_t)(qb + g + 8) * DM + c0;
            qh[kk][0] = *(const uint32_t*)&gQ_h[r0o];
            qh[kk][1] = *(const uint32_t*)&gQ_h[r1o];
            qh[kk][2] = *(const uint32_t*)&gQ_h[r0o + 8];
            qh[kk][3] = *(const uint32_t*)&gQ_h[r1o + 8];
            ql[kk][0] = *(const uint32_t*)&gQ_l[r0o];
            ql[kk][1] = *(const uint32_t*)&gQ_l[r1o];
            ql[kk][2] = *(const uint32_t*)&gQ_l[r0o + 8];
            ql[kk][3] = *(const uint32_t*)&gQ_l[r1o + 8];
        }
    }

    float rs0 = 0.f, rs1 = 0.f;
    const int qg0 = q0 + qb + g;
    const size_t mrow0 = (bS + qg0) * SEQ;
    const size_t mrow1 = mrow0 + 8 * SEQ;

    for (int kc = 0; kc < NC; kc++) {
        const int k0 = kc * TK;

        cp_wait<1>();
        __syncthreads();
        if (kc + 2 < NC) issue_chunk(kc + 2);
        cp_commit();

        const __nv_bfloat16* kh = smb + (kc % 3) * KBUF;

#pragma unroll
        for (int jj = 0; jj < 4; jj++) {
            const int jm = jj * 16 + tig * 2;
            uint2 pmc[4];
            pmc[0] = load_mask2(mask, mrow0 + k0 + jm, mmode);
            pmc[1] = load_mask2(mask, mrow1 + k0 + jm, mmode);
            pmc[2] = load_mask2(mask, mrow0 + k0 + jm + 8, mmode);
            pmc[3] = load_mask2(mask, mrow1 + k0 + jm + 8, mmode);

#pragma unroll
            for (int s = 0; s < 2; s++) {
                const int j0 = jj * 16 + s * 8;
                float c[4]  = {0.f, 0.f, 0.f, 0.f};
                float c2[4] = {0.f, 0.f, 0.f, 0.f};
                {
                    const int dof0 = tig * 2;
                    uint32_t bh0 = *(const uint32_t*)&kh[(j0 + g) * QSTR + dof0];
                    uint32_t bh1 = *(const uint32_t*)&kh[(j0 + g) * QSTR + dof0 + 8];
                    mma16816(c, qh[0][0], qh[0][1], qh[0][2], qh[0][3], bh0, bh1);
                    mma16816(c, ql[0][0], ql[0][1], ql[0][2], ql[0][3], bh0, bh1);
                }
                {
                    const int dof1 = 16 + tig * 2;
                    uint32_t bh0 = *(const uint32_t*)&kh[(j0 + g) * QSTR + dof1];
                    uint32_t bh1 = *(const uint32_t*)&kh[(j0 + g) * QSTR + dof1 + 8];
                    mma16816(c2, qh[1][0], qh[1][1], qh[1][2], qh[1][3], bh0, bh1);
                    mma16816(c2, ql[1][0], ql[1][1], ql[1][2], ql[1][3], bh0, bh1);
                }
#pragma unroll
                for (int i = 0; i < 4; i++) c[i] += c2[i];
                uint2 m0 = pmc[s * 2];
                uint2 m1 = pmc[s * 2 + 1];
                rs0 += (m0.x ? 0.f : ex2(c[0] * CE)) + (m0.y ? 0.f : ex2(c[1] * CE));
                rs1 += (m1.x ? 0.f : ex2(c[2] * CE)) + (m1.y ? 0.f : ex2(c[3] * CE));
            }
        }
    }

    rs0 += __shfl_xor_sync(0xffffffff, rs0, 1);
    rs0 += __shfl_xor_sync(0xffffffff, rs0, 2);
    rs1 += __shfl_xor_sync(0xffffffff, rs1, 1);
    rs1 += __shfl_xor_sync(0xffffffff, rs1, 2);
    __syncthreads();
    if (tig == 0) {
        srow[qb + g]     = rs0;
        srow[qb + g + 8] = rs1;
    }
    __syncthreads();
    if (tid < 128)
        g_rinv[(size_t)bh * SEQ + q0 + tid] = 1.0f / srow[tid];
}

// ---------------------------------------------------------------------------
// K2: tensor-core attention; attn written NORMALIZED; ctx stored bf16 hi/lo.
// ---------------------------------------------------------------------------
__global__ __launch_bounds__(256, 4) void attn_mma(const unsigned char* __restrict__ mask,
                                                   float* __restrict__ attn)
{
    extern __shared__ __nv_bfloat16 smb[];

    const int tid  = threadIdx.x;
    const int w    = tid >> 5;
    const int lane = tid & 31;
    const int g    = lane >> 2;
    const int tig  = lane & 3;
    const int qb   = w * 16;

    const int bh = blockIdx.y;
    const int b = bh >> 2, h = bh & 3;
    const int q0 = blockIdx.x * TQ;
    const float CE = 1.4426950408889634f * 0.17677669529663689f;
    const int mmode = g_mask_mode;
    const size_t bS = (size_t)b * SEQ;

    const int kj   = tid >> 2;
    const int kseg = (tid & 3) * 8;
    const int vv   = tid >> 3;
    const int vseg = (tid & 7) * 8;
    const __nv_bfloat16* gK_h = g_Kh + bS * DM + h * 32;
    const __nv_bfloat16* gK_l = g_Kl + bS * DM + h * 32;
    const __nv_bfloat16* gV_t = g_Vt + ((size_t)bh * 32 + vv) * SEQ;

    auto issue_chunk = [&](int kc) {
        __nv_bfloat16* kh = smb + (kc % 3) * BUF_SZ;
        __nv_bfloat16* kl = kh + 64 * QSTR;
        __nv_bfloat16* vh = kl + 64 * QSTR;
        size_t koff = (size_t)(kc * TK + kj) * DM + kseg;
        cp16(kh + kj * QSTR + kseg, gK_h + koff);
        cp16(kl + kj * QSTR + kseg, gK_l + koff);
        cp16(vh + vv * ESTR + vseg, gV_t + kc * TK + vseg);
    };

    issue_chunk(0);
    cp_commit();
    issue_chunk(1);
    cp_commit();

    uint32_t qh[2][4], ql[2][4];
    {
        const __nv_bfloat16* gQ_h = g_Qh + (bS + q0) * DM + h * 32;
        const __nv_bfloat16* gQ_l = g_Ql + (bS + q0) * DM + h * 32;
#pragma unroll
        for (int kk = 0; kk < 2; kk++) {
            int c0 = kk * 16 + tig * 2;
            size_t r0o = (size_t)(qb + g) * DM + c0;
            size_t r1o = (size_t)(qb + g + 8) * DM + c0;
            qh[kk][0] = *(const uint32_t*)&gQ_h[r0o];
            qh[kk][1] = *(const uint32_t*)&gQ_h[r1o];
            qh[kk][2] = *(const uint32_t*)&gQ_h[r0o + 8];
            qh[kk][3] = *(const uint32_t*)&gQ_h[r1o + 8];
            ql[kk][0] = *(const uint32_t*)&gQ_l[r0o];
            ql[kk][1] = *(const uint32_t*)&gQ_l[r1o];
            ql[kk][2] = *(const uint32_t*)&gQ_l[r0o + 8];
            ql[kk][3] = *(const uint32_t*)&gQ_l[r1o + 8];
        }
    }

    const int qg0 = q0 + qb + g;
    const float rinv0 = g_rinv[(size_t)bh * SEQ + qg0];
    const float rinv1 = g_rinv[(size_t)bh * SEQ + qg0 + 8];

    float cacc[4][4];
#pragma unroll
    for (int n = 0; n < 4; n++)
#pragma unroll
        for (int i = 0; i < 4; i++) cacc[n][i] = 0.f;

    const size_t arow0 = ((size_t)bh * SEQ + qg0) * SEQ;
    const size_t arow1 = arow0 + 8 * SEQ;
    const size_t mrow0 = (bS + qg0) * SEQ;
    const size_t mrow1 = mrow0 + 8 * SEQ;

    for (int kc = 0; kc < NC; kc++) {
        const int k0 = kc * TK;

        cp_wait<1>();
        __syncthreads();
        if (kc + 2 < NC) issue_chunk(kc + 2);
        cp_commit();

        const __nv_bfloat16* kh = smb + (kc % 3) * BUF_SZ;
        const __nv_bfloat16* kl = kh + 64 * QSTR;
        const __nv_bfloat16* vh = kl + 64 * QSTR;

#pragma unroll
        for (int jj = 0; jj < 4; jj++) {
            const int jm = jj * 16 + tig * 2;
            uint2 pmc[4];
            pmc[0] = load_mask2(mask, mrow0 + k0 + jm, mmode);
            pmc[1] = load_mask2(mask, mrow1 + k0 + jm, mmode);
            pmc[2] = load_mask2(mask, mrow0 + k0 + jm + 8, mmode);
            pmc[3] = load_mask2(mask, mrow1 + k0 + jm + 8, mmode);

            uint32_t eh[2][2];
#pragma unroll
            for (int s = 0; s < 2; s++) {
                const int j0 = jj * 16 + s * 8;
                float c[4]  = {0.f, 0.f, 0.f, 0.f};
                float c2[4] = {0.f, 0.f, 0.f, 0.f};
                {
                    const int dof0 = tig * 2;
                    uint32_t bh0 = *(const uint32_t*)&kh[(j0 + g) * QSTR + dof0];
                    uint32_t bh1 = *(const uint32_t*)&kh[(j0 + g) * QSTR + dof0 + 8];
                    uint32_t bl0 = *(const uint32_t*)&kl[(j0 + g) * QSTR + dof0];
                    uint32_t bl1 = *(const uint32_t*)&kl[(j0 + g) * QSTR + dof0 + 8];
                    mma16816(c, qh[0][0], qh[0][1], qh[0][2], qh[0][3], bh0, bh1);
                    mma16816(c, qh[0][0], qh[0][1], qh[0][2], qh[0][3], bl0, bl1);
                    mma16816(c, ql[0][0], ql[0][1], ql[0][2], ql[0][3], bh0, bh1);
                }
                {
                    const int dof1 = 16 + tig * 2;
                    uint32_t bh0 = *(const uint32_t*)&kh[(j0 + g) * QSTR + dof1];
                    uint32_t bh1 = *(const uint32_t*)&kh[(j0 + g) * QSTR + dof1 + 8];
                    uint32_t bl0 = *(const uint32_t*)&kl[(j0 + g) * QSTR + dof1];
                    uint32_t bl1 = *(const uint32_t*)&kl[(j0 + g) * QSTR + dof1 + 8];
                    mma16816(c2, qh[1][0], qh[1][1], qh[1][2], qh[1][3], bh0, bh1);
                    mma16816(c2, qh[1][0], qh[1][1], qh[1][2], qh[1][3], bl0, bl1);
                    mma16816(c2, ql[1][0], ql[1][1], ql[1][2], ql[1][3], bh0, bh1);
                }
#pragma unroll
                for (int i = 0; i < 4; i++) c[i] += c2[i];

                const int jgl = k0 + j0 + tig * 2;
                uint2 m0 = pmc[s * 2];
                uint2 m1 = pmc[s * 2 + 1];
                float e00 = m0.x ? 0.f : ex2(c[0] * CE) * rinv0;
                float e01 = m0.y ? 0.f : ex2(c[1] * CE) * rinv0;
                float e10 = m1.x ? 0.f : ex2(c[2] * CE) * rinv1;
                float e11 = m1.y ? 0.f : ex2(c[3] * CE) * rinv1;
                *(float2*)(attn + arow0 + jgl) = make_float2(e00, e01);
                *(float2*)(attn + arow1 + jgl) = make_float2(e10, e11);
                eh[s][0] = pack_bf16x2(e00, e01);
                eh[s][1] = pack_bf16x2(e10, e11);
            }
            const int c0 = jj * 16 + tig * 2;
#pragma unroll
            for (int nt2 = 0; nt2 < 4; nt2++) {
                int v0 = nt2 * 8;
                uint32_t vb0 = *(const uint32_t*)&vh[(v0 + g) * ESTR + c0];
                uint32_t vb1 = *(const uint32_t*)&vh[(v0 + g) * ESTR + c0 + 8];
                mma16816(cacc[nt2], eh[0][0], eh[0][1], eh[1][0], eh[1][1], vb0, vb1);
            }
        }
    }

    // ---- ctx write as bf16 hi/lo (for tensor-core out_ln) ----
    {
        size_t row0 = (bS + q0 + qb + g) * (size_t)DM + h * 32;
        size_t row1 = row0 + 8 * DM;
#pragma unroll
        for (int nt = 0; nt < 4; nt++) {
            int v = nt * 8 + tig * 2;
#pragma unroll
            for (int rr = 0; rr < 2; rr++) {
                float f0 = cacc[nt][rr * 2], f1 = cacc[nt][rr * 2 + 1];
                uint32_t h0 = bf16_rn_bits(f0), h1 = bf16_rn_bits(f1);
                float l0 = f0 - __uint_as_float(h0 << 16);
                float l1 = f1 - __uint_as_float(h1 << 16);
                size_t off = (rr ? row1 : row0) + v;
                *(uint32_t*)&g_Ch[off] = h0 | (h1 << 16);
                *(uint32_t*)&g_Cl[off] = bf16_rn_bits(l0) | (bf16_rn_bits(l1) << 16);
            }
        }
    }
}

// ---------------------------------------------------------------------------
// K4: out = LayerNorm(ctx @ W_fc + g_R) — tensor-core mainloop (proj_tc style)
// with residual + LN epilogue. Reductions reuse dynamic smem.
// ---------------------------------------------------------------------------
__global__ __launch_bounds__(256) void out_ln_tc(const float* __restrict__ gamma,
                                                 const float* __restrict__ beta,
                                                 float* __restrict__ out)
{
    extern __shared__ __nv_bfloat16 psm[];
    __nv_bfloat16* sAh  = psm + PA_H;
    __nv_bfloat16* sAl  = psm + PA_L;
    __nv_bfloat16* sWth = psm + PW_H;
    __nv_bfloat16* sWtl = psm + PW_L;

    const int tid  = threadIdx.x;
    const int w    = tid >> 5;
    const int lane = tid & 31;
    const int g    = lane >> 2;
    const int tig  = lane & 3;
    const int r0   = blockIdx.x * 64;

    const __nv_bfloat16* gWh = g_Wth + 4 * DM * DM;
    const __nv_bfloat16* gWl = g_Wtl + 4 * DM * DM;

    const int mt = w >> 1;
    const int nh = (w & 1) * 64;
    const int m0 = mt * 16 + g;
    const int m1 = m0 + 8;

    float acc[8][4];
#pragma unroll
    for (int nt = 0; nt < 8; nt++)
#pragma unroll
        for (int i = 0; i < 4; i++) acc[nt][i] = 0.f;

    for (int ks = 0; ks < 2; ks++) {
        if (ks) __syncthreads();
        {
#pragma unroll
            for (int it = 0; it < 2; it++) {
                int id = tid + it * 256;
                int row = id >> 3, seg = (id & 7) * 8;
                size_t src = (size_t)(r0 + row) * DM + ks * 64 + seg;
                cp16(sAh + row * PSTR + seg, g_Ch + src);
                cp16(sAl + row * PSTR + seg, g_Cl + src);
            }
#pragma unroll
            for (int it = 0; it < 4; it++) {
                int id = tid + it * 256;
                int n = id >> 3, seg = (id & 7) * 8;
                size_t src = (size_t)n * DM + ks * 64 + seg;
                cp16(sWth + n * PSTR + seg, gWh + src);
                cp16(sWtl + n * PSTR + seg, gWl + src);
            }
        }
        cp_commit();
        cp_wait<0>();
        __syncthreads();

#pragma unroll
        for (int kk = 0; kk < 64; kk += 16) {
            const int dof = kk + tig * 2;
            uint32_t ah0 = *(const uint32_t*)&sAh[m0 * PSTR + dof];
            uint32_t ah1 = *(const uint32_t*)&sAh[m1 * PSTR + dof];
            uint32_t ah2 = *(const uint32_t*)&sAh[m0 * PSTR + dof + 8];
            uint32_t ah3 = *(const uint32_t*)&sAh[m1 * PSTR + dof + 8];
            uint32_t al0 = *(const uint32_t*)&sAl[m0 * PSTR + dof];
            uint32_t al1 = *(const uint32_t*)&sAl[m1 * PSTR + dof];
            uint32_t al2 = *(const uint32_t*)&sAl[m0 * PSTR + dof + 8];
            uint32_t al3 = *(const uint32_t*)&sAl[m1 * PSTR + dof + 8];
#pragma unroll
            for (int nt = 0; nt < 8; nt++) {
                int ncol = nh + nt * 8 + g;
                uint32_t bh0 = *(const uint32_t*)&sWth[ncol * PSTR + dof];
                uint32_t bh1 = *(const uint32_t*)&sWth[ncol * PSTR + dof + 8];
                uint32_t bl0 = *(const uint32_t*)&sWtl[ncol * PSTR + dof];
                uint32_t bl1 = *(const uint32_t*)&sWtl[ncol * PSTR + dof + 8];
                mma16816(acc[nt], ah0, ah1, ah2, ah3, bh0, bh1);
                mma16816(acc[nt], ah0, ah1, ah2, ah3, bl0, bl1);
                mma16816(acc[nt], al0, al1, al2, al3, bh0, bh1);
            }
        }
    }

    // ---- residual + partial moments ----
    const size_t row0 = (size_t)(r0 + m0);
    const size_t row1 = row0 + 8;
    float ps0 = 0.f, pq0 = 0.f, ps1 = 0.f, pq1 = 0.f;
#pragma unroll
    for (int nt = 0; nt < 8; nt++) {
        int col = nh + nt * 8 + tig * 2;
        float2 rv0 = *(const float2*)&g_R[row0 * DM + col];
        float2 rv1 = *(const float2*)&g_R[row1 * DM + col];
        acc[nt][0] += rv0.x; acc[nt][1] += rv0.y;
        acc[nt][2] += rv1.x; acc[nt][3] += rv1.y;
        ps0 += acc[nt][0] + acc[nt][1];
        pq0 += acc[nt][0] * acc[nt][0] + acc[nt][1] * acc[nt][1];
        ps1 += acc[nt][2] + acc[nt][3];
        pq1 += acc[nt][2] * acc[nt][3] * 0.f + acc[nt][2] * acc[nt][2] + acc[nt][3] * acc[nt][3];
    }

    // ---- LN reductions in reused dynamic smem ----
    float* red1 = (float*)psm;            // [64][8]
    float* red2 = red1 + 64 * 8;          // [64][8]
    float* smu  = red2 + 64 * 8;          // [64]
    float* srs  = smu + 64;               // [64]
    __syncthreads();                      // done reading sA/sW
    const int slot = (w & 1) * 4 + tig;
    red1[m0 * 8 + slot] = ps0;
    red2[m0 * 8 + slot] = pq0;
    red1[m1 * 8 + slot] = ps1;
    red2[m1 * 8 + slot] = pq1;
    __syncthreads();
    if (tid < 64) {
        float s = 0.f, q = 0.f;
#pragma unroll
        for (int j = 0; j < 8; j++) { s += red1[tid * 8 + j]; q += red2[tid * 8 + j]; }
        float mu = s * (1.0f / 128.0f);
        float var = q * (1.0f / 128.0f) - mu * mu;
        smu[tid] = mu;
        srs[tid] = rsqrtf(var + 1e-5f);
    }
    __syncthreads();

    const float mu0 = smu[m0], rs0 = srs[m0];
    const float mu1 = smu[m1], rs1 = srs[m1];
#pragma unroll
    for (int nt = 0; nt < 8; nt++) {
        int col = nh + nt * 8 + tig * 2;
        float2 gm = *(const float2*)&gamma[col];
        float2 bt = *(const float2*)&beta[col];
        float2 o0 = make_float2((acc[nt][0] - mu0) * rs0 * gm.x + bt.x,
                                (acc[nt][1] - mu0) * rs0 * gm.y + bt.y);
        float2 o1 = make_float2((acc[nt][2] - mu1) * rs1 * gm.x + bt.x,
                                (acc[nt][3] - mu1) * rs1 * gm.y + bt.y);
        *(float2*)&out[row0 * DM + col] = o0;
        *(float2*)&out[row1 * DM + col] = o1;
    }
}

// ---------------------------------------------------------------------------
extern "C" void kernel_launch(void* const* d_in, const int* in_sizes, int n_in,
                              void* d_out, int out_size)
{
    const float* inQ  = (const float*)d_in[0];
    const float* inK  = (const float*)d_in[1];
    const float* inV  = (const float*)d_in[2];
    const unsigned char* mask = (const unsigned char*)d_in[3];
    const float* Wfc0 = (const float*)d_in[4];
    const float* WQ   = (const float*)d_in[5];
    const float* WK   = (const float*)d_in[6];
    const float* WV   = (const float*)d_in[7];
    const float* Wfc  = (const float*)d_in[8];
    const float* gam  = (const float*)d_in[9];
    const float* bet  = (const float*)d_in[10];
    float* out  = (float*)d_out;
    float* attn = out + OUT_ELEMS;

    detect_mask<<<1, 256>>>(mask);                                  // 1
    split_inputs<<<dim3(NR * DM / 1024, 3), 256>>>(inQ, inK, inV);  // 2
    split_weights<<<5, 256>>>(Wfc0, WQ, WK, WV, Wfc);               // 3

    cudaFuncSetAttribute(proj_tc, cudaFuncAttributeMaxDynamicSharedMemorySize,
                         (int)P_SMEM_BYTES);
    proj_tc<<<dim3(NR / 64, 4), 256, P_SMEM_BYTES>>>();             // 4

    dim3 agrid(SEQ / TQ, BATCH * 4);
    cudaFuncSetAttribute(rowsum_pass, cudaFuncAttributeMaxDynamicSharedMemorySize,
                         (int)RS_SMEM_BYTES);
    rowsum_pass<<<agrid, 256, RS_SMEM_BYTES>>>(mask);               // 5

    cudaFuncSetAttribute(attn_mma, cudaFuncAttributeMaxDynamicSharedMemorySize,
                         (int)SMEM_BYTES);
    attn_mma<<<agrid, 256, SMEM_BYTES>>>(mask, attn);               // 6 (ncu)

    cudaFuncSetAttribute(out_ln_tc, cudaFuncAttributeMaxDynamicSharedMemorySize,
                         (int)P_SMEM_BYTES);
    out_ln_tc<<<NR / 64, 256, P_SMEM_BYTES>>>(gam, bet, out);       // 7
}

// round 14
// speedup vs baseline: 1.6655x; 1.1497x over previous
#include <cuda_runtime.h>
#include <cuda_bf16.h>
#include <stdint.h>

// ---------------------------------------------------------------------------
// MultiHeadAttention: out = LN(ctx@W_fc + X@W_fc0), attn materialized.
// B=8, S=2048, D=128, H=4, dk=dv=32.
// Output layout: [out (8*2048*128)] then [attn (8*4*2048*2048)].
// R14: mask packed to bits once (4.2MB); rowsum/attn pipe mask bits through
// smem via cp.async -> 16 mask LDGs/chunk/thread become one 8B LDS.
// ---------------------------------------------------------------------------

namespace {
constexpr int BATCH = 8;
constexpr int SEQ   = 2048;
constexpr int DM    = 128;
constexpr int NR    = BATCH * SEQ;                 // 16384 rows
constexpr size_t OUT_ELEMS = (size_t)NR * DM;      // 2,097,152
constexpr int TQ = 128;                            // q-tile per block
constexpr int TK = 64;                             // k-chunk
constexpr int NC = SEQ / TK;                       // 32 chunks
constexpr int SW = SEQ / 32;                       // 64 mask words per row

// attn_mma smem (bf16 units) + mask word region
constexpr int QSTR = 40;
constexpr int ESTR = 72;
constexpr int BUF_SZ  = 64 * QSTR * 2 + 32 * ESTR;     // 7424 bf16
constexpr int SMEM_BF16 = 3 * BUF_SZ;                  // 22272
constexpr size_t MW_BYTES = 3 * 128 * 2 * 4;           // 3072 B (3 bufs x 128 rows x 2 words)
constexpr size_t SMEM_BYTES = (size_t)SMEM_BF16 * 2 + MW_BYTES;  // 47,616 B

// rowsum_pass smem
constexpr int KBUF = 64 * QSTR;                        // 2560 bf16
constexpr size_t RS_SMEM_BYTES = (size_t)(3 * KBUF) * 2 + MW_BYTES;  // 18,432 B

// proj_tc / out_ln_tc smem
constexpr int PSTR = 72;
constexpr int PA_H = 0;
constexpr int PA_L = PA_H + 64 * PSTR;
constexpr int PW_H = PA_L + 64 * PSTR;
constexpr int PW_L = PW_H + 128 * PSTR;
constexpr int P_BF16 = PW_L + 128 * PSTR;
constexpr size_t P_SMEM_BYTES = (size_t)P_BF16 * 2;    // 55,296 B
constexpr int VSTR = 136;
}

// Scratch (device globals: allocation-free rule)
__device__ float g_R  [NR * DM];
__device__ float g_rinv[BATCH * 4 * SEQ];
__device__ uint32_t g_mbits[(size_t)BATCH * SEQ * SW];   // 4 MB bit mask
__device__ __nv_bfloat16 g_Xh[3 * NR * DM];
__device__ __nv_bfloat16 g_Xl[3 * NR * DM];
__device__ __nv_bfloat16 g_Wth[5 * DM * DM];
__device__ __nv_bfloat16 g_Wtl[5 * DM * DM];
__device__ __nv_bfloat16 g_Qh[NR * DM];
__device__ __nv_bfloat16 g_Ql[NR * DM];
__device__ __nv_bfloat16 g_Kh[NR * DM];
__device__ __nv_bfloat16 g_Kl[NR * DM];
__device__ __nv_bfloat16 g_Ch[NR * DM];
__device__ __nv_bfloat16 g_Cl[NR * DM];
__device__ __nv_bfloat16 g_Vt[(size_t)BATCH * 4 * 32 * SEQ];  // [bh][v][s]
__device__ int   g_mask_mode;   // 0=uint8, 1=int32, 2=float32

// ---------------------------------------------------------------------------
__device__ __forceinline__ float ex2(float y)
{
    float r;
    asm("ex2.approx.f32 %0, %1;" : "=f"(r) : "f"(y));
    return r;
}

__device__ __forceinline__ uint32_t pack_bf16x2(float lo, float hi)
{
    uint32_t r;
    asm("cvt.rn.bf16x2.f32 %0, %1, %2;" : "=r"(r) : "f"(hi), "f"(lo));
    return r;
}

__device__ __forceinline__ uint32_t bf16_rn_bits(float x)
{
    uint32_t b = __float_as_uint(x);
    return (b + 0x7fffu + ((b >> 16) & 1u)) >> 16;
}

__device__ __forceinline__ void mma16816(float c[4],
                                         uint32_t a0, uint32_t a1, uint32_t a2, uint32_t a3,
                                         uint32_t b0, uint32_t b1)
{
    asm volatile("mma.sync.aligned.m16n8k16.row.col.f32.bf16.bf16.f32 "
                 "{%0,%1,%2,%3}, {%4,%5,%6,%7}, {%8,%9}, {%0,%1,%2,%3};"
                 : "+f"(c[0]), "+f"(c[1]), "+f"(c[2]), "+f"(c[3])
                 : "r"(a0), "r"(a1), "r"(a2), "r"(a3), "r"(b0), "r"(b1));
}

__device__ __forceinline__ void cp16(const __nv_bfloat16* smem_dst, const void* gsrc)
{
    uint32_t d = (uint32_t)__cvta_generic_to_shared(smem_dst);
    asm volatile("cp.async.cg.shared.global [%0], [%1], 16;" :: "r"(d), "l"(gsrc));
}
__device__ __forceinline__ void cp8(const void* smem_dst, const void* gsrc)
{
    uint32_t d = (uint32_t)__cvta_generic_to_shared(smem_dst);
    asm volatile("cp.async.ca.shared.global [%0], [%1], 8;" :: "r"(d), "l"(gsrc));
}
__device__ __forceinline__ void cp_commit()
{
    asm volatile("cp.async.commit_group;");
}
template <int N>
__device__ __forceinline__ void cp_wait()
{
    asm volatile("cp.async.wait_group %0;" :: "n"(N));
}

// ---------------------------------------------------------------------------
// K0: detect mask dtype.
// ---------------------------------------------------------------------------
__global__ void detect_mask(const unsigned char* __restrict__ m)
{
    __shared__ int s_gt1, s_off;
    if (threadIdx.x == 0) { s_gt1 = 0; s_off = 0; }
    __syncthreads();
    int gt1 = 0, off = 0;
    for (int i = threadIdx.x; i < 4096; i += 256) {
        unsigned char v = m[i];
        if (v > 1) gt1 = 1;
        else if (v == 1 && (i & 3) != 0) off = 1;
    }
    if (gt1) atomicOr(&s_gt1, 1);
    if (off) atomicOr(&s_off, 1);
    __syncthreads();
    if (threadIdx.x == 0)
        g_mask_mode = s_gt1 ? 2 : (s_off ? 0 : 1);
}

// ---------------------------------------------------------------------------
// K0b: pack mask -> bits. One output word (32 flags) per thread.
// flag[j] == bit (g_mbits[j>>5] >> (j&31)) & 1.
// ---------------------------------------------------------------------------
__global__ __launch_bounds__(256) void pack_mask(const unsigned char* __restrict__ mask)
{
    const int mode = g_mask_mode;
    size_t wi = (size_t)blockIdx.x * 256 + threadIdx.x;
    uint32_t bits = 0;
    if (mode == 0) {
        const uint4* p = (const uint4*)(mask + wi * 32);
        uint4 a = p[0], b = p[1];
        const uint32_t wa[8] = {a.x, a.y, a.z, a.w, b.x, b.y, b.z, b.w};
#pragma unroll
        for (int q = 0; q < 8; q++) {
            uint32_t v = wa[q];
#pragma unroll
            for (int t = 0; t < 4; t++)
                bits |= (((v >> (t * 8)) & 0xffu) ? 1u : 0u) << (q * 4 + t);
        }
    } else if (mode == 1) {
        const uint4* p = (const uint4*)((const uint32_t*)mask + wi * 32);
#pragma unroll
        for (int q = 0; q < 8; q++) {
            uint4 v = p[q];
            bits |= (v.x ? 1u : 0u) << (q * 4);
            bits |= (v.y ? 1u : 0u) << (q * 4 + 1);
            bits |= (v.z ? 1u : 0u) << (q * 4 + 2);
            bits |= (v.w ? 1u : 0u) << (q * 4 + 3);
        }
    } else {
        const float4* p = (const float4*)((const float*)mask + wi * 32);
#pragma unroll
        for (int q = 0; q < 8; q++) {
            float4 v = p[q];
            bits |= (v.x != 0.f ? 1u : 0u) << (q * 4);
            bits |= (v.y != 0.f ? 1u : 0u) << (q * 4 + 1);
            bits |= (v.z != 0.f ? 1u : 0u) << (q * 4 + 2);
            bits |= (v.w != 0.f ? 1u : 0u) << (q * 4 + 3);
        }
    }
    g_mbits[wi] = bits;
}

// ---------------------------------------------------------------------------
// P0: split inputs fp32 -> bf16 hi/lo.
// ---------------------------------------------------------------------------
__global__ __launch_bounds__(256) void split_inputs(const float* __restrict__ inQ,
                                                    const float* __restrict__ inK,
                                                    const float* __restrict__ inV)
{
    const float* src = (blockIdx.y == 0) ? inQ : (blockIdx.y == 1) ? inK : inV;
    __nv_bfloat16* H = g_Xh + (size_t)blockIdx.y * NR * DM;
    __nv_bfloat16* L = g_Xl + (size_t)blockIdx.y * NR * DM;
    size_t i = ((size_t)blockIdx.x * 256 + threadIdx.x) * 4;
    float4 v = *(const float4*)&src[i];
    uint32_t hx = bf16_rn_bits(v.x), hy = bf16_rn_bits(v.y);
    uint32_t hz = bf16_rn_bits(v.z), hw = bf16_rn_bits(v.w);
    float lx = v.x - __uint_as_float(hx << 16);
    float ly = v.y - __uint_as_float(hy << 16);
    float lz = v.z - __uint_as_float(hz << 16);
    float lw = v.w - __uint_as_float(hw << 16);
    *(uint2*)&H[i] = make_uint2(hx | (hy << 16), hz | (hw << 16));
    *(uint2*)&L[i] = make_uint2(bf16_rn_bits(lx) | (bf16_rn_bits(ly) << 16),
                                bf16_rn_bits(lz) | (bf16_rn_bits(lw) << 16));
}

// ---------------------------------------------------------------------------
// P1: split + transpose weights (Wfc0, WQ, WK, WV, Wfc).
// ---------------------------------------------------------------------------
__global__ __launch_bounds__(256) void split_weights(const float* __restrict__ Wfc0,
                                                     const float* __restrict__ WQ,
                                                     const float* __restrict__ WK,
                                                     const float* __restrict__ WV,
                                                     const float* __restrict__ Wfc)
{
    const float* W;
    switch (blockIdx.x) {
        case 0:  W = Wfc0; break;
        case 1:  W = WQ;   break;
        case 2:  W = WK;   break;
        case 3:  W = WV;   break;
        default: W = Wfc;  break;
    }
    __nv_bfloat16* H = g_Wth + blockIdx.x * DM * DM;
    __nv_bfloat16* L = g_Wtl + blockIdx.x * DM * DM;
    for (int idx = threadIdx.x; idx < DM * DM; idx += 256) {
        int k = idx >> 7, n = idx & 127;
        float x = W[idx];
        uint32_t hb = bf16_rn_bits(x);
        float lf = x - __uint_as_float(hb << 16);
        ((uint16_t*)H)[n * DM + k] = (uint16_t)hb;
        ((uint16_t*)L)[n * DM + k] = (uint16_t)bf16_rn_bits(lf);
    }
}

// ---------------------------------------------------------------------------
// P2: tensor-core projections (unchanged).
// ---------------------------------------------------------------------------
__global__ __launch_bounds__(256, 4) void proj_tc()
{
    extern __shared__ __nv_bfloat16 psm[];
    __nv_bfloat16* sAh  = psm + PA_H;
    __nv_bfloat16* sAl  = psm + PA_L;
    __nv_bfloat16* sWth = psm + PW_H;
    __nv_bfloat16* sWtl = psm + PW_L;

    const int tid  = threadIdx.x;
    const int w    = tid >> 5;
    const int lane = tid & 31;
    const int g    = lane >> 2;
    const int tig  = lane & 3;
    const int gm   = blockIdx.y;
    const int r0   = blockIdx.x * 64;

    const int xsel = (gm <= 1) ? 0 : (gm - 1);
    const __nv_bfloat16* gXh = g_Xh + (size_t)xsel * NR * DM;
    const __nv_bfloat16* gXl = g_Xl + (size_t)xsel * NR * DM;
    const __nv_bfloat16* gWh = g_Wth + gm * DM * DM;
    const __nv_bfloat16* gWl = g_Wtl + gm * DM * DM;

    const int mt = w >> 1;
    const int nh = (w & 1) * 64;
    const int m0 = mt * 16 + g;
    const int m1 = m0 + 8;

    float acc[8][4];
#pragma unroll
    for (int nt = 0; nt < 8; nt++)
#pragma unroll
        for (int i = 0; i < 4; i++) acc[nt][i] = 0.f;

    for (int ks = 0; ks < 2; ks++) {
        if (ks) __syncthreads();
        {
#pragma unroll
            for (int it = 0; it < 2; it++) {
                int id = tid + it * 256;
                int row = id >> 3, seg = (id & 7) * 8;
                size_t src = (size_t)(r0 + row) * DM + ks * 64 + seg;
                cp16(sAh + row * PSTR + seg, gXh + src);
                cp16(sAl + row * PSTR + seg, gXl + src);
            }
#pragma unroll
            for (int it = 0; it < 4; it++) {
                int id = tid + it * 256;
                int n = id >> 3, seg = (id & 7) * 8;
                size_t src = (size_t)n * DM + ks * 64 + seg;
                cp16(sWth + n * PSTR + seg, gWh + src);
                cp16(sWtl + n * PSTR + seg, gWl + src);
            }
        }
        cp_commit();
        cp_wait<0>();
        __syncthreads();

#pragma unroll
        for (int kk = 0; kk < 64; kk += 16) {
            const int dof = kk + tig * 2;
            uint32_t ah0 = *(const uint32_t*)&sAh[m0 * PSTR + dof];
            uint32_t ah1 = *(const uint32_t*)&sAh[m1 * PSTR + dof];
            uint32_t ah2 = *(const uint32_t*)&sAh[m0 * PSTR + dof + 8];
            uint32_t ah3 = *(const uint32_t*)&sAh[m1 * PSTR + dof + 8];
            uint32_t al0 = *(const uint32_t*)&sAl[m0 * PSTR + dof];
            uint32_t al1 = *(const uint32_t*)&sAl[m1 * PSTR + dof];
            uint32_t al2 = *(const uint32_t*)&sAl[m0 * PSTR + dof + 8];
            uint32_t al3 = *(const uint32_t*)&sAl[m1 * PSTR + dof + 8];
#pragma unroll
            for (int nt = 0; nt < 8; nt++) {
                int ncol = nh + nt * 8 + g;
                uint32_t bh0 = *(const uint32_t*)&sWth[ncol * PSTR + dof];
                uint32_t bh1 = *(const uint32_t*)&sWth[ncol * PSTR + dof + 8];
                uint32_t bl0 = *(const uint32_t*)&sWtl[ncol * PSTR + dof];
                uint32_t bl1 = *(const uint32_t*)&sWtl[ncol * PSTR + dof + 8];
                mma16816(acc[nt], ah0, ah1, ah2, ah3, bh0, bh1);
                mma16816(acc[nt], ah0, ah1, ah2, ah3, bl0, bl1);
                mma16816(acc[nt], al0, al1, al2, al3, bh0, bh1);
            }
        }
    }

    const size_t row0 = (size_t)(r0 + m0);
    const size_t row1 = row0 + 8;

    if (gm == 0) {
#pragma unroll
        for (int nt = 0; nt < 8; nt++) {
            int col = nh + nt * 8 + tig * 2;
            *(float2*)&g_R[row0 * DM + col] = make_float2(acc[nt][0], acc[nt][1]);
            *(float2*)&g_R[row1 * DM + col] = make_float2(acc[nt][2], acc[nt][3]);
        }
    } else if (gm == 1 || gm == 2) {
        __nv_bfloat16* H = (gm == 1) ? g_Qh : g_Kh;
        __nv_bfloat16* L = (gm == 1) ? g_Ql : g_Kl;
#pragma unroll
        for (int nt = 0; nt < 8; nt++) {
            int col = nh + nt * 8 + tig * 2;
#pragma unroll
            for (int rr = 0; rr < 2; rr++) {
                float f0 = acc[nt][rr * 2], f1 = acc[nt][rr * 2 + 1];
                uint32_t h0 = bf16_rn_bits(f0), h1 = bf16_rn_bits(f1);
                float l0 = f0 - __uint_as_float(h0 << 16);
                float l1 = f1 - __uint_as_float(h1 << 16);
                size_t off = (rr ? row1 : row0) * DM + col;
                *(uint32_t*)&H[off] = h0 | (h1 << 16);
                *(uint32_t*)&L[off] = bf16_rn_bits(l0) | (bf16_rn_bits(l1) << 16);
            }
        }
    } else {
        uint16_t* sV = (uint16_t*)(psm + PW_H);
        __syncthreads();
#pragma unroll
        for (int nt = 0; nt < 8; nt++) {
            int col = nh + nt * 8 + tig * 2;
            *(uint32_t*)&sV[m0 * VSTR + col] =
                bf16_rn_bits(acc[nt][0]) | (bf16_rn_bits(acc[nt][1]) << 16);
            *(uint32_t*)&sV[m1 * VSTR + col] =
                bf16_rn_bits(acc[nt][2]) | (bf16_rn_bits(acc[nt][3]) << 16);
        }
        __syncthreads();
        const int v   = tid >> 3;
        const int seg = (tid & 7) * 8;
        const int b   = r0 / SEQ;
        const int sblock = r0 % SEQ;
#pragma unroll
        for (int hd = 0; hd < 4; hd++) {
            uint32_t wv[4];
#pragma unroll
            for (int p = 0; p < 4; p++) {
                uint32_t lo = sV[(seg + p * 2) * VSTR + hd * 32 + v];
                uint32_t hi = sV[(seg + p * 2 + 1) * VSTR + hd * 32 + v];
                wv[p] = lo | (hi << 16);
            }
            size_t off = ((size_t)(b * 4 + hd) * 32 + v) * SEQ + sblock + seg;
            *(uint4*)&g_Vt[off] = make_uint4(wv[0], wv[1], wv[2], wv[3]);
        }
    }
}

// ---------------------------------------------------------------------------
// K1.5: rowsum pre-pass, 2-product scores, bit-mask from smem pipeline.
// ---------------------------------------------------------------------------
__global__ __launch_bounds__(256, 4) void rowsum_pass()
{
    extern __shared__ __nv_bfloat16 smb[];
    uint32_t* mw = (uint32_t*)(smb + 3 * KBUF);   // [3][128][2] words
    __shared__ float srow[128];

    const int tid  = threadIdx.x;
    const int w    = tid >> 5;
    const int lane = tid & 31;
    const int g    = lane >> 2;
    const int tig  = lane & 3;
    const int qb   = w * 16;

    const int bh = blockIdx.y;
    const int b = bh >> 2, h = bh & 3;
    const int q0 = blockIdx.x * TQ;
    const float CE = 1.4426950408889634f * 0.17677669529663689f;
    const size_t bS = (size_t)b * SEQ;

    const int kj   = tid >> 2;
    const int kseg = (tid & 3) * 8;
    const __nv_bfloat16* gK_h = g_Kh + bS * DM + h * 32;
    const uint32_t* gMB = g_mbits + (bS + q0) * SW;

    auto issue_chunk = [&](int kc) {
        cp16(smb + (kc % 3) * KBUF + kj * QSTR + kseg,
             gK_h + (size_t)(kc * TK + kj) * DM + kseg);
        if (tid < 128)
            cp8(mw + (kc % 3) * 256 + tid * 2, gMB + (size_t)tid * SW + kc * 2);
    };
    issue_chunk(0);
    cp_commit();
    issue_chunk(1);
    cp_commit();

    uint32_t qh[2][4], ql[2][4];
    {
        const __nv_bfloat16* gQ_h = g_Qh + (bS + q0) * DM + h * 32;
        const __nv_bfloat16* gQ_l = g_Ql + (bS + q0) * DM + h * 32;
#pragma unroll
        for (int kk = 0; kk < 2; kk++) {
            int c0 = kk * 16 + tig * 2;
            size_t r0o = (size_t)(qb + g) * DM + c0;
            size_t r1o = (size_t)(qb + g + 8) * DM + c0;
            qh[kk][0] = *(const uint32_t*)&gQ_h[r0o];
            qh[kk][1] = *(const uint32_t*)&gQ_h[r1o];
            qh[kk][2] = *(const uint32_t*)&gQ_h[r0o + 8];
            qh[kk][3] = *(const uint32_t*)&gQ_h[r1o + 8];
            ql[kk][0] = *(const uint32_t*)&gQ_l[r0o];
            ql[kk][1] = *(const uint32_t*)&gQ_l[r1o];
            ql[kk][2] = *(const uint32_t*)&gQ_l[r0o + 8];
            ql[kk][3] = *(const uint32_t*)&gQ_l[r1o + 8];
        }
    }

    float rs0 = 0.f, rs1 = 0.f;

    for (int kc = 0; kc < NC; kc++) {
        cp_wait<1>();
        __syncthreads();
        if (kc + 2 < NC) issue_chunk(kc + 2);
        cp_commit();

        const __nv_bfloat16* kh = smb + (kc % 3) * KBUF;
        const uint2 mw0 = *(const uint2*)&mw[(kc % 3) * 256 + (qb + g) * 2];
        const uint2 mw1 = *(const uint2*)&mw[(kc % 3) * 256 + (qb + g + 8) * 2];

#pragma unroll
        for (int jj = 0; jj < 4; jj++) {
            const uint32_t w0 = (jj < 2) ? mw0.x : mw0.y;
            const uint32_t w1 = (jj < 2) ? mw1.x : mw1.y;
#pragma unroll
            for (int s = 0; s < 2; s++) {
                const int j0 = jj * 16 + s * 8;
                float c[4]  = {0.f, 0.f, 0.f, 0.f};
                float c2[4] = {0.f, 0.f, 0.f, 0.f};
                {
                    const int dof0 = tig * 2;
                    uint32_t bh0 = *(const uint32_t*)&kh[(j0 + g) * QSTR + dof0];
                    uint32_t bh1 = *(const uint32_t*)&kh[(j0 + g) * QSTR + dof0 + 8];
                    mma16816(c, qh[0][0], qh[0][1], qh[0][2], qh[0][3], bh0, bh1);
                    mma16816(c, ql[0][0], ql[0][1], ql[0][2], ql[0][3], bh0, bh1);
                }
                {
                    const int dof1 = 16 + tig * 2;
                    uint32_t bh0 = *(const uint32_t*)&kh[(j0 + g) * QSTR + dof1];
                    uint32_t bh1 = *(const uint32_t*)&kh[(j0 + g) * QSTR + dof1 + 8];
                    mma16816(c2, qh[1][0], qh[1][1], qh[1][2], qh[1][3], bh0, bh1);
                    mma16816(c2, ql[1][0], ql[1][1], ql[1][2], ql[1][3], bh0, bh1);
                }
#pragma unroll
                for (int i = 0; i < 4; i++) c[i] += c2[i];
                const int bp = ((jj & 1) * 16 + s * 8 + tig * 2);
                rs0 += (((w0 >> bp) & 1) ? 0.f : ex2(c[0] * CE))
                     + (((w0 >> (bp + 1)) & 1) ? 0.f : ex2(c[1] * CE));
                rs1 += (((w1 >> bp) & 1) ? 0.f : ex2(c[2] * CE))
                     + (((w1 >> (bp + 1)) & 1) ? 0.f : ex2(c[3] * CE));
            }
        }
    }

    rs0 += __shfl_xor_sync(0xffffffff, rs0, 1);
    rs0 += __shfl_xor_sync(0xffffffff, rs0, 2);
    rs1 += __shfl_xor_sync(0xffffffff, rs1, 1);
    rs1 += __shfl_xor_sync(0xffffffff, rs1, 2);
    __syncthreads();
    if (tig == 0) {
        srow[qb + g]     = rs0;
        srow[qb + g + 8] = rs1;
    }
    __syncthreads();
    if (tid < 128)
        g_rinv[(size_t)bh * SEQ + q0 + tid] = 1.0f / srow[tid];
}

// ---------------------------------------------------------------------------
// K2: tensor-core attention; attn written NORMALIZED; bit-mask via smem.
// ---------------------------------------------------------------------------
__global__ __launch_bounds__(256, 4) void attn_mma(float* __restrict__ attn)
{
    extern __shared__ __nv_bfloat16 smb[];
    uint32_t* mw = (uint32_t*)(smb + SMEM_BF16);   // [3][128][2] words

    const int tid  = threadIdx.x;
    const int w    = tid >> 5;
    const int lane = tid & 31;
    const int g    = lane >> 2;
    const int tig  = lane & 3;
    const int qb   = w * 16;

    const int bh = blockIdx.y;
    const int b = bh >> 2, h = bh & 3;
    const int q0 = blockIdx.x * TQ;
    const float CE = 1.4426950408889634f * 0.17677669529663689f;
    const size_t bS = (size_t)b * SEQ;

    const int kj   = tid >> 2;
    const int kseg = (tid & 3) * 8;
    const int vv   = tid >> 3;
    const int vseg = (tid & 7) * 8;
    const __nv_bfloat16* gK_h = g_Kh + bS * DM + h * 32;
    const __nv_bfloat16* gK_l = g_Kl + bS * DM + h * 32;
    const __nv_bfloat16* gV_t = g_Vt + ((size_t)bh * 32 + vv) * SEQ;
    const uint32_t* gMB = g_mbits + (bS + q0) * SW;

    auto issue_chunk = [&](int kc) {
        __nv_bfloat16* kh = smb + (kc % 3) * BUF_SZ;
        __nv_bfloat16* kl = kh + 64 * QSTR;
        __nv_bfloat16* vh = kl + 64 * QSTR;
        size_t koff = (size_t)(kc * TK + kj) * DM + kseg;
        cp16(kh + kj * QSTR + kseg, gK_h + koff);
        cp16(kl + kj * QSTR + kseg, gK_l + koff);
        cp16(vh + vv * ESTR + vseg, gV_t + kc * TK + vseg);
        if (tid < 128)
            cp8(mw + (kc % 3) * 256 + tid * 2, gMB + (size_t)tid * SW + kc * 2);
    };

    issue_chunk(0);
    cp_commit();
    issue_chunk(1);
    cp_commit();

    uint32_t qh[2][4], ql[2][4];
    {
        const __nv_bfloat16* gQ_h = g_Qh + (bS + q0) * DM + h * 32;
        const __nv_bfloat16* gQ_l = g_Ql + (bS + q0) * DM + h * 32;
#pragma unroll
        for (int kk = 0; kk < 2; kk++) {
            int c0 = kk * 16 + tig * 2;
            size_t r0o = (size_t)(qb + g) * DM + c0;
            size_t r1o = (size_t)(qb + g + 8) * DM + c0;
            qh[kk][0] = *(const uint32_t*)&gQ_h[r0o];
            qh[kk][1] = *(const uint32_t*)&gQ_h[r1o];
            qh[kk][2] = *(const uint32_t*)&gQ_h[r0o + 8];
            qh[kk][3] = *(const uint32_t*)&gQ_h[r1o + 8];
            ql[kk][0] = *(const uint32_t*)&gQ_l[r0o];
            ql[kk][1] = *(const uint32_t*)&gQ_l[r1o];
            ql[kk][2] = *(const uint32_t*)&gQ_l[r0o + 8];
            ql[kk][3] = *(const uint32_t*)&gQ_l[r1o + 8];
        }
    }

    const int qg0 = q0 + qb + g;
    const float rinv0 = g_rinv[(size_t)bh * SEQ + qg0];
    const float rinv1 = g_rinv[(size_t)bh * SEQ + qg0 + 8];

    float cacc[4][4];
#pragma unroll
    for (int n = 0; n < 4; n++)
#pragma unroll
        for (int i = 0; i < 4; i++) cacc[n][i] = 0.f;

    const size_t arow0 = ((size_t)bh * SEQ + qg0) * SEQ;
    const size_t arow1 = arow0 + 8 * SEQ;

    for (int kc = 0; kc < NC; kc++) {
        const int k0 = kc * TK;

        cp_wait<1>();
        __syncthreads();
        if (kc + 2 < NC) issue_chunk(kc + 2);
        cp_commit();

        const __nv_bfloat16* kh = smb + (kc % 3) * BUF_SZ;
        const __nv_bfloat16* kl = kh + 64 * QSTR;
        const __nv_bfloat16* vh = kl + 64 * QSTR;
        const uint2 mw0 = *(const uint2*)&mw[(kc % 3) * 256 + (qb + g) * 2];
        const uint2 mw1 = *(const uint2*)&mw[(kc % 3) * 256 + (qb + g + 8) * 2];

#pragma unroll
        for (int jj = 0; jj < 4; jj++) {
            const uint32_t w0 = (jj < 2) ? mw0.x : mw0.y;
            const uint32_t w1 = (jj < 2) ? mw1.x : mw1.y;

            uint32_t eh[2][2];
#pragma unroll
            for (int s = 0; s < 2; s++) {
                const int j0 = jj * 16 + s * 8;
                float c[4]  = {0.f, 0.f, 0.f, 0.f};
                float c2[4] = {0.f, 0.f, 0.f, 0.f};
                {
                    const int dof0 = tig * 2;
                    uint32_t bh0 = *(const uint32_t*)&kh[(j0 + g) * QSTR + dof0];
                    uint32_t bh1 = *(const uint32_t*)&kh[(j0 + g) * QSTR + dof0 + 8];
                    uint32_t bl0 = *(const uint32_t*)&kl[(j0 + g) * QSTR + dof0];
                    uint32_t bl1 = *(const uint32_t*)&kl[(j0 + g) * QSTR + dof0 + 8];
                    mma16816(c, qh[0][0], qh[0][1], qh[0][2], qh[0][3], bh0, bh1);
                    mma16816(c, qh[0][0], qh[0][1], qh[0][2], qh[0][3], bl0, bl1);
                    mma16816(c, ql[0][0], ql[0][1], ql[0][2], ql[0][3], bh0, bh1);
                }
                {
                    const int dof1 = 16 + tig * 2;
                    uint32_t bh0 = *(const uint32_t*)&kh[(j0 + g) * QSTR + dof1];
                    uint32_t bh1 = *(const uint32_t*)&kh[(j0 + g) * QSTR + dof1 + 8];
                    uint32_t bl0 = *(const uint32_t*)&kl[(j0 + g) * QSTR + dof1];
                    uint32_t bl1 = *(const uint32_t*)&kl[(j0 + g) * QSTR + dof1 + 8];
                    mma16816(c2, qh[1][0], qh[1][1], qh[1][2], qh[1][3], bh0, bh1);
                    mma16816(c2, qh[1][0], qh[1][1], qh[1][2], qh[1][3], bl0, bl1);
                    mma16816(c2, ql[1][0], ql[1][1], ql[1][2], ql[1][3], bh0, bh1);
                }
#pragma unroll
                for (int i = 0; i < 4; i++) c[i] += c2[i];

                const int jgl = k0 + j0 + tig * 2;
                const int bp = ((jj & 1) * 16 + s * 8 + tig * 2);
                float e00 = ((w0 >> bp) & 1)       ? 0.f : ex2(c[0] * CE) * rinv0;
                float e01 = ((w0 >> (bp + 1)) & 1) ? 0.f : ex2(c[1] * CE) * rinv0;
                float e10 = ((w1 >> bp) & 1)       ? 0.f : ex2(c[2] * CE) * rinv1;
                float e11 = ((w1 >> (bp + 1)) & 1) ? 0.f : ex2(c[3] * CE) * rinv1;
                *(float2*)(attn + arow0 + jgl) = make_float2(e00, e01);
                *(float2*)(attn + arow1 + jgl) = make_float2(e10, e11);
                eh[s][0] = pack_bf16x2(e00, e01);
                eh[s][1] = pack_bf16x2(e10, e11);
            }
            const int c0 = jj * 16 + tig * 2;
#pragma unroll
            for (int nt2 = 0; nt2 < 4; nt2++) {
                int v0 = nt2 * 8;
                uint32_t vb0 = *(const uint32_t*)&vh[(v0 + g) * ESTR + c0];
                uint32_t vb1 = *(const uint32_t*)&vh[(v0 + g) * ESTR + c0 + 8];
                mma16816(cacc[nt2], eh[0][0], eh[0][1], eh[1][0], eh[1][1], vb0, vb1);
            }
        }
    }

    // ---- ctx write as bf16 hi/lo ----
    {
        size_t row0 = (bS + q0 + qb + g) * (size_t)DM + h * 32;
        size_t row1 = row0 + 8 * DM;
#pragma unroll
        for (int nt = 0; nt < 4; nt++) {
            int v = nt * 8 + tig * 2;
#pragma unroll
            for (int rr = 0; rr < 2; rr++) {
                float f0 = cacc[nt][rr * 2], f1 = cacc[nt][rr * 2 + 1];
                uint32_t h0 = bf16_rn_bits(f0), h1 = bf16_rn_bits(f1);
                float l0 = f0 - __uint_as_float(h0 << 16);
                float l1 = f1 - __uint_as_float(h1 << 16);
                size_t off = (rr ? row1 : row0) + v;
                *(uint32_t*)&g_Ch[off] = h0 | (h1 << 16);
                *(uint32_t*)&g_Cl[off] = bf16_rn_bits(l0) | (bf16_rn_bits(l1) << 16);
            }
        }
    }
}

// ---------------------------------------------------------------------------
// K4: out = LayerNorm(ctx @ W_fc + g_R), tensor-core (unchanged from R13).
// ---------------------------------------------------------------------------
__global__ __launch_bounds__(256) void out_ln_tc(const float* __restrict__ gamma,
                                                 const float* __restrict__ beta,
                                                 float* __restrict__ out)
{
    extern __shared__ __nv_bfloat16 psm[];
    __nv_bfloat16* sAh  = psm + PA_H;
    __nv_bfloat16* sAl  = psm + PA_L;
    __nv_bfloat16* sWth = psm + PW_H;
    __nv_bfloat16* sWtl = psm + PW_L;

    const int tid  = threadIdx.x;
    const int w    = tid >> 5;
    const int lane = tid & 31;
    const int g    = lane >> 2;
    const int tig  = lane & 3;
    const int r0   = blockIdx.x * 64;

    const __nv_bfloat16* gWh = g_Wth + 4 * DM * DM;
    const __nv_bfloat16* gWl = g_Wtl + 4 * DM * DM;

    const int mt = w >> 1;
    const int nh = (w & 1) * 64;
    const int m0 = mt * 16 + g;
    const int m1 = m0 + 8;

    float acc[8][4];
#pragma unroll
    for (int nt = 0; nt < 8; nt++)
#pragma unroll
        for (int i = 0; i < 4; i++) acc[nt][i] = 0.f;

    for (int ks = 0; ks < 2; ks++) {
        if (ks) __syncthreads();
        {
#pragma unroll
            for (int it = 0; it < 2; it++) {
                int id = tid + it * 256;
                int row = id >> 3, seg = (id & 7) * 8;
                size_t src = (size_t)(r0 + row) * DM + ks * 64 + seg;
                cp16(sAh + row * PSTR + seg, g_Ch + src);
                cp16(sAl + row * PSTR + seg, g_Cl + src);
            }
#pragma unroll
            for (int it = 0; it < 4; it++) {
                int id = tid + it * 256;
                int n = id >> 3, seg = (id & 7) * 8;
                size_t src = (size_t)n * DM + ks * 64 + seg;
                cp16(sWth + n * PSTR + seg, gWh + src);
                cp16(sWtl + n * PSTR + seg, gWl + src);
            }
        }
        cp_commit();
        cp_wait<0>();
        __syncthreads();

#pragma unroll
        for (int kk = 0; kk < 64; kk += 16) {
            const int dof = kk + tig * 2;
            uint32_t ah0 = *(const uint32_t*)&sAh[m0 * PSTR + dof];
            uint32_t ah1 = *(const uint32_t*)&sAh[m1 * PSTR + dof];
            uint32_t ah2 = *(const uint32_t*)&sAh[m0 * PSTR + dof + 8];
            uint32_t ah3 = *(const uint32_t*)&sAh[m1 * PSTR + dof + 8];
            uint32_t al0 = *(const uint32_t*)&sAl[m0 * PSTR + dof];
            uint32_t al1 = *(const uint32_t*)&sAl[m1 * PSTR + dof];
            uint32_t al2 = *(const uint32_t*)&sAl[m0 * PSTR + dof + 8];
            uint32_t al3 = *(const uint32_t*)&sAl[m1 * PSTR + dof + 8];
#pragma unroll
            for (int nt = 0; nt < 8; nt++) {
                int ncol = nh + nt * 8 + g;
                uint32_t bh0 = *(const uint32_t*)&sWth[ncol * PSTR + dof];
                uint32_t bh1 = *(const uint32_t*)&sWth[ncol * PSTR + dof + 8];
                uint32_t bl0 = *(const uint32_t*)&sWtl[ncol * PSTR + dof];
                uint32_t bl1 = *(const uint32_t*)&sWtl[ncol * PSTR + dof + 8];
                mma16816(acc[nt], ah0, ah1, ah2, ah3, bh0, bh1);
                mma16816(acc[nt], ah0, ah1, ah2, ah3, bl0, bl1);
                mma16816(acc[nt], al0, al1, al2, al3, bh0, bh1);
            }
        }
    }

    const size_t row0 = (size_t)(r0 + m0);
    const size_t row1 = row0 + 8;
    float ps0 = 0.f, pq0 = 0.f, ps1 = 0.f, pq1 = 0.f;
#pragma unroll
    for (int nt = 0; nt < 8; nt++) {
        int col = nh + nt * 8 + tig * 2;
        float2 rv0 = *(const float2*)&g_R[row0 * DM + col];
        float2 rv1 = *(const float2*)&g_R[row1 * DM + col];
        acc[nt][0] += rv0.x; acc[nt][1] += rv0.y;
        acc[nt][2] += rv1.x; acc[nt][3] += rv1.y;
        ps0 += acc[nt][0] + acc[nt][1];
        pq0 += acc[nt][0] * acc[nt][0] + acc[nt][1] * acc[nt][1];
        ps1 += acc[nt][2] + acc[nt][3];
        pq1 += acc[nt][2] * acc[nt][2] + acc[nt][3] * acc[nt][3];
    }

    float* red1 = (float*)psm;
    float* red2 = red1 + 64 * 8;
    float* smu  = red2 + 64 * 8;
    float* srs  = smu + 64;
    __syncthreads();
    const int slot = (w & 1) * 4 + tig;
    red1[m0 * 8 + slot] = ps0;
    red2[m0 * 8 + slot] = pq0;
    red1[m1 * 8 + slot] = ps1;
    red2[m1 * 8 + slot] = pq1;
    __syncthreads();
    if (tid < 64) {
        float s = 0.f, q = 0.f;
#pragma unroll
        for (int j = 0; j < 8; j++) { s += red1[tid * 8 + j]; q += red2[tid * 8 + j]; }
        float mu = s * (1.0f / 128.0f);
        float var = q * (1.0f / 128.0f) - mu * mu;
        smu[tid] = mu;
        srs[tid] = rsqrtf(var + 1e-5f);
    }
    __syncthreads();

    const float mu0 = smu[m0], rs0 = srs[m0];
    const float mu1 = smu[m1], rs1 = srs[m1];
#pragma unroll
    for (int nt = 0; nt < 8; nt++) {
        int col = nh + nt * 8 + tig * 2;
        float2 gm = *(const float2*)&gamma[col];
        float2 bt = *(const float2*)&beta[col];
        float2 o0 = make_float2((acc[nt][0] - mu0) * rs0 * gm.x + bt.x,
                                (acc[nt][1] - mu0) * rs0 * gm.y + bt.y);
        float2 o1 = make_float2((acc[nt][2] - mu1) * rs1 * gm.x + bt.x,
                                (acc[nt][3] - mu1) * rs1 * gm.y + bt.y);
        *(float2*)&out[row0 * DM + col] = o0;
        *(float2*)&out[row1 * DM + col] = o1;
    }
}

// ---------------------------------------------------------------------------
extern "C" void kernel_launch(void* const* d_in, const int* in_sizes, int n_in,
                              void* d_out, int out_size)
{
    const float* inQ  = (const float*)d_in[0];
    const float* inK  = (const float*)d_in[1];
    const float* inV  = (const float*)d_in[2];
    const unsigned char* mask = (const unsigned char*)d_in[3];
    const float* Wfc0 = (const float*)d_in[4];
    const float* WQ   = (const float*)d_in[5];
    const float* WK   = (const float*)d_in[6];
    const float* WV   = (const float*)d_in[7];
    const float* Wfc  = (const float*)d_in[8];
    const float* gam  = (const float*)d_in[9];
    const float* bet  = (const float*)d_in[10];
    float* out  = (float*)d_out;
    float* attn = out + OUT_ELEMS;

    detect_mask<<<1, 256>>>(mask);                                  // 1
    pack_mask<<<(unsigned)((size_t)BATCH * SEQ * SW / 256), 256>>>(mask);  // 2
    split_inputs<<<dim3(NR * DM / 1024, 3), 256>>>(inQ, inK, inV);  // 3
    split_weights<<<5, 256>>>(Wfc0, WQ, WK, WV, Wfc);               // 4

    cudaFuncSetAttribute(proj_tc, cudaFuncAttributeMaxDynamicSharedMemorySize,
                         (int)P_SMEM_BYTES);
    proj_tc<<<dim3(NR / 64, 4), 256, P_SMEM_BYTES>>>();             // 5

    dim3 agrid(SEQ / TQ, BATCH * 4);
    cudaFuncSetAttribute(rowsum_pass, cudaFuncAttributeMaxDynamicSharedMemorySize,
                         (int)RS_SMEM_BYTES);
    rowsum_pass<<<agrid, 256, RS_SMEM_BYTES>>>();                   // 6 (ncu)

    cudaFuncSetAttribute(attn_mma, cudaFuncAttributeMaxDynamicSharedMemorySize,
                         (int)SMEM_BYTES);
    attn_mma<<<agrid, 256, SMEM_BYTES>>>(attn);                     // 7

    cudaFuncSetAttribute(out_ln_tc, cudaFuncAttributeMaxDynamicSharedMemorySize,
                         (int)P_SMEM_BYTES);
    out_ln_tc<<<NR / 64, 256, P_SMEM_BYTES>>>(gam, bet, out);       // 8
}

// round 15
// speedup vs baseline: 1.8201x; 1.0928x over previous
#include <cuda_runtime.h>
#include <cuda_bf16.h>
#include <stdint.h>

// ---------------------------------------------------------------------------
// MultiHeadAttention: out = LN(ctx@W_fc + X@W_fc0), attn materialized.
// B=8, S=2048, D=128, H=4, dk=dv=32.
// Output layout: [out (8*2048*128)] then [attn (8*4*2048*2048)].
// R15: split_weights parallelized (5 blocks -> 40, 64 serial loads -> 1).
// ---------------------------------------------------------------------------

namespace {
constexpr int BATCH = 8;
constexpr int SEQ   = 2048;
constexpr int DM    = 128;
constexpr int NR    = BATCH * SEQ;                 // 16384 rows
constexpr size_t OUT_ELEMS = (size_t)NR * DM;      // 2,097,152
constexpr int TQ = 128;                            // q-tile per block
constexpr int TK = 64;                             // k-chunk
constexpr int NC = SEQ / TK;                       // 32 chunks
constexpr int SW = SEQ / 32;                       // 64 mask words per row

// attn_mma smem (bf16 units) + mask word region
constexpr int QSTR = 40;
constexpr int ESTR = 72;
constexpr int BUF_SZ  = 64 * QSTR * 2 + 32 * ESTR;     // 7424 bf16
constexpr int SMEM_BF16 = 3 * BUF_SZ;                  // 22272
constexpr size_t MW_BYTES = 3 * 128 * 2 * 4;           // 3072 B
constexpr size_t SMEM_BYTES = (size_t)SMEM_BF16 * 2 + MW_BYTES;  // 47,616 B

// rowsum_pass smem
constexpr int KBUF = 64 * QSTR;                        // 2560 bf16
constexpr size_t RS_SMEM_BYTES = (size_t)(3 * KBUF) * 2 + MW_BYTES;  // 18,432 B

// proj_tc / out_ln_tc smem
constexpr int PSTR = 72;
constexpr int PA_H = 0;
constexpr int PA_L = PA_H + 64 * PSTR;
constexpr int PW_H = PA_L + 64 * PSTR;
constexpr int PW_L = PW_H + 128 * PSTR;
constexpr int P_BF16 = PW_L + 128 * PSTR;
constexpr size_t P_SMEM_BYTES = (size_t)P_BF16 * 2;    // 55,296 B
constexpr int VSTR = 136;
}

// Scratch (device globals: allocation-free rule)
__device__ float g_R  [NR * DM];
__device__ float g_rinv[BATCH * 4 * SEQ];
__device__ uint32_t g_mbits[(size_t)BATCH * SEQ * SW];   // 4 MB bit mask
__device__ __nv_bfloat16 g_Xh[3 * NR * DM];
__device__ __nv_bfloat16 g_Xl[3 * NR * DM];
__device__ __nv_bfloat16 g_Wth[5 * DM * DM];
__device__ __nv_bfloat16 g_Wtl[5 * DM * DM];
__device__ __nv_bfloat16 g_Qh[NR * DM];
__device__ __nv_bfloat16 g_Ql[NR * DM];
__device__ __nv_bfloat16 g_Kh[NR * DM];
__device__ __nv_bfloat16 g_Kl[NR * DM];
__device__ __nv_bfloat16 g_Ch[NR * DM];
__device__ __nv_bfloat16 g_Cl[NR * DM];
__device__ __nv_bfloat16 g_Vt[(size_t)BATCH * 4 * 32 * SEQ];  // [bh][v][s]
__device__ int   g_mask_mode;   // 0=uint8, 1=int32, 2=float32

// ---------------------------------------------------------------------------
__device__ __forceinline__ float ex2(float y)
{
    float r;
    asm("ex2.approx.f32 %0, %1;" : "=f"(r) : "f"(y));
    return r;
}

__device__ __forceinline__ uint32_t pack_bf16x2(float lo, float hi)
{
    uint32_t r;
    asm("cvt.rn.bf16x2.f32 %0, %1, %2;" : "=r"(r) : "f"(hi), "f"(lo));
    return r;
}

__device__ __forceinline__ uint32_t bf16_rn_bits(float x)
{
    uint32_t b = __float_as_uint(x);
    return (b + 0x7fffu + ((b >> 16) & 1u)) >> 16;
}

__device__ __forceinline__ void mma16816(float c[4],
                                         uint32_t a0, uint32_t a1, uint32_t a2, uint32_t a3,
                                         uint32_t b0, uint32_t b1)
{
    asm volatile("mma.sync.aligned.m16n8k16.row.col.f32.bf16.bf16.f32 "
                 "{%0,%1,%2,%3}, {%4,%5,%6,%7}, {%8,%9}, {%0,%1,%2,%3};"
                 : "+f"(c[0]), "+f"(c[1]), "+f"(c[2]), "+f"(c[3])
                 : "r"(a0), "r"(a1), "r"(a2), "r"(a3), "r"(b0), "r"(b1));
}

__device__ __forceinline__ void cp16(const __nv_bfloat16* smem_dst, const void* gsrc)
{
    uint32_t d = (uint32_t)__cvta_generic_to_shared(smem_dst);
    asm volatile("cp.async.cg.shared.global [%0], [%1], 16;" :: "r"(d), "l"(gsrc));
}
__device__ __forceinline__ void cp8(const void* smem_dst, const void* gsrc)
{
    uint32_t d = (uint32_t)__cvta_generic_to_shared(smem_dst);
    asm volatile("cp.async.ca.shared.global [%0], [%1], 8;" :: "r"(d), "l"(gsrc));
}
__device__ __forceinline__ void cp_commit()
{
    asm volatile("cp.async.commit_group;");
}
template <int N>
__device__ __forceinline__ void cp_wait()
{
    asm volatile("cp.async.wait_group %0;" :: "n"(N));
}

// ---------------------------------------------------------------------------
// K0: detect mask dtype.
// ---------------------------------------------------------------------------
__global__ void detect_mask(const unsigned char* __restrict__ m)
{
    __shared__ int s_gt1, s_off;
    if (threadIdx.x == 0) { s_gt1 = 0; s_off = 0; }
    __syncthreads();
    int gt1 = 0, off = 0;
    for (int i = threadIdx.x; i < 4096; i += 256) {
        unsigned char v = m[i];
        if (v > 1) gt1 = 1;
        else if (v == 1 && (i & 3) != 0) off = 1;
    }
    if (gt1) atomicOr(&s_gt1, 1);
    if (off) atomicOr(&s_off, 1);
    __syncthreads();
    if (threadIdx.x == 0)
        g_mask_mode = s_gt1 ? 2 : (s_off ? 0 : 1);
}

// ---------------------------------------------------------------------------
// K0b: pack mask -> bits. One output word (32 flags) per thread.
// ---------------------------------------------------------------------------
__global__ __launch_bounds__(256) void pack_mask(const unsigned char* __restrict__ mask)
{
    const int mode = g_mask_mode;
    size_t wi = (size_t)blockIdx.x * 256 + threadIdx.x;
    uint32_t bits = 0;
    if (mode == 0) {
        const uint4* p = (const uint4*)(mask + wi * 32);
        uint4 a = p[0], b = p[1];
        const uint32_t wa[8] = {a.x, a.y, a.z, a.w, b.x, b.y, b.z, b.w};
#pragma unroll
        for (int q = 0; q < 8; q++) {
            uint32_t v = wa[q];
#pragma unroll
            for (int t = 0; t < 4; t++)
                bits |= (((v >> (t * 8)) & 0xffu) ? 1u : 0u) << (q * 4 + t);
        }
    } else if (mode == 1) {
        const uint4* p = (const uint4*)((const uint32_t*)mask + wi * 32);
#pragma unroll
        for (int q = 0; q < 8; q++) {
            uint4 v = p[q];
            bits |= (v.x ? 1u : 0u) << (q * 4);
            bits |= (v.y ? 1u : 0u) << (q * 4 + 1);
            bits |= (v.z ? 1u : 0u) << (q * 4 + 2);
            bits |= (v.w ? 1u : 0u) << (q * 4 + 3);
        }
    } else {
        const float4* p = (const float4*)((const float*)mask + wi * 32);
#pragma unroll
        for (int q = 0; q < 8; q++) {
            float4 v = p[q];
            bits |= (v.x != 0.f ? 1u : 0u) << (q * 4);
            bits |= (v.y != 0.f ? 1u : 0u) << (q * 4 + 1);
            bits |= (v.z != 0.f ? 1u : 0u) << (q * 4 + 2);
            bits |= (v.w != 0.f ? 1u : 0u) << (q * 4 + 3);
        }
    }
    g_mbits[wi] = bits;
}

// ---------------------------------------------------------------------------
// P0: split inputs fp32 -> bf16 hi/lo.
// ---------------------------------------------------------------------------
__global__ __launch_bounds__(256) void split_inputs(const float* __restrict__ inQ,
                                                    const float* __restrict__ inK,
                                                    const float* __restrict__ inV)
{
    const float* src = (blockIdx.y == 0) ? inQ : (blockIdx.y == 1) ? inK : inV;
    __nv_bfloat16* H = g_Xh + (size_t)blockIdx.y * NR * DM;
    __nv_bfloat16* L = g_Xl + (size_t)blockIdx.y * NR * DM;
    size_t i = ((size_t)blockIdx.x * 256 + threadIdx.x) * 4;
    float4 v = *(const float4*)&src[i];
    uint32_t hx = bf16_rn_bits(v.x), hy = bf16_rn_bits(v.y);
    uint32_t hz = bf16_rn_bits(v.z), hw = bf16_rn_bits(v.w);
    float lx = v.x - __uint_as_float(hx << 16);
    float ly = v.y - __uint_as_float(hy << 16);
    float lz = v.z - __uint_as_float(hz << 16);
    float lw = v.w - __uint_as_float(hw << 16);
    *(uint2*)&H[i] = make_uint2(hx | (hy << 16), hz | (hw << 16));
    *(uint2*)&L[i] = make_uint2(bf16_rn_bits(lx) | (bf16_rn_bits(ly) << 16),
                                bf16_rn_bits(lz) | (bf16_rn_bits(lw) << 16));
}

// ---------------------------------------------------------------------------
// P1: split + transpose weights. grid (8, 5): 40 blocks, 8 weights/thread
// via two float4 loads — no loop-carried latency chain.
// ---------------------------------------------------------------------------
__global__ __launch_bounds__(256) void split_weights(const float* __restrict__ Wfc0,
                                                     const float* __restrict__ WQ,
                                                     const float* __restrict__ WK,
                                                     const float* __restrict__ WV,
                                                     const float* __restrict__ Wfc)
{
    const float* W;
    switch (blockIdx.y) {
        case 0:  W = Wfc0; break;
        case 1:  W = WQ;   break;
        case 2:  W = WK;   break;
        case 3:  W = WV;   break;
        default: W = Wfc;  break;
    }
    __nv_bfloat16* H = g_Wth + blockIdx.y * DM * DM;
    __nv_bfloat16* L = g_Wtl + blockIdx.y * DM * DM;
    int base = (blockIdx.x * 256 + threadIdx.x) * 8;   // element index (k*128+n)
    int k = base >> 7, n = base & 127;                 // 8 consecutive n, same k
    float4 v0 = *(const float4*)&W[base];
    float4 v1 = *(const float4*)&W[base + 4];
    const float vs[8] = {v0.x, v0.y, v0.z, v0.w, v1.x, v1.y, v1.z, v1.w};
#pragma unroll
    for (int t = 0; t < 8; t++) {
        float x = vs[t];
        uint32_t hb = bf16_rn_bits(x);
        float lf = x - __uint_as_float(hb << 16);
        ((uint16_t*)H)[(n + t) * DM + k] = (uint16_t)hb;
        ((uint16_t*)L)[(n + t) * DM + k] = (uint16_t)bf16_rn_bits(lf);
    }
}

// ---------------------------------------------------------------------------
// P2: tensor-core projections (unchanged).
// ---------------------------------------------------------------------------
__global__ __launch_bounds__(256, 4) void proj_tc()
{
    extern __shared__ __nv_bfloat16 psm[];
    __nv_bfloat16* sAh  = psm + PA_H;
    __nv_bfloat16* sAl  = psm + PA_L;
    __nv_bfloat16* sWth = psm + PW_H;
    __nv_bfloat16* sWtl = psm + PW_L;

    const int tid  = threadIdx.x;
    const int w    = tid >> 5;
    const int lane = tid & 31;
    const int g    = lane >> 2;
    const int tig  = lane & 3;
    const int gm   = blockIdx.y;
    const int r0   = blockIdx.x * 64;

    const int xsel = (gm <= 1) ? 0 : (gm - 1);
    const __nv_bfloat16* gXh = g_Xh + (size_t)xsel * NR * DM;
    const __nv_bfloat16* gXl = g_Xl + (size_t)xsel * NR * DM;
    const __nv_bfloat16* gWh = g_Wth + gm * DM * DM;
    const __nv_bfloat16* gWl = g_Wtl + gm * DM * DM;

    const int mt = w >> 1;
    const int nh = (w & 1) * 64;
    const int m0 = mt * 16 + g;
    const int m1 = m0 + 8;

    float acc[8][4];
#pragma unroll
    for (int nt = 0; nt < 8; nt++)
#pragma unroll
        for (int i = 0; i < 4; i++) acc[nt][i] = 0.f;

    for (int ks = 0; ks < 2; ks++) {
        if (ks) __syncthreads();
        {
#pragma unroll
            for (int it = 0; it < 2; it++) {
                int id = tid + it * 256;
                int row = id >> 3, seg = (id & 7) * 8;
                size_t src = (size_t)(r0 + row) * DM + ks * 64 + seg;
                cp16(sAh + row * PSTR + seg, gXh + src);
                cp16(sAl + row * PSTR + seg, gXl + src);
            }
#pragma unroll
            for (int it = 0; it < 4; it++) {
                int id = tid + it * 256;
                int n = id >> 3, seg = (id & 7) * 8;
                size_t src = (size_t)n * DM + ks * 64 + seg;
                cp16(sWth + n * PSTR + seg, gWh + src);
                cp16(sWtl + n * PSTR + seg, gWl + src);
            }
        }
        cp_commit();
        cp_wait<0>();
        __syncthreads();

#pragma unroll
        for (int kk = 0; kk < 64; kk += 16) {
            const int dof = kk + tig * 2;
            uint32_t ah0 = *(const uint32_t*)&sAh[m0 * PSTR + dof];
            uint32_t ah1 = *(const uint32_t*)&sAh[m1 * PSTR + dof];
            uint32_t ah2 = *(const uint32_t*)&sAh[m0 * PSTR + dof + 8];
            uint32_t ah3 = *(const uint32_t*)&sAh[m1 * PSTR + dof + 8];
            uint32_t al0 = *(const uint32_t*)&sAl[m0 * PSTR + dof];
            uint32_t al1 = *(const uint32_t*)&sAl[m1 * PSTR + dof];
            uint32_t al2 = *(const uint32_t*)&sAl[m0 * PSTR + dof + 8];
            uint32_t al3 = *(const uint32_t*)&sAl[m1 * PSTR + dof + 8];
#pragma unroll
            for (int nt = 0; nt < 8; nt++) {
                int ncol = nh + nt * 8 + g;
                uint32_t bh0 = *(const uint32_t*)&sWth[ncol * PSTR + dof];
                uint32_t bh1 = *(const uint32_t*)&sWth[ncol * PSTR + dof + 8];
                uint32_t bl0 = *(const uint32_t*)&sWtl[ncol * PSTR + dof];
                uint32_t bl1 = *(const uint32_t*)&sWtl[ncol * PSTR + dof + 8];
                mma16816(acc[nt], ah0, ah1, ah2, ah3, bh0, bh1);
                mma16816(acc[nt], ah0, ah1, ah2, ah3, bl0, bl1);
                mma16816(acc[nt], al0, al1, al2, al3, bh0, bh1);
            }
        }
    }

    const size_t row0 = (size_t)(r0 + m0);
    const size_t row1 = row0 + 8;

    if (gm == 0) {
#pragma unroll
        for (int nt = 0; nt < 8; nt++) {
            int col = nh + nt * 8 + tig * 2;
            *(float2*)&g_R[row0 * DM + col] = make_float2(acc[nt][0], acc[nt][1]);
            *(float2*)&g_R[row1 * DM + col] = make_float2(acc[nt][2], acc[nt][3]);
        }
    } else if (gm == 1 || gm == 2) {
        __nv_bfloat16* H = (gm == 1) ? g_Qh : g_Kh;
        __nv_bfloat16* L = (gm == 1) ? g_Ql : g_Kl;
#pragma unroll
        for (int nt = 0; nt < 8; nt++) {
            int col = nh + nt * 8 + tig * 2;
#pragma unroll
            for (int rr = 0; rr < 2; rr++) {
                float f0 = acc[nt][rr * 2], f1 = acc[nt][rr * 2 + 1];
                uint32_t h0 = bf16_rn_bits(f0), h1 = bf16_rn_bits(f1);
                float l0 = f0 - __uint_as_float(h0 << 16);
                float l1 = f1 - __uint_as_float(h1 << 16);
                size_t off = (rr ? row1 : row0) * DM + col;
                *(uint32_t*)&H[off] = h0 | (h1 << 16);
                *(uint32_t*)&L[off] = bf16_rn_bits(l0) | (bf16_rn_bits(l1) << 16);
            }
        }
    } else {
        uint16_t* sV = (uint16_t*)(psm + PW_H);
        __syncthreads();
#pragma unroll
        for (int nt = 0; nt < 8; nt++) {
            int col = nh + nt * 8 + tig * 2;
            *(uint32_t*)&sV[m0 * VSTR + col] =
                bf16_rn_bits(acc[nt][0]) | (bf16_rn_bits(acc[nt][1]) << 16);
            *(uint32_t*)&sV[m1 * VSTR + col] =
                bf16_rn_bits(acc[nt][2]) | (bf16_rn_bits(acc[nt][3]) << 16);
        }
        __syncthreads();
        const int v   = tid >> 3;
        const int seg = (tid & 7) * 8;
        const int b   = r0 / SEQ;
        const int sblock = r0 % SEQ;
#pragma unroll
        for (int hd = 0; hd < 4; hd++) {
            uint32_t wv[4];
#pragma unroll
            for (int p = 0; p < 4; p++) {
                uint32_t lo = sV[(seg + p * 2) * VSTR + hd * 32 + v];
                uint32_t hi = sV[(seg + p * 2 + 1) * VSTR + hd * 32 + v];
                wv[p] = lo | (hi << 16);
            }
            size_t off = ((size_t)(b * 4 + hd) * 32 + v) * SEQ + sblock + seg;
            *(uint4*)&g_Vt[off] = make_uint4(wv[0], wv[1], wv[2], wv[3]);
        }
    }
}

// ---------------------------------------------------------------------------
// K1.5: rowsum pre-pass, 2-product scores, bit-mask from smem pipeline.
// ---------------------------------------------------------------------------
__global__ __launch_bounds__(256, 4) void rowsum_pass()
{
    extern __shared__ __nv_bfloat16 smb[];
    uint32_t* mw = (uint32_t*)(smb + 3 * KBUF);   // [3][128][2] words
    __shared__ float srow[128];

    const int tid  = threadIdx.x;
    const int w    = tid >> 5;
    const int lane = tid & 31;
    const int g    = lane >> 2;
    const int tig  = lane & 3;
    const int qb   = w * 16;

    const int bh = blockIdx.y;
    const int b = bh >> 2, h = bh & 3;
    const int q0 = blockIdx.x * TQ;
    const float CE = 1.4426950408889634f * 0.17677669529663689f;
    const size_t bS = (size_t)b * SEQ;

    const int kj   = tid >> 2;
    const int kseg = (tid & 3) * 8;
    const __nv_bfloat16* gK_h = g_Kh + bS * DM + h * 32;
    const uint32_t* gMB = g_mbits + (bS + q0) * SW;

    auto issue_chunk = [&](int kc) {
        cp16(smb + (kc % 3) * KBUF + kj * QSTR + kseg,
             gK_h + (size_t)(kc * TK + kj) * DM + kseg);
        if (tid < 128)
            cp8(mw + (kc % 3) * 256 + tid * 2, gMB + (size_t)tid * SW + kc * 2);
    };
    issue_chunk(0);
    cp_commit();
    issue_chunk(1);
    cp_commit();

    uint32_t qh[2][4], ql[2][4];
    {
        const __nv_bfloat16* gQ_h = g_Qh + (bS + q0) * DM + h * 32;
        const __nv_bfloat16* gQ_l = g_Ql + (bS + q0) * DM + h * 32;
#pragma unroll
        for (int kk = 0; kk < 2; kk++) {
            int c0 = kk * 16 + tig * 2;
            size_t r0o = (size_t)(qb + g) * DM + c0;
            size_t r1o = (size_t)(qb + g + 8) * DM + c0;
            qh[kk][0] = *(const uint32_t*)&gQ_h[r0o];
            qh[kk][1] = *(const uint32_t*)&gQ_h[r1o];
            qh[kk][2] = *(const uint32_t*)&gQ_h[r0o + 8];
            qh[kk][3] = *(const uint32_t*)&gQ_h[r1o + 8];
            ql[kk][0] = *(const uint32_t*)&gQ_l[r0o];
            ql[kk][1] = *(const uint32_t*)&gQ_l[r1o];
            ql[kk][2] = *(const uint32_t*)&gQ_l[r0o + 8];
            ql[kk][3] = *(const uint32_t*)&gQ_l[r1o + 8];
        }
    }

    float rs0 = 0.f, rs1 = 0.f;

    for (int kc = 0; kc < NC; kc++) {
        cp_wait<1>();
        __syncthreads();
        if (kc + 2 < NC) issue_chunk(kc + 2);
        cp_commit();

        const __nv_bfloat16* kh = smb + (kc % 3) * KBUF;
        const uint2 mw0 = *(const uint2*)&mw[(kc % 3) * 256 + (qb + g) * 2];
        const uint2 mw1 = *(const uint2*)&mw[(kc % 3) * 256 + (qb + g + 8) * 2];

#pragma unroll
        for (int jj = 0; jj < 4; jj++) {
            const uint32_t w0 = (jj < 2) ? mw0.x : mw0.y;
            const uint32_t w1 = (jj < 2) ? mw1.x : mw1.y;
#pragma unroll
            for (int s = 0; s < 2; s++) {
                const int j0 = jj * 16 + s * 8;
                float c[4]  = {0.f, 0.f, 0.f, 0.f};
                float c2[4] = {0.f, 0.f, 0.f, 0.f};
                {
                    const int dof0 = tig * 2;
                    uint32_t bh0 = *(const uint32_t*)&kh[(j0 + g) * QSTR + dof0];
                    uint32_t bh1 = *(const uint32_t*)&kh[(j0 + g) * QSTR + dof0 + 8];
                    mma16816(c, qh[0][0], qh[0][1], qh[0][2], qh[0][3], bh0, bh1);
                    mma16816(c, ql[0][0], ql[0][1], ql[0][2], ql[0][3], bh0, bh1);
                }
                {
                    const int dof1 = 16 + tig * 2;
                    uint32_t bh0 = *(const uint32_t*)&kh[(j0 + g) * QSTR + dof1];
                    uint32_t bh1 = *(const uint32_t*)&kh[(j0 + g) * QSTR + dof1 + 8];
                    mma16816(c2, qh[1][0], qh[1][1], qh[1][2], qh[1][3], bh0, bh1);
                    mma16816(c2, ql[1][0], ql[1][1], ql[1][2], ql[1][3], bh0, bh1);
                }
#pragma unroll
                for (int i = 0; i < 4; i++) c[i] += c2[i];
                const int bp = ((jj & 1) * 16 + s * 8 + tig * 2);
                rs0 += (((w0 >> bp) & 1) ? 0.f : ex2(c[0] * CE))
                     + (((w0 >> (bp + 1)) & 1) ? 0.f : ex2(c[1] * CE));
                rs1 += (((w1 >> bp) & 1) ? 0.f : ex2(c[2] * CE))
                     + (((w1 >> (bp + 1)) & 1) ? 0.f : ex2(c[3] * CE));
            }
        }
    }

    rs0 += __shfl_xor_sync(0xffffffff, rs0, 1);
    rs0 += __shfl_xor_sync(0xffffffff, rs0, 2);
    rs1 += __shfl_xor_sync(0xffffffff, rs1, 1);
    rs1 += __shfl_xor_sync(0xffffffff, rs1, 2);
    __syncthreads();
    if (tig == 0) {
        srow[qb + g]     = rs0;
        srow[qb + g + 8] = rs1;
    }
    __syncthreads();
    if (tid < 128)
        g_rinv[(size_t)bh * SEQ + q0 + tid] = 1.0f / srow[tid];
}

// ---------------------------------------------------------------------------
// K2: tensor-core attention; attn written NORMALIZED; bit-mask via smem.
// ---------------------------------------------------------------------------
__global__ __launch_bounds__(256, 4) void attn_mma(float* __restrict__ attn)
{
    extern __shared__ __nv_bfloat16 smb[];
    uint32_t* mw = (uint32_t*)(smb + SMEM_BF16);   // [3][128][2] words

    const int tid  = threadIdx.x;
    const int w    = tid >> 5;
    const int lane = tid & 31;
    const int g    = lane >> 2;
    const int tig  = lane & 3;
    const int qb   = w * 16;

    const int bh = blockIdx.y;
    const int b = bh >> 2, h = bh & 3;
    const int q0 = blockIdx.x * TQ;
    const float CE = 1.4426950408889634f * 0.17677669529663689f;
    const size_t bS = (size_t)b * SEQ;

    const int kj   = tid >> 2;
    const int kseg = (tid & 3) * 8;
    const int vv   = tid >> 3;
    const int vseg = (tid & 7) * 8;
    const __nv_bfloat16* gK_h = g_Kh + bS * DM + h * 32;
    const __nv_bfloat16* gK_l = g_Kl + bS * DM + h * 32;
    const __nv_bfloat16* gV_t = g_Vt + ((size_t)bh * 32 + vv) * SEQ;
    const uint32_t* gMB = g_mbits + (bS + q0) * SW;

    auto issue_chunk = [&](int kc) {
        __nv_bfloat16* kh = smb + (kc % 3) * BUF_SZ;
        __nv_bfloat16* kl = kh + 64 * QSTR;
        __nv_bfloat16* vh = kl + 64 * QSTR;
        size_t koff = (size_t)(kc * TK + kj) * DM + kseg;
        cp16(kh + kj * QSTR + kseg, gK_h + koff);
        cp16(kl + kj * QSTR + kseg, gK_l + koff);
        cp16(vh + vv * ESTR + vseg, gV_t + kc * TK + vseg);
        if (tid < 128)
            cp8(mw + (kc % 3) * 256 + tid * 2, gMB + (size_t)tid * SW + kc * 2);
    };

    issue_chunk(0);
    cp_commit();
    issue_chunk(1);
    cp_commit();

    uint32_t qh[2][4], ql[2][4];
    {
        const __nv_bfloat16* gQ_h = g_Qh + (bS + q0) * DM + h * 32;
        const __nv_bfloat16* gQ_l = g_Ql + (bS + q0) * DM + h * 32;
#pragma unroll
        for (int kk = 0; kk < 2; kk++) {
            int c0 = kk * 16 + tig * 2;
            size_t r0o = (size_t)(qb + g) * DM + c0;
            size_t r1o = (size_t)(qb + g + 8) * DM + c0;
            qh[kk][0] = *(const uint32_t*)&gQ_h[r0o];
            qh[kk][1] = *(const uint32_t*)&gQ_h[r1o];
            qh[kk][2] = *(const uint32_t*)&gQ_h[r0o + 8];
            qh[kk][3] = *(const uint32_t*)&gQ_h[r1o + 8];
            ql[kk][0] = *(const uint32_t*)&gQ_l[r0o];
            ql[kk][1] = *(const uint32_t*)&gQ_l[r1o];
            ql[kk][2] = *(const uint32_t*)&gQ_l[r0o + 8];
            ql[kk][3] = *(const uint32_t*)&gQ_l[r1o + 8];
        }
    }

    const int qg0 = q0 + qb + g;
    const float rinv0 = g_rinv[(size_t)bh * SEQ + qg0];
    const float rinv1 = g_rinv[(size_t)bh * SEQ + qg0 + 8];

    float cacc[4][4];
#pragma unroll
    for (int n = 0; n < 4; n++)
#pragma unroll
        for (int i = 0; i < 4; i++) cacc[n][i] = 0.f;

    const size_t arow0 = ((size_t)bh * SEQ + qg0) * SEQ;
    const size_t arow1 = arow0 + 8 * SEQ;

    for (int kc = 0; kc < NC; kc++) {
        const int k0 = kc * TK;

        cp_wait<1>();
        __syncthreads();
        if (kc + 2 < NC) issue_chunk(kc + 2);
        cp_commit();

        const __nv_bfloat16* kh = smb + (kc % 3) * BUF_SZ;
        const __nv_bfloat16* kl = kh + 64 * QSTR;
        const __nv_bfloat16* vh = kl + 64 * QSTR;
        const uint2 mw0 = *(const uint2*)&mw[(kc % 3) * 256 + (qb + g) * 2];
        const uint2 mw1 = *(const uint2*)&mw[(kc % 3) * 256 + (qb + g + 8) * 2];

#pragma unroll
        for (int jj = 0; jj < 4; jj++) {
            const uint32_t w0 = (jj < 2) ? mw0.x : mw0.y;
            const uint32_t w1 = (jj < 2) ? mw1.x : mw1.y;

            uint32_t eh[2][2];
#pragma unroll
            for (int s = 0; s < 2; s++) {
                const int j0 = jj * 16 + s * 8;
                float c[4]  = {0.f, 0.f, 0.f, 0.f};
                float c2[4] = {0.f, 0.f, 0.f, 0.f};
                {
                    const int dof0 = tig * 2;
                    uint32_t bh0 = *(const uint32_t*)&kh[(j0 + g) * QSTR + dof0];
                    uint32_t bh1 = *(const uint32_t*)&kh[(j0 + g) * QSTR + dof0 + 8];
                    uint32_t bl0 = *(const uint32_t*)&kl[(j0 + g) * QSTR + dof0];
                    uint32_t bl1 = *(const uint32_t*)&kl[(j0 + g) * QSTR + dof0 + 8];
                    mma16816(c, qh[0][0], qh[0][1], qh[0][2], qh[0][3], bh0, bh1);
                    mma16816(c, qh[0][0], qh[0][1], qh[0][2], qh[0][3], bl0, bl1);
                    mma16816(c, ql[0][0], ql[0][1], ql[0][2], ql[0][3], bh0, bh1);
                }
                {
                    const int dof1 = 16 + tig * 2;
                    uint32_t bh0 = *(const uint32_t*)&kh[(j0 + g) * QSTR + dof1];
                    uint32_t bh1 = *(const uint32_t*)&kh[(j0 + g) * QSTR + dof1 + 8];
                    uint32_t bl0 = *(const uint32_t*)&kl[(j0 + g) * QSTR + dof1];
                    uint32_t bl1 = *(const uint32_t*)&kl[(j0 + g) * QSTR + dof1 + 8];
                    mma16816(c2, qh[1][0], qh[1][1], qh[1][2], qh[1][3], bh0, bh1);
                    mma16816(c2, qh[1][0], qh[1][1], qh[1][2], qh[1][3], bl0, bl1);
                    mma16816(c2, ql[1][0], ql[1][1], ql[1][2], ql[1][3], bh0, bh1);
                }
#pragma unroll
                for (int i = 0; i < 4; i++) c[i] += c2[i];

                const int jgl = k0 + j0 + tig * 2;
                const int bp = ((jj & 1) * 16 + s * 8 + tig * 2);
                float e00 = ((w0 >> bp) & 1)       ? 0.f : ex2(c[0] * CE) * rinv0;
                float e01 = ((w0 >> (bp + 1)) & 1) ? 0.f : ex2(c[1] * CE) * rinv0;
                float e10 = ((w1 >> bp) & 1)       ? 0.f : ex2(c[2] * CE) * rinv1;
                float e11 = ((w1 >> (bp + 1)) & 1) ? 0.f : ex2(c[3] * CE) * rinv1;
                *(float2*)(attn + arow0 + jgl) = make_float2(e00, e01);
                *(float2*)(attn + arow1 + jgl) = make_float2(e10, e11);
                eh[s][0] = pack_bf16x2(e00, e01);
                eh[s][1] = pack_bf16x2(e10, e11);
            }
            const int c0 = jj * 16 + tig * 2;
#pragma unroll
            for (int nt2 = 0; nt2 < 4; nt2++) {
                int v0 = nt2 * 8;
                uint32_t vb0 = *(const uint32_t*)&vh[(v0 + g) * ESTR + c0];
                uint32_t vb1 = *(const uint32_t*)&vh[(v0 + g) * ESTR + c0 + 8];
                mma16816(cacc[nt2], eh[0][0], eh[0][1], eh[1][0], eh[1][1], vb0, vb1);
            }
        }
    }

    // ---- ctx write as bf16 hi/lo ----
    {
        size_t row0 = (bS + q0 + qb + g) * (size_t)DM + h * 32;
        size_t row1 = row0 + 8 * DM;
#pragma unroll
        for (int nt = 0; nt < 4; nt++) {
            int v = nt * 8 + tig * 2;
#pragma unroll
            for (int rr = 0; rr < 2; rr++) {
                float f0 = cacc[nt][rr * 2], f1 = cacc[nt][rr * 2 + 1];
                uint32_t h0 = bf16_rn_bits(f0), h1 = bf16_rn_bits(f1);
                float l0 = f0 - __uint_as_float(h0 << 16);
                float l1 = f1 - __uint_as_float(h1 << 16);
                size_t off = (rr ? row1 : row0) + v;
                *(uint32_t*)&g_Ch[off] = h0 | (h1 << 16);
                *(uint32_t*)&g_Cl[off] = bf16_rn_bits(l0) | (bf16_rn_bits(l1) << 16);
            }
        }
    }
}

// ---------------------------------------------------------------------------
// K4: out = LayerNorm(ctx @ W_fc + g_R), tensor-core.
// ---------------------------------------------------------------------------
__global__ __launch_bounds__(256) void out_ln_tc(const float* __restrict__ gamma,
                                                 const float* __restrict__ beta,
                                                 float* __restrict__ out)
{
    extern __shared__ __nv_bfloat16 psm[];
    __nv_bfloat16* sAh  = psm + PA_H;
    __nv_bfloat16* sAl  = psm + PA_L;
    __nv_bfloat16* sWth = psm + PW_H;
    __nv_bfloat16* sWtl = psm + PW_L;

    const int tid  = threadIdx.x;
    const int w    = tid >> 5;
    const int lane = tid & 31;
    const int g    = lane >> 2;
    const int tig  = lane & 3;
    const int r0   = blockIdx.x * 64;

    const __nv_bfloat16* gWh = g_Wth + 4 * DM * DM;
    const __nv_bfloat16* gWl = g_Wtl + 4 * DM * DM;

    const int mt = w >> 1;
    const int nh = (w & 1) * 64;
    const int m0 = mt * 16 + g;
    const int m1 = m0 + 8;

    float acc[8][4];
#pragma unroll
    for (int nt = 0; nt < 8; nt++)
#pragma unroll
        for (int i = 0; i < 4; i++) acc[nt][i] = 0.f;

    for (int ks = 0; ks < 2; ks++) {
        if (ks) __syncthreads();
        {
#pragma unroll
            for (int it = 0; it < 2; it++) {
                int id = tid + it * 256;
                int row = id >> 3, seg = (id & 7) * 8;
                size_t src = (size_t)(r0 + row) * DM + ks * 64 + seg;
                cp16(sAh + row * PSTR + seg, g_Ch + src);
                cp16(sAl + row * PSTR + seg, g_Cl + src);
            }
#pragma unroll
            for (int it = 0; it < 4; it++) {
                int id = tid + it * 256;
                int n = id >> 3, seg = (id & 7) * 8;
                size_t src = (size_t)n * DM + ks * 64 + seg;
                cp16(sWth + n * PSTR + seg, gWh + src);
                cp16(sWtl + n * PSTR + seg, gWl + src);
            }
        }
        cp_commit();
        cp_wait<0>();
        __syncthreads();

#pragma unroll
        for (int kk = 0; kk < 64; kk += 16) {
            const int dof = kk + tig * 2;
            uint32_t ah0 = *(const uint32_t*)&sAh[m0 * PSTR + dof];
            uint32_t ah1 = *(const uint32_t*)&sAh[m1 * PSTR + dof];
            uint32_t ah2 = *(const uint32_t*)&sAh[m0 * PSTR + dof + 8];
            uint32_t ah3 = *(const uint32_t*)&sAh[m1 * PSTR + dof + 8];
            uint32_t al0 = *(const uint32_t*)&sAl[m0 * PSTR + dof];
            uint32_t al1 = *(const uint32_t*)&sAl[m1 * PSTR + dof];
            uint32_t al2 = *(const uint32_t*)&sAl[m0 * PSTR + dof + 8];
            uint32_t al3 = *(const uint32_t*)&sAl[m1 * PSTR + dof + 8];
#pragma unroll
            for (int nt = 0; nt < 8; nt++) {
                int ncol = nh + nt * 8 + g;
                uint32_t bh0 = *(const uint32_t*)&sWth[ncol * PSTR + dof];
                uint32_t bh1 = *(const uint32_t*)&sWth[ncol * PSTR + dof + 8];
                uint32_t bl0 = *(const uint32_t*)&sWtl[ncol * PSTR + dof];
                uint32_t bl1 = *(const uint32_t*)&sWtl[ncol * PSTR + dof + 8];
                mma16816(acc[nt], ah0, ah1, ah2, ah3, bh0, bh1);
                mma16816(acc[nt], ah0, ah1, ah2, ah3, bl0, bl1);
                mma16816(acc[nt], al0, al1, al2, al3, bh0, bh1);
            }
        }
    }

    const size_t row0 = (size_t)(r0 + m0);
    const size_t row1 = row0 + 8;
    float ps0 = 0.f, pq0 = 0.f, ps1 = 0.f, pq1 = 0.f;
#pragma unroll
    for (int nt = 0; nt < 8; nt++) {
        int col = nh + nt * 8 + tig * 2;
        float2 rv0 = *(const float2*)&g_R[row0 * DM + col];
        float2 rv1 = *(const float2*)&g_R[row1 * DM + col];
        acc[nt][0] += rv0.x; acc[nt][1] += rv0.y;
        acc[nt][2] += rv1.x; acc[nt][3] += rv1.y;
        ps0 += acc[nt][0] + acc[nt][1];
        pq0 += acc[nt][0] * acc[nt][0] + acc[nt][1] * acc[nt][1];
        ps1 += acc[nt][2] + acc[nt][3];
        pq1 += acc[nt][2] * acc[nt][2] + acc[nt][3] * acc[nt][3];
    }

    float* red1 = (float*)psm;
    float* red2 = red1 + 64 * 8;
    float* smu  = red2 + 64 * 8;
    float* srs  = smu + 64;
    __syncthreads();
    const int slot = (w & 1) * 4 + tig;
    red1[m0 * 8 + slot] = ps0;
    red2[m0 * 8 + slot] = pq0;
    red1[m1 * 8 + slot] = ps1;
    red2[m1 * 8 + slot] = pq1;
    __syncthreads();
    if (tid < 64) {
        float s = 0.f, q = 0.f;
#pragma unroll
        for (int j = 0; j < 8; j++) { s += red1[tid * 8 + j]; q += red2[tid * 8 + j]; }
        float mu = s * (1.0f / 128.0f);
        float var = q * (1.0f / 128.0f) - mu * mu;
        smu[tid] = mu;
        srs[tid] = rsqrtf(var + 1e-5f);
    }
    __syncthreads();

    const float mu0 = smu[m0], rs0 = srs[m0];
    const float mu1 = smu[m1], rs1 = srs[m1];
#pragma unroll
    for (int nt = 0; nt < 8; nt++) {
        int col = nh + nt * 8 + tig * 2;
        float2 gm = *(const float2*)&gamma[col];
        float2 bt = *(const float2*)&beta[col];
        float2 o0 = make_float2((acc[nt][0] - mu0) * rs0 * gm.x + bt.x,
                                (acc[nt][1] - mu0) * rs0 * gm.y + bt.y);
        float2 o1 = make_float2((acc[nt][2] - mu1) * rs1 * gm.x + bt.x,
                                (acc[nt][3] - mu1) * rs1 * gm.y + bt.y);
        *(float2*)&out[row0 * DM + col] = o0;
        *(float2*)&out[row1 * DM + col] = o1;
    }
}

// ---------------------------------------------------------------------------
extern "C" void kernel_launch(void* const* d_in, const int* in_sizes, int n_in,
                              void* d_out, int out_size)
{
    const float* inQ  = (const float*)d_in[0];
    const float* inK  = (const float*)d_in[1];
    const float* inV  = (const float*)d_in[2];
    const unsigned char* mask = (const unsigned char*)d_in[3];
    const float* Wfc0 = (const float*)d_in[4];
    const float* WQ   = (const float*)d_in[5];
    const float* WK   = (const float*)d_in[6];
    const float* WV   = (const float*)d_in[7];
    const float* Wfc  = (const float*)d_in[8];
    const float* gam  = (const float*)d_in[9];
    const float* bet  = (const float*)d_in[10];
    float* out  = (float*)d_out;
    float* attn = out + OUT_ELEMS;

    detect_mask<<<1, 256>>>(mask);                                  // 1
    pack_mask<<<(unsigned)((size_t)BATCH * SEQ * SW / 256), 256>>>(mask);  // 2
    split_inputs<<<dim3(NR * DM / 1024, 3), 256>>>(inQ, inK, inV);  // 3
    split_weights<<<dim3(8, 5), 256>>>(Wfc0, WQ, WK, WV, Wfc);      // 4

    cudaFuncSetAttribute(proj_tc, cudaFuncAttributeMaxDynamicSharedMemorySize,
                         (int)P_SMEM_BYTES);
    proj_tc<<<dim3(NR / 64, 4), 256, P_SMEM_BYTES>>>();             // 5

    dim3 agrid(SEQ / TQ, BATCH * 4);
    cudaFuncSetAttribute(rowsum_pass, cudaFuncAttributeMaxDynamicSharedMemorySize,
                         (int)RS_SMEM_BYTES);
    rowsum_pass<<<agrid, 256, RS_SMEM_BYTES>>>();                   // 6 (ncu)

    cudaFuncSetAttribute(attn_mma, cudaFuncAttributeMaxDynamicSharedMemorySize,
                         (int)SMEM_BYTES);
    attn_mma<<<agrid, 256, SMEM_BYTES>>>(attn);                     // 7

    cudaFuncSetAttribute(out_ln_tc, cudaFuncAttributeMaxDynamicSharedMemorySize,
                         (int)P_SMEM_BYTES);
    out_ln_tc<<<NR / 64, 256, P_SMEM_BYTES>>>(gam, bet, out);       // 8
}